// round 11
// baseline (speedup 1.0000x reference)
#include <cuda_runtime.h>
#include <cuda_bf16.h>
#include <math.h>

#define N0 50000
#define E0 1600000
#define K1 40000
#define K2 32000
#define NB_SCAN 49   // ceil(N0/1024)

// ---------------- scratch (device globals; no runtime allocation) ----------------
__device__ float g_x1[N0*128];
__device__ float g_agg[N0*128];
__device__ float g_t[K1*64];
__device__ float g_x2[K1*64];
__device__ float g_x3[K2*64];
__device__ float g_u1[K1*64];
__device__ float g_x4[K1*128];
__device__ float g_u2[N0*128];
__device__ float g_x5[N0*128];
__device__ int   g_rowptr[N0+1];
__device__ int   g_fill[N0];
__device__ int   g_part[64];
__device__ int   g_partx[66];
__device__ int   g_esrc[E0];
__device__ float g_score[N0];
__device__ unsigned g_key[N0];
__device__ int   g_map1[N0];
__device__ int   g_perm1[K1];
__device__ int   g_map2[K1];
__device__ int   g_perm2[K2];
__device__ int   g_map02[N0];
__device__ int   g_perm02[K2];
__device__ float g_wT[4*128*128];

// ---------------- CSR build ----------------
__global__ void zero_int_kernel(int* p, int n)
{
    int i = blockIdx.x*blockDim.x + threadIdx.x;
    if (i < n) p[i] = 0;
}

__global__ void edge_count_kernel(const int* __restrict__ dst)
{
    int e = blockIdx.x*blockDim.x + threadIdx.x;
    if (e < E0) atomicAdd(&g_fill[dst[e]], 1);
}

__device__ __forceinline__ int block_scan_incl(int val, int& total, int* ws)
{
    int lane = threadIdx.x & 31, wid = threadIdx.x >> 5;
    int x = val;
    #pragma unroll
    for (int off = 1; off < 32; off <<= 1){
        int y = __shfl_up_sync(0xffffffffu, x, off);
        if (lane >= off) x += y;
    }
    if (lane == 31) ws[wid] = x;
    __syncthreads();
    if (wid == 0){
        int s = ws[lane];
        #pragma unroll
        for (int off = 1; off < 32; off <<= 1){
            int y = __shfl_up_sync(0xffffffffu, s, off);
            if (lane >= off) s += y;
        }
        ws[lane] = s;
    }
    __syncthreads();
    int res = x + (wid ? ws[wid-1] : 0);
    total = ws[31];
    __syncthreads();
    return res;
}

__global__ void scan_kernel(const int* __restrict__ in, int* __restrict__ out, int n)
{
    __shared__ int ws[32];
    int run = 0;
    for (int base = 0; base < n; base += 1024){
        int i = base + threadIdx.x;
        int v = (i < n) ? in[i] : 0;
        int tot; int incl = block_scan_incl(v, tot, ws);
        if (i < n) out[i] = run + incl - v;
        run += tot;
    }
    if (threadIdx.x == 0) out[n] = run;
}

__global__ void deg_reduce_kernel(const int* __restrict__ in, int* __restrict__ part, int n)
{
    __shared__ int ws[32];
    int i = blockIdx.x*1024 + threadIdx.x;
    int v = (i < n) ? in[i] : 0;
    int lane = threadIdx.x & 31, wid = threadIdx.x >> 5;
    #pragma unroll
    for (int off = 16; off; off >>= 1) v += __shfl_down_sync(0xffffffffu, v, off);
    if (lane == 0) ws[wid] = v;
    __syncthreads();
    if (wid == 0){
        v = ws[lane];
        #pragma unroll
        for (int off = 16; off; off >>= 1) v += __shfl_down_sync(0xffffffffu, v, off);
        if (lane == 0) part[blockIdx.x] = v;
    }
}

__global__ void deg_apply_kernel(const int* __restrict__ in, const int* __restrict__ partx,
                                 int* __restrict__ rowptr, int n)
{
    __shared__ int ws[32];
    int i = blockIdx.x*1024 + threadIdx.x;
    int v = (i < n) ? in[i] : 0;
    int tot; int incl = block_scan_incl(v, tot, ws);
    if (i < n) rowptr[i] = partx[blockIdx.x] + incl - v;
    if (i == n) rowptr[n] = partx[gridDim.x];
}

__global__ void edge_scatter_kernel(const int* __restrict__ src, const int* __restrict__ dst)
{
    int e = blockIdx.x*blockDim.x + threadIdx.x;
    if (e < E0){
        int d = dst[e];
        int off = atomicSub(&g_fill[d], 1) - 1;
        g_esrc[g_rowptr[d] + off] = src[e];
    }
}

// ---------------- transpose of the 4 tf32-path weight matrices ----------------
__global__ void transpose_all_kernel(
    const float* w0, const float* w1, const float* w2, const float* w3,
    float* __restrict__ wT)
{
    const float* ws[4] = {w0,w1,w2,w3};
    const int CO[4] = {128,128,64,64};
    const int CI[4] = {128,128,128,128};
    int m = blockIdx.y;
    int idx = blockIdx.x*blockDim.x + threadIdx.x;
    int nEl = CO[m]*CI[m];
    if (idx < nEl){
        int r = idx / CI[m], c = idx % CI[m];
        wT[m*16384 + c*CO[m] + r] = ws[m][idx];
    }
}

// ---------------- aggregation: warp per node, vectorized row gather ----------------
template<int C>
__global__ void agg_kernel(const float* __restrict__ xin, float* __restrict__ out,
                           const int* __restrict__ perm, const int* __restrict__ mapping, int n)
{
    int warp = (blockIdx.x*blockDim.x + threadIdx.x) >> 5;
    int lane = threadIdx.x & 31;
    if (warp >= n) return;
    int old = perm ? perm[warp] : warp;
    int beg = g_rowptr[old], end = g_rowptr[old+1];
    if constexpr (C == 128){
        float4 acc = make_float4(0.f,0.f,0.f,0.f);
        for (int b = beg; b < end; b += 32){
            int e = b + lane;
            int s = -1;
            if (e < end){ s = g_esrc[e]; if (mapping) s = mapping[s]; }
            int cnt = min(32, end - b);
            for (int j = 0; j < cnt; j++){
                int sj = __shfl_sync(0xffffffffu, s, j);
                if (sj >= 0){
                    float4 v = ((const float4*)(xin + (size_t)sj*128))[lane];
                    acc.x += v.x; acc.y += v.y; acc.z += v.z; acc.w += v.w;
                }
            }
        }
        ((float4*)(out + (size_t)warp*128))[lane] = acc;
    } else {
        float2 acc = make_float2(0.f,0.f);
        for (int b = beg; b < end; b += 32){
            int e = b + lane;
            int s = -1;
            if (e < end){ s = g_esrc[e]; if (mapping) s = mapping[s]; }
            int cnt = min(32, end - b);
            for (int j = 0; j < cnt; j++){
                int sj = __shfl_sync(0xffffffffu, s, j);
                if (sj >= 0){
                    float2 v = ((const float2*)(xin + (size_t)sj*64))[lane];
                    acc.x += v.x; acc.y += v.y;
                }
            }
        }
        ((float2*)(out + (size_t)warp*64))[lane] = acc;
    }
}

// ---------------- tf32 split helpers ----------------
__device__ __forceinline__ void tf32_split(float a, float& hi, float& lo)
{
    unsigned h;
    asm("cvt.rna.tf32.f32 %0, %1;" : "=r"(h) : "f"(a));
    float hf = __uint_as_float(h);
    float l = a - hf;
    unsigned lu;
    asm("cvt.rna.tf32.f32 %0, %1;" : "=r"(lu) : "f"(l));
    hi = hf; lo = __uint_as_float(lu);
}

#define MMA_TF32(d, a0,a1,a2,a3, b0,b1) \
    asm volatile("mma.sync.aligned.m16n8k8.row.col.f32.tf32.tf32.f32 " \
        "{%0,%1,%2,%3}, {%4,%5,%6,%7}, {%8,%9}, {%0,%1,%2,%3};" \
        : "+f"((d)[0]), "+f"((d)[1]), "+f"((d)[2]), "+f"((d)[3]) \
        : "r"(a0), "r"(a1), "r"(a2), "r"(a3), "r"(b0), "r"(b1))

#define MMA_BF16(d, a0,a1,a2,a3, b0,b1) \
    asm volatile("mma.sync.aligned.m16n8k16.row.col.f32.bf16.bf16.f32 " \
        "{%0,%1,%2,%3}, {%4,%5,%6,%7}, {%8,%9}, {%0,%1,%2,%3};" \
        : "+f"((d)[0]), "+f"((d)[1]), "+f"((d)[2]), "+f"((d)[3]) \
        : "r"(a0), "r"(a1), "r"(a2), "r"(a3), "r"(b0), "r"(b1))

__device__ __forceinline__ unsigned short f2bf(float x)
{
    __nv_bfloat16 b = __float2bfloat16(x);
    return *reinterpret_cast<unsigned short*>(&b);
}
__device__ __forceinline__ void bf16_split(float x, unsigned short& hi, unsigned short& lo)
{
    __nv_bfloat16 h = __float2bfloat16(x);
    float hf = __bfloat162float(h);
    hi = *reinterpret_cast<unsigned short*>(&h);
    lo = f2bf(x - hf);
}

// ---------------- tf32 tensor-core GEMM (selection-critical layers; R8 version) ----------------
template<int BN, int CIN, bool DUAL, bool RELU, bool GATHER>
__global__ void __launch_bounds__(256, 2) gemm_tc_kernel(
    const float* __restrict__ A1, const float* __restrict__ A2,
    const float* __restrict__ W1, const float* __restrict__ W2,   // transposed [CIN][BN]
    const float* __restrict__ bias, const float* __restrict__ D,
    float* __restrict__ out, int n,
    const int* __restrict__ perm, const float* __restrict__ score)
{
    constexpr int BM = 128, BK = 16, TPB = 256;
    constexpr int BMp = 136, BNp = BN + 8;
    constexpr int AV = (BM*BK/4)/TPB;
    constexpr int BV = (BK*BN/4)/TPB;
    constexpr int TILES = CIN/BK;
    constexpr int T = (DUAL?2:1)*TILES;
    constexpr int MT = 2;
    constexpr int NT = BN/16;

    __shared__ float As[2][BK][BMp];
    __shared__ float Bs[2][BK][BNp];

    int tid = threadIdx.x, lane = tid & 31, warp = tid >> 5;
    int m0 = (warp >> 1) * 32;
    int n0 = (warp & 1) * (BN/2);
    int row0 = blockIdx.x * BM;
    int gid = lane >> 2, tig = lane & 3;

    int am[AV], akq[AV], aar[AV]; float asc[AV];
    #pragma unroll
    for (int u = 0; u < AV; u++){
        int f = tid + u*TPB;
        am[u] = f >> 2; akq[u] = (f & 3) << 2;
        int r = row0 + am[u];
        aar[u] = -1; asc[u] = 1.f;
        if (r < n){
            int ar = r;
            if (GATHER){ ar = perm[r]; asc[u] = score[ar]; }
            aar[u] = ar;
        }
    }
    int bkk[BV], bc4[BV];
    #pragma unroll
    for (int u = 0; u < BV; u++){
        int f = tid + u*TPB;
        bkk[u] = f / (BN/4); bc4[u] = (f % (BN/4)) << 2;
    }

    float4 ra[AV], rb[BV];
    auto load_tile = [&](int t){
        int ph = DUAL ? (t / TILES) : 0;
        int k0 = (t % TILES) * BK;
        const float* A = (DUAL && ph) ? A2 : A1;
        const float* W = (DUAL && ph) ? W2 : W1;
        #pragma unroll
        for (int u = 0; u < AV; u++){
            float4 v = make_float4(0.f,0.f,0.f,0.f);
            if (aar[u] >= 0){
                v = *(const float4*)(A + (size_t)aar[u]*CIN + k0 + akq[u]);
                if (GATHER){ v.x*=asc[u]; v.y*=asc[u]; v.z*=asc[u]; v.w*=asc[u]; }
            }
            ra[u] = v;
        }
        #pragma unroll
        for (int u = 0; u < BV; u++)
            rb[u] = *(const float4*)(W + (size_t)(k0 + bkk[u])*BN + bc4[u]);
    };
    auto store_split = [&](){
        #pragma unroll
        for (int u = 0; u < AV; u++){
            const float* s = (const float*)&ra[u];
            #pragma unroll
            for (int q = 0; q < 4; q++){
                float hi, lo; tf32_split(s[q], hi, lo);
                As[0][akq[u]+q][am[u]] = hi;
                As[1][akq[u]+q][am[u]] = lo;
            }
        }
        #pragma unroll
        for (int u = 0; u < BV; u++){
            const float* s = (const float*)&rb[u];
            #pragma unroll
            for (int q = 0; q < 4; q++){
                float hi, lo; tf32_split(s[q], hi, lo);
                Bs[0][bkk[u]][bc4[u]+q] = hi;
                Bs[1][bkk[u]][bc4[u]+q] = lo;
            }
        }
    };

    float acc[MT][NT][4];
    #pragma unroll
    for (int mi = 0; mi < MT; mi++)
        #pragma unroll
        for (int ni = 0; ni < NT; ni++)
            #pragma unroll
            for (int q = 0; q < 4; q++) acc[mi][ni][q] = 0.f;

    load_tile(0);
    for (int t = 0; t < T; t++){
        store_split();
        __syncthreads();
        if (t + 1 < T) load_tile(t + 1);
        #pragma unroll
        for (int kk = 0; kk < 2; kk++){
            int ko = kk * 8;
            unsigned ah[MT][4], al[MT][4];
            #pragma unroll
            for (int mi = 0; mi < MT; mi++){
                int mb = m0 + mi*16 + gid;
                ah[mi][0] = __float_as_uint(As[0][ko+tig  ][mb  ]);
                ah[mi][1] = __float_as_uint(As[0][ko+tig  ][mb+8]);
                ah[mi][2] = __float_as_uint(As[0][ko+tig+4][mb  ]);
                ah[mi][3] = __float_as_uint(As[0][ko+tig+4][mb+8]);
                al[mi][0] = __float_as_uint(As[1][ko+tig  ][mb  ]);
                al[mi][1] = __float_as_uint(As[1][ko+tig  ][mb+8]);
                al[mi][2] = __float_as_uint(As[1][ko+tig+4][mb  ]);
                al[mi][3] = __float_as_uint(As[1][ko+tig+4][mb+8]);
            }
            #pragma unroll
            for (int ni = 0; ni < NT; ni++){
                int nb = n0 + ni*8 + gid;
                unsigned bh0 = __float_as_uint(Bs[0][ko+tig  ][nb]);
                unsigned bh1 = __float_as_uint(Bs[0][ko+tig+4][nb]);
                unsigned bl0 = __float_as_uint(Bs[1][ko+tig  ][nb]);
                unsigned bl1 = __float_as_uint(Bs[1][ko+tig+4][nb]);
                #pragma unroll
                for (int mi = 0; mi < MT; mi++){
                    MMA_TF32(acc[mi][ni], ah[mi][0],ah[mi][1],ah[mi][2],ah[mi][3], bh0,bh1);
                    MMA_TF32(acc[mi][ni], ah[mi][0],ah[mi][1],ah[mi][2],ah[mi][3], bl0,bl1);
                    MMA_TF32(acc[mi][ni], al[mi][0],al[mi][1],al[mi][2],al[mi][3], bh0,bh1);
                }
            }
        }
        __syncthreads();
    }

    #pragma unroll
    for (int mi = 0; mi < MT; mi++){
        #pragma unroll
        for (int ni = 0; ni < NT; ni++){
            int cc = n0 + ni*8 + tig*2;
            #pragma unroll
            for (int h = 0; h < 2; h++){
                int rr = row0 + m0 + mi*16 + gid + h*8;
                if (rr < n){
                    float v0 = acc[mi][ni][h*2+0];
                    float v1 = acc[mi][ni][h*2+1];
                    if (bias){ v0 += __ldg(&bias[cc]); v1 += __ldg(&bias[cc+1]); }
                    if (D){ v0 += D[(size_t)rr*BN + cc]; v1 += D[(size_t)rr*BN + cc + 1]; }
                    if (RELU){ v0 = fmaxf(v0, 0.f); v1 = fmaxf(v1, 0.f); }
                    *(float2*)(out + (size_t)rr*BN + cc) = make_float2(v0, v1);
                }
            }
        }
    }
}

// ---------------- bf16-split tensor-core GEMM (R8 version; selection-independent) ----------------
template<int BN, int CIN, bool DUAL, bool RELU, bool GATHER>
__global__ void __launch_bounds__(256, 2) gemm_bf16_kernel(
    const float* __restrict__ A1, const float* __restrict__ A2,
    const float* __restrict__ W1, const float* __restrict__ W2,
    const float* __restrict__ bias, const float* __restrict__ D,
    float* __restrict__ out, int n,
    const int* __restrict__ perm, const float* __restrict__ score)
{
    constexpr int BM = 128, BK = 32, TPB = 256;
    constexpr int STR = 20;
    constexpr int AV = (BM*BK/4)/TPB;
    constexpr int BV = (BN*BK/4)/TPB;
    constexpr int TILES = CIN/BK;
    constexpr int T = (DUAL?2:1)*TILES;
    constexpr int MT = 2;
    constexpr int NT = BN/16;

    __shared__ unsigned As[2][BM][STR];
    __shared__ unsigned Bs[2][BN][STR];

    int tid = threadIdx.x, lane = tid & 31, warp = tid >> 5;
    int m0 = (warp >> 1) * 32;
    int n0 = (warp & 1) * (BN/2);
    int row0 = blockIdx.x * BM;
    int gid = lane >> 2, tig = lane & 3;

    int am[AV], akq[AV], aar[AV]; float asc[AV];
    #pragma unroll
    for (int u = 0; u < AV; u++){
        int f = tid + u*TPB;
        am[u] = f >> 3; akq[u] = (f & 7) << 2;
        int r = row0 + am[u];
        aar[u] = -1; asc[u] = 1.f;
        if (r < n){
            int ar = r;
            if (GATHER){ ar = perm[r]; asc[u] = score[ar]; }
            aar[u] = ar;
        }
    }
    int bm[BV], bkq[BV];
    #pragma unroll
    for (int u = 0; u < BV; u++){
        int f = tid + u*TPB;
        bm[u] = f >> 3; bkq[u] = (f & 7) << 2;
    }

    float4 ra[AV], rb[BV];
    auto load_tile = [&](int t){
        int ph = DUAL ? (t / TILES) : 0;
        int k0 = (t % TILES) * BK;
        const float* A = (DUAL && ph) ? A2 : A1;
        const float* W = (DUAL && ph) ? W2 : W1;
        #pragma unroll
        for (int u = 0; u < AV; u++){
            float4 v = make_float4(0.f,0.f,0.f,0.f);
            if (aar[u] >= 0){
                v = *(const float4*)(A + (size_t)aar[u]*CIN + k0 + akq[u]);
                if (GATHER){ v.x*=asc[u]; v.y*=asc[u]; v.z*=asc[u]; v.w*=asc[u]; }
            }
            ra[u] = v;
        }
        #pragma unroll
        for (int u = 0; u < BV; u++)
            rb[u] = *(const float4*)(W + (size_t)bm[u]*CIN + k0 + bkq[u]);
    };
    auto store_split = [&](){
        #pragma unroll
        for (int u = 0; u < AV; u++){
            const float* s = (const float*)&ra[u];
            unsigned short h0,l0,h1,l1,h2,l2,h3,l3;
            bf16_split(s[0],h0,l0); bf16_split(s[1],h1,l1);
            bf16_split(s[2],h2,l2); bf16_split(s[3],h3,l3);
            int w = akq[u] >> 1;
            As[0][am[u]][w  ] = (unsigned)h0 | ((unsigned)h1 << 16);
            As[0][am[u]][w+1] = (unsigned)h2 | ((unsigned)h3 << 16);
            As[1][am[u]][w  ] = (unsigned)l0 | ((unsigned)l1 << 16);
            As[1][am[u]][w+1] = (unsigned)l2 | ((unsigned)l3 << 16);
        }
        #pragma unroll
        for (int u = 0; u < BV; u++){
            const float* s = (const float*)&rb[u];
            unsigned short h0,l0,h1,l1,h2,l2,h3,l3;
            bf16_split(s[0],h0,l0); bf16_split(s[1],h1,l1);
            bf16_split(s[2],h2,l2); bf16_split(s[3],h3,l3);
            int w = bkq[u] >> 1;
            Bs[0][bm[u]][w  ] = (unsigned)h0 | ((unsigned)h1 << 16);
            Bs[0][bm[u]][w+1] = (unsigned)h2 | ((unsigned)h3 << 16);
            Bs[1][bm[u]][w  ] = (unsigned)l0 | ((unsigned)l1 << 16);
            Bs[1][bm[u]][w+1] = (unsigned)l2 | ((unsigned)l3 << 16);
        }
    };

    float acc[MT][NT][4];
    #pragma unroll
    for (int mi = 0; mi < MT; mi++)
        #pragma unroll
        for (int ni = 0; ni < NT; ni++)
            #pragma unroll
            for (int q = 0; q < 4; q++) acc[mi][ni][q] = 0.f;

    load_tile(0);
    for (int t = 0; t < T; t++){
        store_split();
        __syncthreads();
        if (t + 1 < T) load_tile(t + 1);
        #pragma unroll
        for (int kk = 0; kk < 2; kk++){
            int ko = kk * 8;
            unsigned ah[MT][4], al[MT][4];
            #pragma unroll
            for (int mi = 0; mi < MT; mi++){
                int mb = m0 + mi*16 + gid;
                ah[mi][0] = As[0][mb  ][ko+tig  ];
                ah[mi][1] = As[0][mb+8][ko+tig  ];
                ah[mi][2] = As[0][mb  ][ko+tig+4];
                ah[mi][3] = As[0][mb+8][ko+tig+4];
                al[mi][0] = As[1][mb  ][ko+tig  ];
                al[mi][1] = As[1][mb+8][ko+tig  ];
                al[mi][2] = As[1][mb  ][ko+tig+4];
                al[mi][3] = As[1][mb+8][ko+tig+4];
            }
            #pragma unroll
            for (int ni = 0; ni < NT; ni++){
                int nb = n0 + ni*8 + gid;
                unsigned bh0 = Bs[0][nb][ko+tig  ];
                unsigned bh1 = Bs[0][nb][ko+tig+4];
                unsigned bl0 = Bs[1][nb][ko+tig  ];
                unsigned bl1 = Bs[1][nb][ko+tig+4];
                #pragma unroll
                for (int mi = 0; mi < MT; mi++){
                    MMA_BF16(acc[mi][ni], ah[mi][0],ah[mi][1],ah[mi][2],ah[mi][3], bh0,bh1);
                    MMA_BF16(acc[mi][ni], ah[mi][0],ah[mi][1],ah[mi][2],ah[mi][3], bl0,bl1);
                    MMA_BF16(acc[mi][ni], al[mi][0],al[mi][1],al[mi][2],al[mi][3], bh0,bh1);
                }
            }
        }
        __syncthreads();
    }

    #pragma unroll
    for (int mi = 0; mi < MT; mi++){
        #pragma unroll
        for (int ni = 0; ni < NT; ni++){
            int cc = n0 + ni*8 + tig*2;
            #pragma unroll
            for (int h = 0; h < 2; h++){
                int rr = row0 + m0 + mi*16 + gid + h*8;
                if (rr < n){
                    float v0 = acc[mi][ni][h*2+0];
                    float v1 = acc[mi][ni][h*2+1];
                    if (bias){ v0 += __ldg(&bias[cc]); v1 += __ldg(&bias[cc+1]); }
                    if (D){ v0 += D[(size_t)rr*BN + cc]; v1 += D[(size_t)rr*BN + cc + 1]; }
                    if (RELU){ v0 = fmaxf(v0, 0.f); v1 = fmaxf(v1, 0.f); }
                    *(float2*)(out + (size_t)rr*BN + cc) = make_float2(v0, v1);
                }
            }
        }
    }
}

// ---------------- elementwise: out = relu(root + agg + bias) ----------------
template<int C>
__global__ void add_bias_relu_kernel(float* __restrict__ inout, const float* __restrict__ agg,
                                     const float* __restrict__ bias, int n)
{
    int idx = blockIdx.x*blockDim.x + threadIdx.x;
    int total = n * (C/4);
    if (idx >= total) return;
    int i = idx / (C/4), t = idx % (C/4);
    float4 v = ((const float4*)(inout + (size_t)i*C))[t];
    float4 a = ((const float4*)(agg + (size_t)i*C))[t];
    float4 b = *(const float4*)(bias + t*4);
    v.x = fmaxf(v.x + a.x + b.x, 0.f);
    v.y = fmaxf(v.y + a.y + b.y, 0.f);
    v.z = fmaxf(v.z + a.z + b.z, 0.f);
    v.w = fmaxf(v.w + a.w + b.w, 0.f);
    ((float4*)(inout + (size_t)i*C))[t] = v;
}

// ---------------- topk pooling ----------------
template<int C>
__global__ void score_kernel(const float* __restrict__ x, const float* __restrict__ w, int n)
{
    int gw = blockIdx.x*(blockDim.x>>5) + (threadIdx.x>>5);
    int lane = threadIdx.x & 31;
    if (gw >= n) return;
    float p, q;
    if constexpr (C == 128){
        float4 xv = ((const float4*)(x + (size_t)gw*128))[lane];
        float4 wv = ((const float4*)w)[lane];
        p = xv.x*wv.x + xv.y*wv.y + xv.z*wv.z + xv.w*wv.w;
        q = wv.x*wv.x + wv.y*wv.y + wv.z*wv.z + wv.w*wv.w;
    } else {
        float2 xv = ((const float2*)(x + (size_t)gw*64))[lane];
        float2 wv = ((const float2*)w)[lane];
        p = xv.x*wv.x + xv.y*wv.y;
        q = wv.x*wv.x + wv.y*wv.y;
    }
    #pragma unroll
    for (int off = 16; off; off >>= 1){
        p += __shfl_xor_sync(0xffffffffu, p, off);
        q += __shfl_xor_sync(0xffffffffu, q, off);
    }
    if (lane == 0){
        float s = tanhf(p / sqrtf(q));
        g_score[gw] = s;
        unsigned u = __float_as_uint(s);
        u = (u & 0x80000000u) ? ~u : (u | 0x80000000u);
        g_key[gw] = u;
    }
}

// ONE-KERNEL radix select + compact (single block, 1024 threads).
__global__ void __launch_bounds__(1024) topk_select_kernel(
    int* __restrict__ mapping, int* __restrict__ perm, int n, int k)
{
    __shared__ unsigned hist[256];
    __shared__ int ws[32];
    __shared__ int s_b, s_rem;

    unsigned prefix = 0;
    int remaining = k;
    for (int pass = 3; pass >= 0; pass--){
        for (int t = threadIdx.x; t < 256; t += 1024) hist[t] = 0;
        __syncthreads();
        int shf = (pass+1)*8;
        unsigned pref_hi = (pass == 3) ? 0u : (prefix >> shf);
        for (int base = 0; base < n; base += 1024){
            int i = base + threadIdx.x;
            if (i < n){
                unsigned key = g_key[i];
                bool ok = (pass == 3) || ((key >> shf) == pref_hi);
                if (ok) atomicAdd(&hist[(key >> (pass*8)) & 255], 1u);
            }
        }
        __syncthreads();
        if (threadIdx.x == 0){
            unsigned r = (unsigned)remaining;
            unsigned c = 0; int b = 255;
            for (; b > 0; b--){
                unsigned h = hist[b];
                if (c + h >= r) break;
                c += h;
            }
            s_b = b; s_rem = (int)(r - c);
        }
        __syncthreads();
        prefix |= ((unsigned)s_b) << (pass*8);
        remaining = s_rem;
        __syncthreads();
    }

    unsigned thr = prefix;
    int local = 0;
    for (int base = 0; base < n; base += 1024){
        int i = base + threadIdx.x;
        if (i < n) local += (g_key[i] > thr) ? 1 : 0;
    }
    int totG; block_scan_incl(local, totG, ws);
    int need_eq = k - totG;

    int run_eq = 0, run_sel = 0;
    for (int base = 0; base < n; base += 1024){
        int i = base + threadIdx.x;
        int gt = 0, eq = 0;
        if (i < n){
            unsigned kv = g_key[i];
            gt = (kv > thr); eq = (kv == thr);
        }
        int tot_eq; int incl_eq = block_scan_incl(eq, tot_eq, ws);
        int excl_eq = incl_eq - eq;
        int sel = gt | (eq & ((run_eq + excl_eq) < need_eq ? 1 : 0));
        int tot_sel; int incl_sel = block_scan_incl(sel, tot_sel, ws);
        if (i < n){
            if (sel){
                int idx = run_sel + incl_sel - 1;
                mapping[i] = idx;
                perm[idx] = i;
            } else mapping[i] = -1;
        }
        run_eq += tot_eq; run_sel += tot_sel;
    }
}

// fused compose of level0->level2 mapping and perm
__global__ void compose_kernel()
{
    int i = blockIdx.x*blockDim.x + threadIdx.x;
    if (i < N0){ int m = g_map1[i]; g_map02[i] = (m >= 0) ? g_map2[m] : -1; }
    if (i < K2) g_perm02[i] = g_perm1[g_perm2[i]];
}

template<int C>
__global__ void unpool_kernel(const float* __restrict__ xb, const float* __restrict__ xs,
                              const int* __restrict__ mapping, float* __restrict__ out, int n)
{
    int idx = blockIdx.x*blockDim.x + threadIdx.x;
    int total = n * (C/4);
    if (idx >= total) return;
    int i = idx / (C/4), t = idx % (C/4);
    int m = mapping[i];
    float4 v = ((const float4*)(xb + (size_t)i*C))[t];
    if (m >= 0){
        float4 w = ((const float4*)(xs + (size_t)m*C))[t];
        v.x += w.x; v.y += w.y; v.z += w.z; v.w += w.w;
    }
    ((float4*)(out + (size_t)i*C))[t] = v;
}

// ---------------- final linear + log_softmax (warp per node) ----------------
__global__ void final_kernel(const float* __restrict__ x, const float* __restrict__ lw,
                             const float* __restrict__ lb, float* __restrict__ out, int n)
{
    int gw = blockIdx.x*(blockDim.x>>5) + (threadIdx.x>>5);
    int lane = threadIdx.x & 31;
    if (gw >= n) return;
    float4 xv = ((const float4*)(x + (size_t)gw*128))[lane];
    float lg[10]; float myv = 0.f;
    #pragma unroll
    for (int c = 0; c < 10; c++){
        float4 wv = ((const float4*)(lw + c*128))[lane];
        float p = xv.x*wv.x + xv.y*wv.y + xv.z*wv.z + xv.w*wv.w;
        #pragma unroll
        for (int off = 16; off; off >>= 1) p += __shfl_xor_sync(0xffffffffu, p, off);
        p += __ldg(&lb[c]);
        lg[c] = p;
        if (lane == c) myv = p;
    }
    float m = lg[0];
    #pragma unroll
    for (int c = 1; c < 10; c++) m = fmaxf(m, lg[c]);
    float s = 0.f;
    #pragma unroll
    for (int c = 0; c < 10; c++) s += expf(lg[c] - m);
    float lse = m + logf(s);
    if (lane < 10) out[(size_t)gw*10 + lane] = myv - lse;
}

// ---------------- host driver ----------------
extern "C" void kernel_launch(void* const* d_in, const int* in_sizes, int n_in,
                              void* d_out, int out_size)
{
    (void)in_sizes; (void)n_in; (void)out_size;
    const float* x    = (const float*)d_in[0];
    const int*   ei   = (const int*)d_in[1];
    const int*   src0 = ei;
    const int*   dst0 = ei + E0;
    const float *w1r=(const float*)d_in[2], *w1o=(const float*)d_in[3], *b1=(const float*)d_in[4], *p1w=(const float*)d_in[5];
    const float *w2r=(const float*)d_in[6], *w2o=(const float*)d_in[7], *b2=(const float*)d_in[8], *p2w=(const float*)d_in[9];
    const float *w3r=(const float*)d_in[10],*w3o=(const float*)d_in[11],*b3=(const float*)d_in[12];
    const float *w4r=(const float*)d_in[13],*w4o=(const float*)d_in[14],*b4=(const float*)d_in[15];
    const float *w5r=(const float*)d_in[16],*w5o=(const float*)d_in[17],*b5=(const float*)d_in[18];
    const float *lw =(const float*)d_in[19],*lb =(const float*)d_in[20];
    float* out = (float*)d_out;

    float *x1,*agg,*tbuf,*x2,*x3,*u1,*x4,*u2,*x5,*wT,*score;
    int *rowptr,*fill,*part,*partx,*map1,*perm1,*map2,*perm2,*map02,*perm02;
    cudaGetSymbolAddress((void**)&x1, g_x1);
    cudaGetSymbolAddress((void**)&agg, g_agg);
    cudaGetSymbolAddress((void**)&tbuf, g_t);
    cudaGetSymbolAddress((void**)&x2, g_x2);
    cudaGetSymbolAddress((void**)&x3, g_x3);
    cudaGetSymbolAddress((void**)&u1, g_u1);
    cudaGetSymbolAddress((void**)&x4, g_x4);
    cudaGetSymbolAddress((void**)&u2, g_u2);
    cudaGetSymbolAddress((void**)&x5, g_x5);
    cudaGetSymbolAddress((void**)&wT, g_wT);
    cudaGetSymbolAddress((void**)&score, g_score);
    cudaGetSymbolAddress((void**)&rowptr, g_rowptr);
    cudaGetSymbolAddress((void**)&fill, g_fill);
    cudaGetSymbolAddress((void**)&part, g_part);
    cudaGetSymbolAddress((void**)&partx, g_partx);
    cudaGetSymbolAddress((void**)&map1, g_map1);
    cudaGetSymbolAddress((void**)&perm1, g_perm1);
    cudaGetSymbolAddress((void**)&map2, g_map2);
    cudaGetSymbolAddress((void**)&perm2, g_perm2);
    cudaGetSymbolAddress((void**)&map02, g_map02);
    cudaGetSymbolAddress((void**)&perm02, g_perm02);

    const int W = 16384;

    cudaStream_t s2;
    cudaStreamCreateWithFlags(&s2, cudaStreamNonBlocking);
    cudaEvent_t ev[10];
    for (int i = 0; i < 10; i++) cudaEventCreateWithFlags(&ev[i], cudaEventDisableTiming);

    // ---- prologue: CSR + conv1 agg on s2, transpose + conv1 root GEMM on main ----
    cudaEventRecord(ev[0], 0);
    cudaStreamWaitEvent(s2, ev[0], 0);
    {
        dim3 g(64, 4);
        transpose_all_kernel<<<g,256>>>(w1r,w1o,w2r,w2o, wT);
    }
    zero_int_kernel<<<(N0+255)/256,256,0,s2>>>(fill, N0);
    edge_count_kernel<<<(E0+255)/256,256,0,s2>>>(dst0);
    gemm_tc_kernel<128,128,false,false,false><<<(N0+127)/128,256>>>(
        x, nullptr, wT+1*W, nullptr, nullptr, nullptr, x1, N0, nullptr, nullptr);
    deg_reduce_kernel<<<NB_SCAN,1024,0,s2>>>(fill, part, N0);
    scan_kernel<<<1,1024,0,s2>>>(part, partx, NB_SCAN);
    deg_apply_kernel<<<NB_SCAN,1024,0,s2>>>(fill, partx, rowptr, N0);
    edge_scatter_kernel<<<(E0+255)/256,256,0,s2>>>(src0, dst0);
    agg_kernel<128><<<(N0+7)/8,256,0,s2>>>(x, agg, nullptr, nullptr, N0);
    cudaEventRecord(ev[1], s2);
    cudaStreamWaitEvent(0, ev[1], 0);

    // conv1 rel-half (D add, bias, relu)
    gemm_tc_kernel<128,128,false,true,false><<<(N0+127)/128,256>>>(
        agg, nullptr, wT+0*W, nullptr, b1, x1, x1, N0, nullptr, nullptr);

    // pool1
    score_kernel<128><<<(N0+7)/8,256>>>(x1, p1w, N0);
    topk_select_kernel<<<1,1024>>>(map1, perm1, N0, K1);

    // ---- conv2: root GEMM on s2 || (transform GEMM + agg) on main ----
    cudaEventRecord(ev[2], 0);
    cudaStreamWaitEvent(s2, ev[2], 0);
    gemm_tc_kernel<64,128,false,false,true><<<(K1+127)/128,256,0,s2>>>(
        x1, nullptr, wT+3*W, nullptr, nullptr, nullptr, x2, K1, perm1, score);   // root: x1p·W2o
    gemm_tc_kernel<64,128,false,false,true><<<(K1+127)/128,256>>>(
        x1, nullptr, wT+2*W, nullptr, nullptr, nullptr, tbuf, K1, perm1, score); // t = x1p·W2r
    agg_kernel<64><<<(K1+7)/8,256>>>(tbuf, agg, perm1, map1, K1);
    cudaEventRecord(ev[3], s2);
    cudaStreamWaitEvent(0, ev[3], 0);
    add_bias_relu_kernel<64><<<(K1*16+255)/256,256>>>(x2, agg, b2, K1);

    // pool2
    score_kernel<64><<<(K1+7)/8,256>>>(x2, p2w, K1);
    topk_select_kernel<<<1,1024>>>(map2, perm2, K1, K2);
    compose_kernel<<<(N0+255)/256,256>>>();

    // ---- conv3: root GEMM on s2 || (transform GEMM + agg) on main ----
    cudaEventRecord(ev[4], 0);
    cudaStreamWaitEvent(s2, ev[4], 0);
    gemm_bf16_kernel<64,64,false,false,true><<<(K2+127)/128,256,0,s2>>>(
        x2, nullptr, w3o, nullptr, nullptr, nullptr, x3, K2, perm2, score);      // root: x2p·W3o
    gemm_bf16_kernel<64,64,false,false,true><<<(K2+127)/128,256>>>(
        x2, nullptr, w3r, nullptr, nullptr, nullptr, tbuf, K2, perm2, score);    // t = x2p·W3r
    agg_kernel<64><<<(K2+7)/8,256>>>(tbuf, agg, perm02, map02, K2);
    cudaEventRecord(ev[5], s2);
    cudaStreamWaitEvent(0, ev[5], 0);
    add_bias_relu_kernel<64><<<(K2*16+255)/256,256>>>(x3, agg, b3, K2);

    // unpool1 + skip
    unpool_kernel<64><<<(K1*16+255)/256,256>>>(x2, x3, map2, u1, K1);

    // ---- conv4: root GEMM on s2 || agg on main ----
    cudaEventRecord(ev[6], 0);
    cudaStreamWaitEvent(s2, ev[6], 0);
    gemm_bf16_kernel<128,64,false,false,false><<<(K1+127)/128,256,0,s2>>>(
        u1, nullptr, w4o, nullptr, nullptr, nullptr, x4, K1, nullptr, nullptr);  // root: u1·W4o
    agg_kernel<64><<<(K1+7)/8,256>>>(u1, agg, perm1, map1, K1);
    cudaEventRecord(ev[7], s2);
    cudaStreamWaitEvent(0, ev[7], 0);
    gemm_bf16_kernel<128,64,false,true,false><<<(K1+127)/128,256>>>(
        agg, nullptr, w4r, nullptr, b4, x4, x4, K1, nullptr, nullptr);           // rel + D + relu

    // unpool2 + skip
    unpool_kernel<128><<<(N0*32+255)/256,256>>>(x1, x4, map1, u2, N0);

    // ---- conv5: root GEMM on s2 || agg on main ----
    cudaEventRecord(ev[8], 0);
    cudaStreamWaitEvent(s2, ev[8], 0);
    gemm_bf16_kernel<128,128,false,false,false><<<(N0+127)/128,256,0,s2>>>(
        u2, nullptr, w5o, nullptr, nullptr, nullptr, x5, N0, nullptr, nullptr);  // root: u2·W5o
    agg_kernel<128><<<(N0+7)/8,256>>>(u2, agg, nullptr, nullptr, N0);
    cudaEventRecord(ev[9], s2);
    cudaStreamWaitEvent(0, ev[9], 0);
    gemm_bf16_kernel<128,128,false,true,false><<<(N0+127)/128,256>>>(
        agg, nullptr, w5r, nullptr, b5, x5, x5, N0, nullptr, nullptr);           // rel + D + relu

    // final linear + log_softmax
    final_kernel<<<(N0+7)/8,256>>>(x5, lw, lb, out, N0);
}

// round 12
// speedup vs baseline: 1.1001x; 1.1001x over previous
#include <cuda_runtime.h>
#include <cuda_bf16.h>
#include <math.h>

#define N0 50000
#define E0 1600000
#define K1 40000
#define K2 32000
#define NB_SCAN 49   // ceil(N0/1024)

// ---------------- scratch (device globals; no runtime allocation) ----------------
__device__ float g_x1[N0*128];
__device__ float g_agg[N0*128];
__device__ float g_x2[K1*64];
__device__ float g_x3[K2*64];
__device__ float g_u1[K1*64];
__device__ float g_x4[K1*128];     // also reused as conv2 cat-GEMM output t2
__device__ float g_u2[N0*128];     // also reused as conv3 cat-GEMM output t3
__device__ float g_x5[N0*128];
__device__ int   g_rowptr[N0+1];
__device__ int   g_fill[N0];
__device__ int   g_part[64];
__device__ int   g_partx[66];
__device__ int   g_esrc[E0];
__device__ float g_score[N0];
__device__ unsigned g_key[N0];
__device__ int   g_map1[N0];
__device__ int   g_perm1[K1];
__device__ int   g_map2[K1];
__device__ int   g_perm2[K2];
__device__ int   g_map02[N0];
__device__ int   g_perm02[K2];
__device__ float g_wT[3*128*128];  // 0: W1r^T, 1: W1o^T, 2: [W2r^T | W2o^T] cat (128x128)

// ---------------- CSR build ----------------
__global__ void zero_int_kernel(int* p, int n)
{
    int i = blockIdx.x*blockDim.x + threadIdx.x;
    if (i < n) p[i] = 0;
}

__global__ void edge_count_kernel(const int* __restrict__ dst)
{
    int e = blockIdx.x*blockDim.x + threadIdx.x;
    if (e < E0) atomicAdd(&g_fill[dst[e]], 1);
}

__device__ __forceinline__ int block_scan_incl(int val, int& total, int* ws)
{
    int lane = threadIdx.x & 31, wid = threadIdx.x >> 5;
    int x = val;
    #pragma unroll
    for (int off = 1; off < 32; off <<= 1){
        int y = __shfl_up_sync(0xffffffffu, x, off);
        if (lane >= off) x += y;
    }
    if (lane == 31) ws[wid] = x;
    __syncthreads();
    if (wid == 0){
        int s = ws[lane];
        #pragma unroll
        for (int off = 1; off < 32; off <<= 1){
            int y = __shfl_up_sync(0xffffffffu, s, off);
            if (lane >= off) s += y;
        }
        ws[lane] = s;
    }
    __syncthreads();
    int res = x + (wid ? ws[wid-1] : 0);
    total = ws[31];
    __syncthreads();
    return res;
}

__global__ void scan_kernel(const int* __restrict__ in, int* __restrict__ out, int n)
{
    __shared__ int ws[32];
    int run = 0;
    for (int base = 0; base < n; base += 1024){
        int i = base + threadIdx.x;
        int v = (i < n) ? in[i] : 0;
        int tot; int incl = block_scan_incl(v, tot, ws);
        if (i < n) out[i] = run + incl - v;
        run += tot;
    }
    if (threadIdx.x == 0) out[n] = run;
}

__global__ void deg_reduce_kernel(const int* __restrict__ in, int* __restrict__ part, int n)
{
    __shared__ int ws[32];
    int i = blockIdx.x*1024 + threadIdx.x;
    int v = (i < n) ? in[i] : 0;
    int lane = threadIdx.x & 31, wid = threadIdx.x >> 5;
    #pragma unroll
    for (int off = 16; off; off >>= 1) v += __shfl_down_sync(0xffffffffu, v, off);
    if (lane == 0) ws[wid] = v;
    __syncthreads();
    if (wid == 0){
        v = ws[lane];
        #pragma unroll
        for (int off = 16; off; off >>= 1) v += __shfl_down_sync(0xffffffffu, v, off);
        if (lane == 0) part[blockIdx.x] = v;
    }
}

__global__ void deg_apply_kernel(const int* __restrict__ in, const int* __restrict__ partx,
                                 int* __restrict__ rowptr, int n)
{
    __shared__ int ws[32];
    int i = blockIdx.x*1024 + threadIdx.x;
    int v = (i < n) ? in[i] : 0;
    int tot; int incl = block_scan_incl(v, tot, ws);
    if (i < n) rowptr[i] = partx[blockIdx.x] + incl - v;
    if (i == n) rowptr[n] = partx[gridDim.x];
}

__global__ void edge_scatter_kernel(const int* __restrict__ src, const int* __restrict__ dst)
{
    int e = blockIdx.x*blockDim.x + threadIdx.x;
    if (e < E0){
        int d = dst[e];
        int off = atomicSub(&g_fill[d], 1) - 1;
        g_esrc[g_rowptr[d] + off] = src[e];
    }
}

// ---------------- transpose of tf32-path weights; W2r/W2o concatenated along N ----------------
__global__ void transpose_all_kernel(
    const float* w0, const float* w1, const float* w2, const float* w3,
    float* __restrict__ wT)
{
    const float* ws[4] = {w0,w1,w2,w3};
    const int CO[4] = {128,128,64,64};
    const int CI[4] = {128,128,128,128};
    int m = blockIdx.y;
    int idx = blockIdx.x*blockDim.x + threadIdx.x;
    int nEl = CO[m]*CI[m];
    if (idx < nEl){
        int r = idx / CI[m], c = idx % CI[m];
        if (m < 2) wT[m*16384 + c*CO[m] + r] = ws[m][idx];
        else       wT[2*16384 + c*128 + (m == 3 ? 64 : 0) + r] = ws[m][idx];
    }
}

// ---------------- aggregation: warp per node, vectorized row gather (strided input) ----------------
template<int C>
__global__ void agg_kernel(const float* __restrict__ xin, float* __restrict__ out,
                           const int* __restrict__ perm, const int* __restrict__ mapping,
                           int n, int instride)
{
    int warp = (blockIdx.x*blockDim.x + threadIdx.x) >> 5;
    int lane = threadIdx.x & 31;
    if (warp >= n) return;
    int old = perm ? perm[warp] : warp;
    int beg = g_rowptr[old], end = g_rowptr[old+1];
    if constexpr (C == 128){
        float4 acc = make_float4(0.f,0.f,0.f,0.f);
        for (int b = beg; b < end; b += 32){
            int e = b + lane;
            int s = -1;
            if (e < end){ s = g_esrc[e]; if (mapping) s = mapping[s]; }
            int cnt = min(32, end - b);
            for (int j = 0; j < cnt; j++){
                int sj = __shfl_sync(0xffffffffu, s, j);
                if (sj >= 0){
                    float4 v = ((const float4*)(xin + (size_t)sj*instride))[lane];
                    acc.x += v.x; acc.y += v.y; acc.z += v.z; acc.w += v.w;
                }
            }
        }
        ((float4*)(out + (size_t)warp*128))[lane] = acc;
    } else {
        float2 acc = make_float2(0.f,0.f);
        for (int b = beg; b < end; b += 32){
            int e = b + lane;
            int s = -1;
            if (e < end){ s = g_esrc[e]; if (mapping) s = mapping[s]; }
            int cnt = min(32, end - b);
            for (int j = 0; j < cnt; j++){
                int sj = __shfl_sync(0xffffffffu, s, j);
                if (sj >= 0){
                    float2 v = ((const float2*)(xin + (size_t)sj*instride))[lane];
                    acc.x += v.x; acc.y += v.y;
                }
            }
        }
        ((float2*)(out + (size_t)warp*64))[lane] = acc;
    }
}

// ---------------- tf32 split helpers ----------------
__device__ __forceinline__ void tf32_split(float a, float& hi, float& lo)
{
    unsigned h;
    asm("cvt.rna.tf32.f32 %0, %1;" : "=r"(h) : "f"(a));
    float hf = __uint_as_float(h);
    float l = a - hf;
    unsigned lu;
    asm("cvt.rna.tf32.f32 %0, %1;" : "=r"(lu) : "f"(l));
    hi = hf; lo = __uint_as_float(lu);
}

#define MMA_TF32(d, a0,a1,a2,a3, b0,b1) \
    asm volatile("mma.sync.aligned.m16n8k8.row.col.f32.tf32.tf32.f32 " \
        "{%0,%1,%2,%3}, {%4,%5,%6,%7}, {%8,%9}, {%0,%1,%2,%3};" \
        : "+f"((d)[0]), "+f"((d)[1]), "+f"((d)[2]), "+f"((d)[3]) \
        : "r"(a0), "r"(a1), "r"(a2), "r"(a3), "r"(b0), "r"(b1))

#define MMA_BF16(d, a0,a1,a2,a3, b0,b1) \
    asm volatile("mma.sync.aligned.m16n8k16.row.col.f32.bf16.bf16.f32 " \
        "{%0,%1,%2,%3}, {%4,%5,%6,%7}, {%8,%9}, {%0,%1,%2,%3};" \
        : "+f"((d)[0]), "+f"((d)[1]), "+f"((d)[2]), "+f"((d)[3]) \
        : "r"(a0), "r"(a1), "r"(a2), "r"(a3), "r"(b0), "r"(b1))

__device__ __forceinline__ unsigned short f2bf(float x)
{
    __nv_bfloat16 b = __float2bfloat16(x);
    return *reinterpret_cast<unsigned short*>(&b);
}
__device__ __forceinline__ void bf16_split(float x, unsigned short& hi, unsigned short& lo)
{
    __nv_bfloat16 h = __float2bfloat16(x);
    float hf = __bfloat162float(h);
    hi = *reinterpret_cast<unsigned short*>(&h);
    lo = f2bf(x - hf);
}

// ---------------- tf32 tensor-core GEMM (selection-critical layers; R8 version) ----------------
template<int BN, int CIN, bool DUAL, bool RELU, bool GATHER>
__global__ void __launch_bounds__(256, 2) gemm_tc_kernel(
    const float* __restrict__ A1, const float* __restrict__ A2,
    const float* __restrict__ W1, const float* __restrict__ W2,   // transposed [CIN][BN]
    const float* __restrict__ bias, const float* __restrict__ D,
    float* __restrict__ out, int n,
    const int* __restrict__ perm, const float* __restrict__ score)
{
    constexpr int BM = 128, BK = 16, TPB = 256;
    constexpr int BMp = 136, BNp = BN + 8;
    constexpr int AV = (BM*BK/4)/TPB;
    constexpr int BV = (BK*BN/4)/TPB;
    constexpr int TILES = CIN/BK;
    constexpr int T = (DUAL?2:1)*TILES;
    constexpr int MT = 2;
    constexpr int NT = BN/16;

    __shared__ float As[2][BK][BMp];
    __shared__ float Bs[2][BK][BNp];

    int tid = threadIdx.x, lane = tid & 31, warp = tid >> 5;
    int m0 = (warp >> 1) * 32;
    int n0 = (warp & 1) * (BN/2);
    int row0 = blockIdx.x * BM;
    int gid = lane >> 2, tig = lane & 3;

    int am[AV], akq[AV], aar[AV]; float asc[AV];
    #pragma unroll
    for (int u = 0; u < AV; u++){
        int f = tid + u*TPB;
        am[u] = f >> 2; akq[u] = (f & 3) << 2;
        int r = row0 + am[u];
        aar[u] = -1; asc[u] = 1.f;
        if (r < n){
            int ar = r;
            if (GATHER){ ar = perm[r]; asc[u] = score[ar]; }
            aar[u] = ar;
        }
    }
    int bkk[BV], bc4[BV];
    #pragma unroll
    for (int u = 0; u < BV; u++){
        int f = tid + u*TPB;
        bkk[u] = f / (BN/4); bc4[u] = (f % (BN/4)) << 2;
    }

    float4 ra[AV], rb[BV];
    auto load_tile = [&](int t){
        int ph = DUAL ? (t / TILES) : 0;
        int k0 = (t % TILES) * BK;
        const float* A = (DUAL && ph) ? A2 : A1;
        const float* W = (DUAL && ph) ? W2 : W1;
        #pragma unroll
        for (int u = 0; u < AV; u++){
            float4 v = make_float4(0.f,0.f,0.f,0.f);
            if (aar[u] >= 0){
                v = *(const float4*)(A + (size_t)aar[u]*CIN + k0 + akq[u]);
                if (GATHER){ v.x*=asc[u]; v.y*=asc[u]; v.z*=asc[u]; v.w*=asc[u]; }
            }
            ra[u] = v;
        }
        #pragma unroll
        for (int u = 0; u < BV; u++)
            rb[u] = *(const float4*)(W + (size_t)(k0 + bkk[u])*BN + bc4[u]);
    };
    auto store_split = [&](){
        #pragma unroll
        for (int u = 0; u < AV; u++){
            const float* s = (const float*)&ra[u];
            #pragma unroll
            for (int q = 0; q < 4; q++){
                float hi, lo; tf32_split(s[q], hi, lo);
                As[0][akq[u]+q][am[u]] = hi;
                As[1][akq[u]+q][am[u]] = lo;
            }
        }
        #pragma unroll
        for (int u = 0; u < BV; u++){
            const float* s = (const float*)&rb[u];
            #pragma unroll
            for (int q = 0; q < 4; q++){
                float hi, lo; tf32_split(s[q], hi, lo);
                Bs[0][bkk[u]][bc4[u]+q] = hi;
                Bs[1][bkk[u]][bc4[u]+q] = lo;
            }
        }
    };

    float acc[MT][NT][4];
    #pragma unroll
    for (int mi = 0; mi < MT; mi++)
        #pragma unroll
        for (int ni = 0; ni < NT; ni++)
            #pragma unroll
            for (int q = 0; q < 4; q++) acc[mi][ni][q] = 0.f;

    load_tile(0);
    for (int t = 0; t < T; t++){
        store_split();
        __syncthreads();
        if (t + 1 < T) load_tile(t + 1);
        #pragma unroll
        for (int kk = 0; kk < 2; kk++){
            int ko = kk * 8;
            unsigned ah[MT][4], al[MT][4];
            #pragma unroll
            for (int mi = 0; mi < MT; mi++){
                int mb = m0 + mi*16 + gid;
                ah[mi][0] = __float_as_uint(As[0][ko+tig  ][mb  ]);
                ah[mi][1] = __float_as_uint(As[0][ko+tig  ][mb+8]);
                ah[mi][2] = __float_as_uint(As[0][ko+tig+4][mb  ]);
                ah[mi][3] = __float_as_uint(As[0][ko+tig+4][mb+8]);
                al[mi][0] = __float_as_uint(As[1][ko+tig  ][mb  ]);
                al[mi][1] = __float_as_uint(As[1][ko+tig  ][mb+8]);
                al[mi][2] = __float_as_uint(As[1][ko+tig+4][mb  ]);
                al[mi][3] = __float_as_uint(As[1][ko+tig+4][mb+8]);
            }
            #pragma unroll
            for (int ni = 0; ni < NT; ni++){
                int nb = n0 + ni*8 + gid;
                unsigned bh0 = __float_as_uint(Bs[0][ko+tig  ][nb]);
                unsigned bh1 = __float_as_uint(Bs[0][ko+tig+4][nb]);
                unsigned bl0 = __float_as_uint(Bs[1][ko+tig  ][nb]);
                unsigned bl1 = __float_as_uint(Bs[1][ko+tig+4][nb]);
                #pragma unroll
                for (int mi = 0; mi < MT; mi++){
                    MMA_TF32(acc[mi][ni], ah[mi][0],ah[mi][1],ah[mi][2],ah[mi][3], bh0,bh1);
                    MMA_TF32(acc[mi][ni], ah[mi][0],ah[mi][1],ah[mi][2],ah[mi][3], bl0,bl1);
                    MMA_TF32(acc[mi][ni], al[mi][0],al[mi][1],al[mi][2],al[mi][3], bh0,bh1);
                }
            }
        }
        __syncthreads();
    }

    #pragma unroll
    for (int mi = 0; mi < MT; mi++){
        #pragma unroll
        for (int ni = 0; ni < NT; ni++){
            int cc = n0 + ni*8 + tig*2;
            #pragma unroll
            for (int h = 0; h < 2; h++){
                int rr = row0 + m0 + mi*16 + gid + h*8;
                if (rr < n){
                    float v0 = acc[mi][ni][h*2+0];
                    float v1 = acc[mi][ni][h*2+1];
                    if (bias){ v0 += __ldg(&bias[cc]); v1 += __ldg(&bias[cc+1]); }
                    if (D){ v0 += D[(size_t)rr*BN + cc]; v1 += D[(size_t)rr*BN + cc + 1]; }
                    if (RELU){ v0 = fmaxf(v0, 0.f); v1 = fmaxf(v1, 0.f); }
                    *(float2*)(out + (size_t)rr*BN + cc) = make_float2(v0, v1);
                }
            }
        }
    }
}

// ---------------- bf16-split tensor-core GEMM (R8 version + DUALN row-concat mode) ----------------
// DUALN: B rows [0,BN/2) from W1, [BN/2,BN) from W2 (both [BN/2][CIN] row-major).
template<int BN, int CIN, bool DUAL, bool DUALN, bool RELU, bool GATHER>
__global__ void __launch_bounds__(256, 2) gemm_bf16_kernel(
    const float* __restrict__ A1, const float* __restrict__ A2,
    const float* __restrict__ W1, const float* __restrict__ W2,
    const float* __restrict__ bias, const float* __restrict__ D,
    float* __restrict__ out, int n,
    const int* __restrict__ perm, const float* __restrict__ score)
{
    constexpr int BM = 128, BK = 32, TPB = 256;
    constexpr int STR = 20;
    constexpr int AV = (BM*BK/4)/TPB;
    constexpr int BV = (BN*BK/4)/TPB;
    constexpr int TILES = CIN/BK;
    constexpr int T = (DUAL?2:1)*TILES;
    constexpr int MT = 2;
    constexpr int NT = BN/16;

    __shared__ unsigned As[2][BM][STR];
    __shared__ unsigned Bs[2][BN][STR];

    int tid = threadIdx.x, lane = tid & 31, warp = tid >> 5;
    int m0 = (warp >> 1) * 32;
    int n0 = (warp & 1) * (BN/2);
    int row0 = blockIdx.x * BM;
    int gid = lane >> 2, tig = lane & 3;

    int am[AV], akq[AV], aar[AV]; float asc[AV];
    #pragma unroll
    for (int u = 0; u < AV; u++){
        int f = tid + u*TPB;
        am[u] = f >> 3; akq[u] = (f & 7) << 2;
        int r = row0 + am[u];
        aar[u] = -1; asc[u] = 1.f;
        if (r < n){
            int ar = r;
            if (GATHER){ ar = perm[r]; asc[u] = score[ar]; }
            aar[u] = ar;
        }
    }
    int bm[BV], bkq[BV];
    #pragma unroll
    for (int u = 0; u < BV; u++){
        int f = tid + u*TPB;
        bm[u] = f >> 3; bkq[u] = (f & 7) << 2;
    }

    float4 ra[AV], rb[BV];
    auto load_tile = [&](int t){
        int ph = DUAL ? (t / TILES) : 0;
        int k0 = (t % TILES) * BK;
        const float* A = (DUAL && ph) ? A2 : A1;
        const float* W = (DUAL && ph) ? W2 : W1;
        #pragma unroll
        for (int u = 0; u < AV; u++){
            float4 v = make_float4(0.f,0.f,0.f,0.f);
            if (aar[u] >= 0){
                v = *(const float4*)(A + (size_t)aar[u]*CIN + k0 + akq[u]);
                if (GATHER){ v.x*=asc[u]; v.y*=asc[u]; v.z*=asc[u]; v.w*=asc[u]; }
            }
            ra[u] = v;
        }
        #pragma unroll
        for (int u = 0; u < BV; u++){
            const float* Wp = W;
            int row = bm[u];
            if (DUALN){
                if (row >= BN/2){ Wp = W2; row -= BN/2; }
                else Wp = W1;
            }
            rb[u] = *(const float4*)(Wp + (size_t)row*CIN + k0 + bkq[u]);
        }
    };
    auto store_split = [&](){
        #pragma unroll
        for (int u = 0; u < AV; u++){
            const float* s = (const float*)&ra[u];
            unsigned short h0,l0,h1,l1,h2,l2,h3,l3;
            bf16_split(s[0],h0,l0); bf16_split(s[1],h1,l1);
            bf16_split(s[2],h2,l2); bf16_split(s[3],h3,l3);
            int w = akq[u] >> 1;
            As[0][am[u]][w  ] = (unsigned)h0 | ((unsigned)h1 << 16);
            As[0][am[u]][w+1] = (unsigned)h2 | ((unsigned)h3 << 16);
            As[1][am[u]][w  ] = (unsigned)l0 | ((unsigned)l1 << 16);
            As[1][am[u]][w+1] = (unsigned)l2 | ((unsigned)l3 << 16);
        }
        #pragma unroll
        for (int u = 0; u < BV; u++){
            const float* s = (const float*)&rb[u];
            unsigned short h0,l0,h1,l1,h2,l2,h3,l3;
            bf16_split(s[0],h0,l0); bf16_split(s[1],h1,l1);
            bf16_split(s[2],h2,l2); bf16_split(s[3],h3,l3);
            int w = bkq[u] >> 1;
            Bs[0][bm[u]][w  ] = (unsigned)h0 | ((unsigned)h1 << 16);
            Bs[0][bm[u]][w+1] = (unsigned)h2 | ((unsigned)h3 << 16);
            Bs[1][bm[u]][w  ] = (unsigned)l0 | ((unsigned)l1 << 16);
            Bs[1][bm[u]][w+1] = (unsigned)l2 | ((unsigned)l3 << 16);
        }
    };

    float acc[MT][NT][4];
    #pragma unroll
    for (int mi = 0; mi < MT; mi++)
        #pragma unroll
        for (int ni = 0; ni < NT; ni++)
            #pragma unroll
            for (int q = 0; q < 4; q++) acc[mi][ni][q] = 0.f;

    load_tile(0);
    for (int t = 0; t < T; t++){
        store_split();
        __syncthreads();
        if (t + 1 < T) load_tile(t + 1);
        #pragma unroll
        for (int kk = 0; kk < 2; kk++){
            int ko = kk * 8;
            unsigned ah[MT][4], al[MT][4];
            #pragma unroll
            for (int mi = 0; mi < MT; mi++){
                int mb = m0 + mi*16 + gid;
                ah[mi][0] = As[0][mb  ][ko+tig  ];
                ah[mi][1] = As[0][mb+8][ko+tig  ];
                ah[mi][2] = As[0][mb  ][ko+tig+4];
                ah[mi][3] = As[0][mb+8][ko+tig+4];
                al[mi][0] = As[1][mb  ][ko+tig  ];
                al[mi][1] = As[1][mb+8][ko+tig  ];
                al[mi][2] = As[1][mb  ][ko+tig+4];
                al[mi][3] = As[1][mb+8][ko+tig+4];
            }
            #pragma unroll
            for (int ni = 0; ni < NT; ni++){
                int nb = n0 + ni*8 + gid;
                unsigned bh0 = Bs[0][nb][ko+tig  ];
                unsigned bh1 = Bs[0][nb][ko+tig+4];
                unsigned bl0 = Bs[1][nb][ko+tig  ];
                unsigned bl1 = Bs[1][nb][ko+tig+4];
                #pragma unroll
                for (int mi = 0; mi < MT; mi++){
                    MMA_BF16(acc[mi][ni], ah[mi][0],ah[mi][1],ah[mi][2],ah[mi][3], bh0,bh1);
                    MMA_BF16(acc[mi][ni], ah[mi][0],ah[mi][1],ah[mi][2],ah[mi][3], bl0,bl1);
                    MMA_BF16(acc[mi][ni], al[mi][0],al[mi][1],al[mi][2],al[mi][3], bh0,bh1);
                }
            }
        }
        __syncthreads();
    }

    #pragma unroll
    for (int mi = 0; mi < MT; mi++){
        #pragma unroll
        for (int ni = 0; ni < NT; ni++){
            int cc = n0 + ni*8 + tig*2;
            #pragma unroll
            for (int h = 0; h < 2; h++){
                int rr = row0 + m0 + mi*16 + gid + h*8;
                if (rr < n){
                    float v0 = acc[mi][ni][h*2+0];
                    float v1 = acc[mi][ni][h*2+1];
                    if (bias){ v0 += __ldg(&bias[cc]); v1 += __ldg(&bias[cc+1]); }
                    if (D){ v0 += D[(size_t)rr*BN + cc]; v1 += D[(size_t)rr*BN + cc + 1]; }
                    if (RELU){ v0 = fmaxf(v0, 0.f); v1 = fmaxf(v1, 0.f); }
                    *(float2*)(out + (size_t)rr*BN + cc) = make_float2(v0, v1);
                }
            }
        }
    }
}

// ---------------- elementwise: x = relu(t[:,64:128] + agg + bias), t stride 128 ----------------
__global__ void merge_conv_kernel(const float* __restrict__ t, const float* __restrict__ agg,
                                  const float* __restrict__ bias, float* __restrict__ xout, int n)
{
    int idx = blockIdx.x*blockDim.x + threadIdx.x;
    int total = n * 16;
    if (idx >= total) return;
    int i = idx >> 4, c4 = (idx & 15) << 2;
    float4 r = *(const float4*)(t + (size_t)i*128 + 64 + c4);
    float4 a = *(const float4*)(agg + (size_t)i*64 + c4);
    float4 b = *(const float4*)(bias + c4);
    r.x = fmaxf(r.x + a.x + b.x, 0.f);
    r.y = fmaxf(r.y + a.y + b.y, 0.f);
    r.z = fmaxf(r.z + a.z + b.z, 0.f);
    r.w = fmaxf(r.w + a.w + b.w, 0.f);
    *(float4*)(xout + (size_t)i*64 + c4) = r;
}

// ---------------- topk pooling ----------------
template<int C>
__global__ void score_kernel(const float* __restrict__ x, const float* __restrict__ w, int n)
{
    int gw = blockIdx.x*(blockDim.x>>5) + (threadIdx.x>>5);
    int lane = threadIdx.x & 31;
    if (gw >= n) return;
    float p, q;
    if constexpr (C == 128){
        float4 xv = ((const float4*)(x + (size_t)gw*128))[lane];
        float4 wv = ((const float4*)w)[lane];
        p = xv.x*wv.x + xv.y*wv.y + xv.z*wv.z + xv.w*wv.w;
        q = wv.x*wv.x + wv.y*wv.y + wv.z*wv.z + wv.w*wv.w;
    } else {
        float2 xv = ((const float2*)(x + (size_t)gw*64))[lane];
        float2 wv = ((const float2*)w)[lane];
        p = xv.x*wv.x + xv.y*wv.y;
        q = wv.x*wv.x + wv.y*wv.y;
    }
    #pragma unroll
    for (int off = 16; off; off >>= 1){
        p += __shfl_xor_sync(0xffffffffu, p, off);
        q += __shfl_xor_sync(0xffffffffu, q, off);
    }
    if (lane == 0){
        float s = tanhf(p / sqrtf(q));
        g_score[gw] = s;
        unsigned u = __float_as_uint(s);
        u = (u & 0x80000000u) ? ~u : (u | 0x80000000u);
        g_key[gw] = u;
    }
}

// ONE-KERNEL radix select + compact; keys staged in dynamic shared memory.
__global__ void __launch_bounds__(1024) topk_select_kernel(
    int* __restrict__ mapping, int* __restrict__ perm, int n, int k)
{
    extern __shared__ unsigned skey[];
    __shared__ unsigned hist[256];
    __shared__ int ws[32];
    __shared__ int s_b, s_rem;

    for (int i = threadIdx.x; i < n; i += 1024) skey[i] = g_key[i];
    __syncthreads();

    unsigned prefix = 0;
    int remaining = k;
    for (int pass = 3; pass >= 0; pass--){
        for (int t = threadIdx.x; t < 256; t += 1024) hist[t] = 0;
        __syncthreads();
        int shf = (pass+1)*8;
        unsigned pref_hi = (pass == 3) ? 0u : (prefix >> shf);
        for (int base = 0; base < n; base += 1024){
            int i = base + threadIdx.x;
            if (i < n){
                unsigned key = skey[i];
                bool ok = (pass == 3) || ((key >> shf) == pref_hi);
                if (ok) atomicAdd(&hist[(key >> (pass*8)) & 255], 1u);
            }
        }
        __syncthreads();
        if (threadIdx.x == 0){
            unsigned r = (unsigned)remaining;
            unsigned c = 0; int b = 255;
            for (; b > 0; b--){
                unsigned h = hist[b];
                if (c + h >= r) break;
                c += h;
            }
            s_b = b; s_rem = (int)(r - c);
        }
        __syncthreads();
        prefix |= ((unsigned)s_b) << (pass*8);
        remaining = s_rem;
        __syncthreads();
    }

    unsigned thr = prefix;
    int local = 0;
    for (int base = 0; base < n; base += 1024){
        int i = base + threadIdx.x;
        if (i < n) local += (skey[i] > thr) ? 1 : 0;
    }
    int totG; block_scan_incl(local, totG, ws);
    int need_eq = k - totG;

    int run_eq = 0, run_sel = 0;
    for (int base = 0; base < n; base += 1024){
        int i = base + threadIdx.x;
        int gt = 0, eq = 0;
        if (i < n){
            unsigned kv = skey[i];
            gt = (kv > thr); eq = (kv == thr);
        }
        int tot_eq; int incl_eq = block_scan_incl(eq, tot_eq, ws);
        int excl_eq = incl_eq - eq;
        int sel = gt | (eq & ((run_eq + excl_eq) < need_eq ? 1 : 0));
        int tot_sel; int incl_sel = block_scan_incl(sel, tot_sel, ws);
        if (i < n){
            if (sel){
                int idx = run_sel + incl_sel - 1;
                mapping[i] = idx;
                perm[idx] = i;
            } else mapping[i] = -1;
        }
        run_eq += tot_eq; run_sel += tot_sel;
    }
}

// fused compose of level0->level2 mapping and perm
__global__ void compose_kernel()
{
    int i = blockIdx.x*blockDim.x + threadIdx.x;
    if (i < N0){ int m = g_map1[i]; g_map02[i] = (m >= 0) ? g_map2[m] : -1; }
    if (i < K2) g_perm02[i] = g_perm1[g_perm2[i]];
}

template<int C>
__global__ void unpool_kernel(const float* __restrict__ xb, const float* __restrict__ xs,
                              const int* __restrict__ mapping, float* __restrict__ out, int n)
{
    int idx = blockIdx.x*blockDim.x + threadIdx.x;
    int total = n * (C/4);
    if (idx >= total) return;
    int i = idx / (C/4), t = idx % (C/4);
    int m = mapping[i];
    float4 v = ((const float4*)(xb + (size_t)i*C))[t];
    if (m >= 0){
        float4 w = ((const float4*)(xs + (size_t)m*C))[t];
        v.x += w.x; v.y += w.y; v.z += w.z; v.w += w.w;
    }
    ((float4*)(out + (size_t)i*C))[t] = v;
}

// ---------------- final linear + log_softmax (warp per node) ----------------
__global__ void final_kernel(const float* __restrict__ x, const float* __restrict__ lw,
                             const float* __restrict__ lb, float* __restrict__ out, int n)
{
    int gw = blockIdx.x*(blockDim.x>>5) + (threadIdx.x>>5);
    int lane = threadIdx.x & 31;
    if (gw >= n) return;
    float4 xv = ((const float4*)(x + (size_t)gw*128))[lane];
    float lg[10]; float myv = 0.f;
    #pragma unroll
    for (int c = 0; c < 10; c++){
        float4 wv = ((const float4*)(lw + c*128))[lane];
        float p = xv.x*wv.x + xv.y*wv.y + xv.z*wv.z + xv.w*wv.w;
        #pragma unroll
        for (int off = 16; off; off >>= 1) p += __shfl_xor_sync(0xffffffffu, p, off);
        p += __ldg(&lb[c]);
        lg[c] = p;
        if (lane == c) myv = p;
    }
    float m = lg[0];
    #pragma unroll
    for (int c = 1; c < 10; c++) m = fmaxf(m, lg[c]);
    float s = 0.f;
    #pragma unroll
    for (int c = 0; c < 10; c++) s += expf(lg[c] - m);
    float lse = m + logf(s);
    if (lane < 10) out[(size_t)gw*10 + lane] = myv - lse;
}

// ---------------- host driver ----------------
extern "C" void kernel_launch(void* const* d_in, const int* in_sizes, int n_in,
                              void* d_out, int out_size)
{
    (void)in_sizes; (void)n_in; (void)out_size;
    const float* x    = (const float*)d_in[0];
    const int*   ei   = (const int*)d_in[1];
    const int*   src0 = ei;
    const int*   dst0 = ei + E0;
    const float *w1r=(const float*)d_in[2], *w1o=(const float*)d_in[3], *b1=(const float*)d_in[4], *p1w=(const float*)d_in[5];
    const float *w2r=(const float*)d_in[6], *w2o=(const float*)d_in[7], *b2=(const float*)d_in[8], *p2w=(const float*)d_in[9];
    const float *w3r=(const float*)d_in[10],*w3o=(const float*)d_in[11],*b3=(const float*)d_in[12];
    const float *w4r=(const float*)d_in[13],*w4o=(const float*)d_in[14],*b4=(const float*)d_in[15];
    const float *w5r=(const float*)d_in[16],*w5o=(const float*)d_in[17],*b5=(const float*)d_in[18];
    const float *lw =(const float*)d_in[19],*lb =(const float*)d_in[20];
    float* out = (float*)d_out;

    float *x1,*agg,*x2,*x3,*u1,*x4,*u2,*x5,*wT,*score;
    int *rowptr,*fill,*part,*partx,*map1,*perm1,*map2,*perm2,*map02,*perm02;
    cudaGetSymbolAddress((void**)&x1, g_x1);
    cudaGetSymbolAddress((void**)&agg, g_agg);
    cudaGetSymbolAddress((void**)&x2, g_x2);
    cudaGetSymbolAddress((void**)&x3, g_x3);
    cudaGetSymbolAddress((void**)&u1, g_u1);
    cudaGetSymbolAddress((void**)&x4, g_x4);
    cudaGetSymbolAddress((void**)&u2, g_u2);
    cudaGetSymbolAddress((void**)&x5, g_x5);
    cudaGetSymbolAddress((void**)&wT, g_wT);
    cudaGetSymbolAddress((void**)&score, g_score);
    cudaGetSymbolAddress((void**)&rowptr, g_rowptr);
    cudaGetSymbolAddress((void**)&fill, g_fill);
    cudaGetSymbolAddress((void**)&part, g_part);
    cudaGetSymbolAddress((void**)&partx, g_partx);
    cudaGetSymbolAddress((void**)&map1, g_map1);
    cudaGetSymbolAddress((void**)&perm1, g_perm1);
    cudaGetSymbolAddress((void**)&map2, g_map2);
    cudaGetSymbolAddress((void**)&perm2, g_perm2);
    cudaGetSymbolAddress((void**)&map02, g_map02);
    cudaGetSymbolAddress((void**)&perm02, g_perm02);

    const int W = 16384;
    float* t2 = x4;   // conv2 cat output [K1][128] (x4 written later)
    float* t3 = u2;   // conv3 cat output [K2][128] (u2 written later)

    // allow 200KB dynamic smem for the select kernel (host-side attr; not a stream op)
    cudaFuncSetAttribute(topk_select_kernel,
                         cudaFuncAttributeMaxDynamicSharedMemorySize, N0*sizeof(unsigned) + 1024);

    cudaStream_t s2;
    cudaEvent_t ev1, ev2;
    cudaStreamCreateWithFlags(&s2, cudaStreamNonBlocking);
    cudaEventCreateWithFlags(&ev1, cudaEventDisableTiming);
    cudaEventCreateWithFlags(&ev2, cudaEventDisableTiming);

    // ---- prologue fork (CSR has serialization bubbles; GEMM fills them) ----
    cudaEventRecord(ev1, 0);
    cudaStreamWaitEvent(s2, ev1, 0);
    {
        dim3 g(64, 4);
        transpose_all_kernel<<<g,256>>>(w1r,w1o,w2r,w2o, wT);
    }
    zero_int_kernel<<<(N0+255)/256,256,0,s2>>>(fill, N0);
    edge_count_kernel<<<(E0+255)/256,256,0,s2>>>(dst0);
    gemm_tc_kernel<128,128,false,false,false><<<(N0+127)/128,256>>>(
        x, nullptr, wT+1*W, nullptr, nullptr, nullptr, x1, N0, nullptr, nullptr);
    deg_reduce_kernel<<<NB_SCAN,1024,0,s2>>>(fill, part, N0);
    scan_kernel<<<1,1024,0,s2>>>(part, partx, NB_SCAN);
    deg_apply_kernel<<<NB_SCAN,1024,0,s2>>>(fill, partx, rowptr, N0);
    edge_scatter_kernel<<<(E0+255)/256,256,0,s2>>>(src0, dst0);
    agg_kernel<128><<<(N0+7)/8,256,0,s2>>>(x, agg, nullptr, nullptr, N0, 128);
    cudaEventRecord(ev2, s2);
    cudaStreamWaitEvent(0, ev2, 0);

    // conv1 rel-half (D add, bias, relu)
    gemm_tc_kernel<128,128,false,true,false><<<(N0+127)/128,256>>>(
        agg, nullptr, wT+0*W, nullptr, b1, x1, x1, N0, nullptr, nullptr);

    // pool1
    score_kernel<128><<<(N0+7)/8,256>>>(x1, p1w, N0);
    topk_select_kernel<<<1,1024,N0*sizeof(unsigned)>>>(map1, perm1, N0, K1);

    // conv2 (tf32 cat): t2 = gather(x1)·[W2r^T|W2o^T]; agg left half; merge
    gemm_tc_kernel<128,128,false,false,true><<<(K1+127)/128,256>>>(
        x1, nullptr, wT+2*W, nullptr, nullptr, nullptr, t2, K1, perm1, score);
    agg_kernel<64><<<(K1+7)/8,256>>>(t2, agg, perm1, map1, K1, 128);
    merge_conv_kernel<<<(K1*16+255)/256,256>>>(t2, agg, b2, x2, K1);

    // pool2
    score_kernel<64><<<(K1+7)/8,256>>>(x2, p2w, K1);
    topk_select_kernel<<<1,1024,K1*sizeof(unsigned)>>>(map2, perm2, K1, K2);
    compose_kernel<<<(N0+255)/256,256>>>();

    // conv3 (bf16 cat via DUALN): t3 = gather(x2)·[W3r|W3o]; agg left half; merge
    gemm_bf16_kernel<128,64,false,true,false,true><<<(K2+127)/128,256>>>(
        x2, nullptr, w3r, w3o, nullptr, nullptr, t3, K2, perm2, score);
    agg_kernel<64><<<(K2+7)/8,256>>>(t3, agg, perm02, map02, K2, 128);
    merge_conv_kernel<<<(K2*16+255)/256,256>>>(t3, agg, b3, x3, K2);

    // unpool1 + skip
    unpool_kernel<64><<<(K1*16+255)/256,256>>>(x2, x3, map2, u1, K1);

    // conv4 (bf16 dual-K): agg then relu(agg·W4r + u1·W4o + b4)
    agg_kernel<64><<<(K1+7)/8,256>>>(u1, agg, perm1, map1, K1, 64);
    gemm_bf16_kernel<128,64,true,false,true,false><<<(K1+127)/128,256>>>(
        agg, u1, w4r, w4o, b4, nullptr, x4, K1, nullptr, nullptr);

    // unpool2 + skip
    unpool_kernel<128><<<(N0*32+255)/256,256>>>(x1, x4, map1, u2, N0);

    // conv5 (bf16 dual-K)
    agg_kernel<128><<<(N0+7)/8,256>>>(u2, agg, nullptr, nullptr, N0, 128);
    gemm_bf16_kernel<128,128,true,false,true,false><<<(N0+127)/128,256>>>(
        agg, u2, w5r, w5o, b5, nullptr, x5, N0, nullptr, nullptr);

    // final linear + log_softmax
    final_kernel<<<(N0+7)/8,256>>>(x5, lw, lb, out, N0);
}

// round 13
// speedup vs baseline: 1.1162x; 1.0147x over previous
#include <cuda_runtime.h>
#include <cuda_bf16.h>
#include <math.h>

#define N0 50000
#define E0 1600000
#define K1 40000
#define K2 32000
#define NB_SCAN 49   // ceil(N0/1024)

// ---------------- scratch (device globals; no runtime allocation) ----------------
__device__ float g_x1[N0*128];
__device__ float g_agg[N0*128];
__device__ float g_x2[K1*64];
__device__ float g_x3[K2*64];
__device__ float g_u1[K1*64];
__device__ float g_x4[K1*128];     // also conv2 cat-GEMM output t2
__device__ float g_u2[N0*128];     // also conv3 cat-GEMM output t3
__device__ float g_x5[N0*128];
__device__ int   g_rowptr[N0+1];
__device__ int   g_fill[N0];
__device__ int   g_part[64];
__device__ int   g_partx[66];
__device__ int   g_esrc[E0];
__device__ float g_score[N0];
__device__ unsigned g_key[N0];
__device__ int   g_map1[N0];
__device__ int   g_perm1[K1];
__device__ int   g_map2[K1];
__device__ int   g_perm2[K2];
__device__ int   g_map02[N0];
__device__ int   g_perm02[K2];
// tf32 pre-split transposed weight planes: 0=W1r^T, 1=W1o^T, 2=[W2r^T|W2o^T]
__device__ float g_wHi[3*16384];
__device__ float g_wLo[3*16384];
// bf16 pre-packed hi/lo word planes
__device__ unsigned g_wb3h[128*32],  g_wb3l[128*32];    // conv3 N-cat [128 rows][64 k]
__device__ unsigned g_wb4h[128*64],  g_wb4l[128*64];    // conv4 K-cat [128 rows][128 k]
__device__ unsigned g_wb5h[128*128], g_wb5l[128*128];   // conv5 K-cat [128 rows][256 k]

// ---------------- CSR build ----------------
__global__ void zero_int_kernel(int* p, int n)
{
    int i = blockIdx.x*blockDim.x + threadIdx.x;
    if (i < n) p[i] = 0;
}

__global__ void edge_count_kernel(const int* __restrict__ dst)
{
    int e = blockIdx.x*blockDim.x + threadIdx.x;
    if (e < E0) atomicAdd(&g_fill[dst[e]], 1);
}

__device__ __forceinline__ int block_scan_incl(int val, int& total, int* ws)
{
    int lane = threadIdx.x & 31, wid = threadIdx.x >> 5;
    int x = val;
    #pragma unroll
    for (int off = 1; off < 32; off <<= 1){
        int y = __shfl_up_sync(0xffffffffu, x, off);
        if (lane >= off) x += y;
    }
    if (lane == 31) ws[wid] = x;
    __syncthreads();
    if (wid == 0){
        int s = ws[lane];
        #pragma unroll
        for (int off = 1; off < 32; off <<= 1){
            int y = __shfl_up_sync(0xffffffffu, s, off);
            if (lane >= off) s += y;
        }
        ws[lane] = s;
    }
    __syncthreads();
    int res = x + (wid ? ws[wid-1] : 0);
    total = ws[31];
    __syncthreads();
    return res;
}

__global__ void scan_kernel(const int* __restrict__ in, int* __restrict__ out, int n)
{
    __shared__ int ws[32];
    int run = 0;
    for (int base = 0; base < n; base += 1024){
        int i = base + threadIdx.x;
        int v = (i < n) ? in[i] : 0;
        int tot; int incl = block_scan_incl(v, tot, ws);
        if (i < n) out[i] = run + incl - v;
        run += tot;
    }
    if (threadIdx.x == 0) out[n] = run;
}

__global__ void deg_reduce_kernel(const int* __restrict__ in, int* __restrict__ part, int n)
{
    __shared__ int ws[32];
    int i = blockIdx.x*1024 + threadIdx.x;
    int v = (i < n) ? in[i] : 0;
    int lane = threadIdx.x & 31, wid = threadIdx.x >> 5;
    #pragma unroll
    for (int off = 16; off; off >>= 1) v += __shfl_down_sync(0xffffffffu, v, off);
    if (lane == 0) ws[wid] = v;
    __syncthreads();
    if (wid == 0){
        v = ws[lane];
        #pragma unroll
        for (int off = 16; off; off >>= 1) v += __shfl_down_sync(0xffffffffu, v, off);
        if (lane == 0) part[blockIdx.x] = v;
    }
}

__global__ void deg_apply_kernel(const int* __restrict__ in, const int* __restrict__ partx,
                                 int* __restrict__ rowptr, int n)
{
    __shared__ int ws[32];
    int i = blockIdx.x*1024 + threadIdx.x;
    int v = (i < n) ? in[i] : 0;
    int tot; int incl = block_scan_incl(v, tot, ws);
    if (i < n) rowptr[i] = partx[blockIdx.x] + incl - v;
    if (i == n) rowptr[n] = partx[gridDim.x];
}

__global__ void edge_scatter_kernel(const int* __restrict__ src, const int* __restrict__ dst)
{
    int e = blockIdx.x*blockDim.x + threadIdx.x;
    if (e < E0){
        int d = dst[e];
        int off = atomicSub(&g_fill[d], 1) - 1;
        g_esrc[g_rowptr[d] + off] = src[e];
    }
}

// ---------------- split helpers ----------------
__device__ __forceinline__ void tf32_split(float a, float& hi, float& lo)
{
    unsigned h;
    asm("cvt.rna.tf32.f32 %0, %1;" : "=r"(h) : "f"(a));
    float hf = __uint_as_float(h);
    float l = a - hf;
    unsigned lu;
    asm("cvt.rna.tf32.f32 %0, %1;" : "=r"(lu) : "f"(l));
    hi = hf; lo = __uint_as_float(lu);
}

__device__ __forceinline__ unsigned short f2bf(float x)
{
    __nv_bfloat16 b = __float2bfloat16(x);
    return *reinterpret_cast<unsigned short*>(&b);
}
__device__ __forceinline__ void bf16_split(float x, unsigned short& hi, unsigned short& lo)
{
    __nv_bfloat16 h = __float2bfloat16(x);
    float hf = __bfloat162float(h);
    hi = *reinterpret_cast<unsigned short*>(&h);
    lo = f2bf(x - hf);
}

// ---------------- weight preprocessing ----------------
// tf32: transpose + split; W2r/W2o concatenated along output dim
__global__ void prep_tf32_kernel(const float* w0, const float* w1, const float* w2, const float* w3)
{
    const float* ws[4] = {w0,w1,w2,w3};
    const int CO[4] = {128,128,64,64};
    int m = blockIdx.y;
    int idx = blockIdx.x*blockDim.x + threadIdx.x;
    int nEl = CO[m]*128;
    if (idx < nEl){
        int r = idx >> 7, c = idx & 127;
        float hi, lo; tf32_split(ws[m][idx], hi, lo);
        int off = (m < 2) ? (m*16384 + c*128 + r)
                          : (2*16384 + c*128 + (m == 3 ? 64 : 0) + r);
        g_wHi[off] = hi; g_wLo[off] = lo;
    }
}

// bf16: pack hi/lo planes with cat layouts baked in
__global__ void prep_bf16_kernel(const float* w3r, const float* w3o,
                                 const float* w4r, const float* w4o,
                                 const float* w5r, const float* w5o)
{
    int m = blockIdx.y;
    int idx = blockIdx.x*blockDim.x + threadIdx.x;
    if (m == 0){                 // conv3 N-cat: [128][64], rows 0-63 w3r, 64-127 w3o
        if (idx < 128*32){
            int r = idx >> 5, w = idx & 31;
            const float* src = (r < 64) ? (w3r + r*64) : (w3o + (r-64)*64);
            unsigned short h0,l0,h1,l1;
            bf16_split(src[w*2],   h0, l0);
            bf16_split(src[w*2+1], h1, l1);
            g_wb3h[idx] = (unsigned)h0 | ((unsigned)h1 << 16);
            g_wb3l[idx] = (unsigned)l0 | ((unsigned)l1 << 16);
        }
    } else if (m == 1){          // conv4 K-cat: [128][128], k<64 w4r else w4o
        if (idx < 128*64){
            int r = idx >> 6, w = idx & 63;
            int k = w*2;
            const float* src = (k < 64) ? (w4r + r*64 + k) : (w4o + r*64 + k - 64);
            unsigned short h0,l0,h1,l1;
            bf16_split(src[0], h0, l0);
            bf16_split(src[1], h1, l1);
            g_wb4h[idx] = (unsigned)h0 | ((unsigned)h1 << 16);
            g_wb4l[idx] = (unsigned)l0 | ((unsigned)l1 << 16);
        }
    } else {                     // conv5 K-cat: [128][256], k<128 w5r else w5o
        if (idx < 128*128){
            int r = idx >> 7, w = idx & 127;
            int k = w*2;
            const float* src = (k < 128) ? (w5r + r*128 + k) : (w5o + r*128 + k - 128);
            unsigned short h0,l0,h1,l1;
            bf16_split(src[0], h0, l0);
            bf16_split(src[1], h1, l1);
            g_wb5h[idx] = (unsigned)h0 | ((unsigned)h1 << 16);
            g_wb5l[idx] = (unsigned)l0 | ((unsigned)l1 << 16);
        }
    }
}

// ---------------- aggregation: warp per node, vectorized row gather (strided input) ----------------
template<int C>
__global__ void agg_kernel(const float* __restrict__ xin, float* __restrict__ out,
                           const int* __restrict__ perm, const int* __restrict__ mapping,
                           int n, int instride)
{
    int warp = (blockIdx.x*blockDim.x + threadIdx.x) >> 5;
    int lane = threadIdx.x & 31;
    if (warp >= n) return;
    int old = perm ? perm[warp] : warp;
    int beg = g_rowptr[old], end = g_rowptr[old+1];
    if constexpr (C == 128){
        float4 acc = make_float4(0.f,0.f,0.f,0.f);
        for (int b = beg; b < end; b += 32){
            int e = b + lane;
            int s = -1;
            if (e < end){ s = g_esrc[e]; if (mapping) s = mapping[s]; }
            int cnt = min(32, end - b);
            for (int j = 0; j < cnt; j++){
                int sj = __shfl_sync(0xffffffffu, s, j);
                if (sj >= 0){
                    float4 v = ((const float4*)(xin + (size_t)sj*instride))[lane];
                    acc.x += v.x; acc.y += v.y; acc.z += v.z; acc.w += v.w;
                }
            }
        }
        ((float4*)(out + (size_t)warp*128))[lane] = acc;
    } else {
        float2 acc = make_float2(0.f,0.f);
        for (int b = beg; b < end; b += 32){
            int e = b + lane;
            int s = -1;
            if (e < end){ s = g_esrc[e]; if (mapping) s = mapping[s]; }
            int cnt = min(32, end - b);
            for (int j = 0; j < cnt; j++){
                int sj = __shfl_sync(0xffffffffu, s, j);
                if (sj >= 0){
                    float2 v = ((const float2*)(xin + (size_t)sj*instride))[lane];
                    acc.x += v.x; acc.y += v.y;
                }
            }
        }
        ((float2*)(out + (size_t)warp*64))[lane] = acc;
    }
}

#define MMA_TF32(d, a0,a1,a2,a3, b0,b1) \
    asm volatile("mma.sync.aligned.m16n8k8.row.col.f32.tf32.tf32.f32 " \
        "{%0,%1,%2,%3}, {%4,%5,%6,%7}, {%8,%9}, {%0,%1,%2,%3};" \
        : "+f"((d)[0]), "+f"((d)[1]), "+f"((d)[2]), "+f"((d)[3]) \
        : "r"(a0), "r"(a1), "r"(a2), "r"(a3), "r"(b0), "r"(b1))

#define MMA_BF16(d, a0,a1,a2,a3, b0,b1) \
    asm volatile("mma.sync.aligned.m16n8k16.row.col.f32.bf16.bf16.f32 " \
        "{%0,%1,%2,%3}, {%4,%5,%6,%7}, {%8,%9}, {%0,%1,%2,%3};" \
        : "+f"((d)[0]), "+f"((d)[1]), "+f"((d)[2]), "+f"((d)[3]) \
        : "r"(a0), "r"(a1), "r"(a2), "r"(a3), "r"(b0), "r"(b1))

// ---------------- tf32 GEMM: pre-split weight planes ----------------
template<int BN, int CIN, bool RELU, bool GATHER>
__global__ void __launch_bounds__(256, 2) gemm_tf32_kernel(
    const float* __restrict__ A1,
    const float* __restrict__ Whi, const float* __restrict__ Wlo,  // [CIN][BN] pre-split
    const float* __restrict__ bias, const float* __restrict__ D,
    float* __restrict__ out, int n,
    const int* __restrict__ perm, const float* __restrict__ score)
{
    constexpr int BM = 128, BK = 16, TPB = 256;
    constexpr int BMp = 136, BNp = BN + 8;
    constexpr int AV = (BM*BK/4)/TPB;
    constexpr int BV = (BK*BN/4)/TPB;
    constexpr int T = CIN/BK;
    constexpr int MT = 2;
    constexpr int NT = BN/16;

    __shared__ float As[2][BK][BMp];
    __shared__ float Bs[2][BK][BNp];

    int tid = threadIdx.x, lane = tid & 31, warp = tid >> 5;
    int m0 = (warp >> 1) * 32;
    int n0 = (warp & 1) * (BN/2);
    int row0 = blockIdx.x * BM;
    int gid = lane >> 2, tig = lane & 3;

    int am[AV], akq[AV], aar[AV]; float asc[AV];
    #pragma unroll
    for (int u = 0; u < AV; u++){
        int f = tid + u*TPB;
        am[u] = f >> 2; akq[u] = (f & 3) << 2;
        int r = row0 + am[u];
        aar[u] = -1; asc[u] = 1.f;
        if (r < n){
            int ar = r;
            if (GATHER){ ar = perm[r]; asc[u] = score[ar]; }
            aar[u] = ar;
        }
    }
    int bkk[BV], bc4[BV];
    #pragma unroll
    for (int u = 0; u < BV; u++){
        int f = tid + u*TPB;
        bkk[u] = f / (BN/4); bc4[u] = (f % (BN/4)) << 2;
    }

    float4 ra[AV], rbh[BV], rbl[BV];
    auto load_tile = [&](int t){
        int k0 = t * BK;
        #pragma unroll
        for (int u = 0; u < AV; u++){
            float4 v = make_float4(0.f,0.f,0.f,0.f);
            if (aar[u] >= 0){
                v = *(const float4*)(A1 + (size_t)aar[u]*CIN + k0 + akq[u]);
                if (GATHER){ v.x*=asc[u]; v.y*=asc[u]; v.z*=asc[u]; v.w*=asc[u]; }
            }
            ra[u] = v;
        }
        #pragma unroll
        for (int u = 0; u < BV; u++){
            size_t off = (size_t)(k0 + bkk[u])*BN + bc4[u];
            rbh[u] = *(const float4*)(Whi + off);
            rbl[u] = *(const float4*)(Wlo + off);
        }
    };
    auto store_split = [&](){
        #pragma unroll
        for (int u = 0; u < AV; u++){
            const float* s = (const float*)&ra[u];
            #pragma unroll
            for (int q = 0; q < 4; q++){
                float hi, lo; tf32_split(s[q], hi, lo);
                As[0][akq[u]+q][am[u]] = hi;
                As[1][akq[u]+q][am[u]] = lo;
            }
        }
        #pragma unroll
        for (int u = 0; u < BV; u++){
            *(float4*)&Bs[0][bkk[u]][bc4[u]] = rbh[u];
            *(float4*)&Bs[1][bkk[u]][bc4[u]] = rbl[u];
        }
    };

    float acc[MT][NT][4];
    #pragma unroll
    for (int mi = 0; mi < MT; mi++)
        #pragma unroll
        for (int ni = 0; ni < NT; ni++)
            #pragma unroll
            for (int q = 0; q < 4; q++) acc[mi][ni][q] = 0.f;

    load_tile(0);
    for (int t = 0; t < T; t++){
        store_split();
        __syncthreads();
        if (t + 1 < T) load_tile(t + 1);
        #pragma unroll
        for (int kk = 0; kk < 2; kk++){
            int ko = kk * 8;
            unsigned ah[MT][4], al[MT][4];
            #pragma unroll
            for (int mi = 0; mi < MT; mi++){
                int mb = m0 + mi*16 + gid;
                ah[mi][0] = __float_as_uint(As[0][ko+tig  ][mb  ]);
                ah[mi][1] = __float_as_uint(As[0][ko+tig  ][mb+8]);
                ah[mi][2] = __float_as_uint(As[0][ko+tig+4][mb  ]);
                ah[mi][3] = __float_as_uint(As[0][ko+tig+4][mb+8]);
                al[mi][0] = __float_as_uint(As[1][ko+tig  ][mb  ]);
                al[mi][1] = __float_as_uint(As[1][ko+tig  ][mb+8]);
                al[mi][2] = __float_as_uint(As[1][ko+tig+4][mb  ]);
                al[mi][3] = __float_as_uint(As[1][ko+tig+4][mb+8]);
            }
            #pragma unroll
            for (int ni = 0; ni < NT; ni++){
                int nb = n0 + ni*8 + gid;
                unsigned bh0 = __float_as_uint(Bs[0][ko+tig  ][nb]);
                unsigned bh1 = __float_as_uint(Bs[0][ko+tig+4][nb]);
                unsigned bl0 = __float_as_uint(Bs[1][ko+tig  ][nb]);
                unsigned bl1 = __float_as_uint(Bs[1][ko+tig+4][nb]);
                #pragma unroll
                for (int mi = 0; mi < MT; mi++){
                    MMA_TF32(acc[mi][ni], ah[mi][0],ah[mi][1],ah[mi][2],ah[mi][3], bh0,bh1);
                    MMA_TF32(acc[mi][ni], ah[mi][0],ah[mi][1],ah[mi][2],ah[mi][3], bl0,bl1);
                    MMA_TF32(acc[mi][ni], al[mi][0],al[mi][1],al[mi][2],al[mi][3], bh0,bh1);
                }
            }
        }
        __syncthreads();
    }

    #pragma unroll
    for (int mi = 0; mi < MT; mi++){
        #pragma unroll
        for (int ni = 0; ni < NT; ni++){
            int cc = n0 + ni*8 + tig*2;
            #pragma unroll
            for (int h = 0; h < 2; h++){
                int rr = row0 + m0 + mi*16 + gid + h*8;
                if (rr < n){
                    float v0 = acc[mi][ni][h*2+0];
                    float v1 = acc[mi][ni][h*2+1];
                    if (bias){ v0 += __ldg(&bias[cc]); v1 += __ldg(&bias[cc+1]); }
                    if (D){ v0 += D[(size_t)rr*BN + cc]; v1 += D[(size_t)rr*BN + cc + 1]; }
                    if (RELU){ v0 = fmaxf(v0, 0.f); v1 = fmaxf(v1, 0.f); }
                    *(float2*)(out + (size_t)rr*BN + cc) = make_float2(v0, v1);
                }
            }
        }
    }
}

// ---------------- bf16 GEMM: pre-packed weight planes [BN][KTOT/2 words] ----------------
// DUAL concatenates A along k: tiles [0,CINA) from A1, [CINA,KTOT) from A2.
template<int BN, int KTOT, int CINA, bool DUAL, bool RELU, bool GATHER>
__global__ void __launch_bounds__(256, 2) gemm_bf16_kernel(
    const float* __restrict__ A1, const float* __restrict__ A2,
    const unsigned* __restrict__ Wh, const unsigned* __restrict__ Wl,
    const float* __restrict__ bias, const float* __restrict__ D,
    float* __restrict__ out, int n,
    const int* __restrict__ perm, const float* __restrict__ score)
{
    constexpr int BM = 128, BK = 32, TPB = 256;
    constexpr int STR = 20;
    constexpr int AV = (BM*BK/4)/TPB;
    constexpr int BV = (BN*BK/4)/TPB;
    constexpr int TILESA = CINA/BK;
    constexpr int T = KTOT/BK;
    constexpr int KW = KTOT/2;
    constexpr int MT = 2;
    constexpr int NT = BN/16;

    __shared__ unsigned As[2][BM][STR];
    __shared__ unsigned Bs[2][BN][STR];

    int tid = threadIdx.x, lane = tid & 31, warp = tid >> 5;
    int m0 = (warp >> 1) * 32;
    int n0 = (warp & 1) * (BN/2);
    int row0 = blockIdx.x * BM;
    int gid = lane >> 2, tig = lane & 3;

    int am[AV], akq[AV], aar[AV]; float asc[AV];
    #pragma unroll
    for (int u = 0; u < AV; u++){
        int f = tid + u*TPB;
        am[u] = f >> 3; akq[u] = (f & 7) << 2;
        int r = row0 + am[u];
        aar[u] = -1; asc[u] = 1.f;
        if (r < n){
            int ar = r;
            if (GATHER){ ar = perm[r]; asc[u] = score[ar]; }
            aar[u] = ar;
        }
    }
    int bm[BV], bkq[BV];
    #pragma unroll
    for (int u = 0; u < BV; u++){
        int f = tid + u*TPB;
        bm[u] = f >> 3; bkq[u] = (f & 7) << 2;
    }

    float4 ra[AV];
    uint2 rbh[BV], rbl[BV];
    auto load_tile = [&](int t){
        int ph = DUAL ? (t / TILESA) : 0;
        int k0a = (t % TILESA) * BK;
        int k0w = t * (BK/2);
        const float* A = (DUAL && ph) ? A2 : A1;
        #pragma unroll
        for (int u = 0; u < AV; u++){
            float4 v = make_float4(0.f,0.f,0.f,0.f);
            if (aar[u] >= 0){
                v = *(const float4*)(A + (size_t)aar[u]*CINA + k0a + akq[u]);
                if (GATHER){ v.x*=asc[u]; v.y*=asc[u]; v.z*=asc[u]; v.w*=asc[u]; }
            }
            ra[u] = v;
        }
        #pragma unroll
        for (int u = 0; u < BV; u++){
            size_t off = (size_t)bm[u]*KW + k0w + (bkq[u] >> 1);
            rbh[u] = *(const uint2*)(Wh + off);
            rbl[u] = *(const uint2*)(Wl + off);
        }
    };
    auto store_split = [&](){
        #pragma unroll
        for (int u = 0; u < AV; u++){
            const float* s = (const float*)&ra[u];
            unsigned short h0,l0,h1,l1,h2,l2,h3,l3;
            bf16_split(s[0],h0,l0); bf16_split(s[1],h1,l1);
            bf16_split(s[2],h2,l2); bf16_split(s[3],h3,l3);
            int w = akq[u] >> 1;
            As[0][am[u]][w  ] = (unsigned)h0 | ((unsigned)h1 << 16);
            As[0][am[u]][w+1] = (unsigned)h2 | ((unsigned)h3 << 16);
            As[1][am[u]][w  ] = (unsigned)l0 | ((unsigned)l1 << 16);
            As[1][am[u]][w+1] = (unsigned)l2 | ((unsigned)l3 << 16);
        }
        #pragma unroll
        for (int u = 0; u < BV; u++){
            int w = bkq[u] >> 1;
            *(uint2*)&Bs[0][bm[u]][w] = rbh[u];
            *(uint2*)&Bs[1][bm[u]][w] = rbl[u];
        }
    };

    float acc[MT][NT][4];
    #pragma unroll
    for (int mi = 0; mi < MT; mi++)
        #pragma unroll
        for (int ni = 0; ni < NT; ni++)
            #pragma unroll
            for (int q = 0; q < 4; q++) acc[mi][ni][q] = 0.f;

    load_tile(0);
    for (int t = 0; t < T; t++){
        store_split();
        __syncthreads();
        if (t + 1 < T) load_tile(t + 1);
        #pragma unroll
        for (int kk = 0; kk < 2; kk++){
            int ko = kk * 8;
            unsigned ah[MT][4], al[MT][4];
            #pragma unroll
            for (int mi = 0; mi < MT; mi++){
                int mb = m0 + mi*16 + gid;
                ah[mi][0] = As[0][mb  ][ko+tig  ];
                ah[mi][1] = As[0][mb+8][ko+tig  ];
                ah[mi][2] = As[0][mb  ][ko+tig+4];
                ah[mi][3] = As[0][mb+8][ko+tig+4];
                al[mi][0] = As[1][mb  ][ko+tig  ];
                al[mi][1] = As[1][mb+8][ko+tig  ];
                al[mi][2] = As[1][mb  ][ko+tig+4];
                al[mi][3] = As[1][mb+8][ko+tig+4];
            }
            #pragma unroll
            for (int ni = 0; ni < NT; ni++){
                int nb = n0 + ni*8 + gid;
                unsigned bh0 = Bs[0][nb][ko+tig  ];
                unsigned bh1 = Bs[0][nb][ko+tig+4];
                unsigned bl0 = Bs[1][nb][ko+tig  ];
                unsigned bl1 = Bs[1][nb][ko+tig+4];
                #pragma unroll
                for (int mi = 0; mi < MT; mi++){
                    MMA_BF16(acc[mi][ni], ah[mi][0],ah[mi][1],ah[mi][2],ah[mi][3], bh0,bh1);
                    MMA_BF16(acc[mi][ni], ah[mi][0],ah[mi][1],ah[mi][2],ah[mi][3], bl0,bl1);
                    MMA_BF16(acc[mi][ni], al[mi][0],al[mi][1],al[mi][2],al[mi][3], bh0,bh1);
                }
            }
        }
        __syncthreads();
    }

    #pragma unroll
    for (int mi = 0; mi < MT; mi++){
        #pragma unroll
        for (int ni = 0; ni < NT; ni++){
            int cc = n0 + ni*8 + tig*2;
            #pragma unroll
            for (int h = 0; h < 2; h++){
                int rr = row0 + m0 + mi*16 + gid + h*8;
                if (rr < n){
                    float v0 = acc[mi][ni][h*2+0];
                    float v1 = acc[mi][ni][h*2+1];
                    if (bias){ v0 += __ldg(&bias[cc]); v1 += __ldg(&bias[cc+1]); }
                    if (D){ v0 += D[(size_t)rr*BN + cc]; v1 += D[(size_t)rr*BN + cc + 1]; }
                    if (RELU){ v0 = fmaxf(v0, 0.f); v1 = fmaxf(v1, 0.f); }
                    *(float2*)(out + (size_t)rr*BN + cc) = make_float2(v0, v1);
                }
            }
        }
    }
}

// ---------------- elementwise: x = relu(t[:,64:128] + agg + bias), t stride 128 ----------------
__global__ void merge_conv_kernel(const float* __restrict__ t, const float* __restrict__ agg,
                                  const float* __restrict__ bias, float* __restrict__ xout, int n)
{
    int idx = blockIdx.x*blockDim.x + threadIdx.x;
    int total = n * 16;
    if (idx >= total) return;
    int i = idx >> 4, c4 = (idx & 15) << 2;
    float4 r = *(const float4*)(t + (size_t)i*128 + 64 + c4);
    float4 a = *(const float4*)(agg + (size_t)i*64 + c4);
    float4 b = *(const float4*)(bias + c4);
    r.x = fmaxf(r.x + a.x + b.x, 0.f);
    r.y = fmaxf(r.y + a.y + b.y, 0.f);
    r.z = fmaxf(r.z + a.z + b.z, 0.f);
    r.w = fmaxf(r.w + a.w + b.w, 0.f);
    *(float4*)(xout + (size_t)i*64 + c4) = r;
}

// ---------------- topk pooling ----------------
template<int C>
__global__ void score_kernel(const float* __restrict__ x, const float* __restrict__ w, int n)
{
    int gw = blockIdx.x*(blockDim.x>>5) + (threadIdx.x>>5);
    int lane = threadIdx.x & 31;
    if (gw >= n) return;
    float p, q;
    if constexpr (C == 128){
        float4 xv = ((const float4*)(x + (size_t)gw*128))[lane];
        float4 wv = ((const float4*)w)[lane];
        p = xv.x*wv.x + xv.y*wv.y + xv.z*wv.z + xv.w*wv.w;
        q = wv.x*wv.x + wv.y*wv.y + wv.z*wv.z + wv.w*wv.w;
    } else {
        float2 xv = ((const float2*)(x + (size_t)gw*64))[lane];
        float2 wv = ((const float2*)w)[lane];
        p = xv.x*wv.x + xv.y*wv.y;
        q = wv.x*wv.x + wv.y*wv.y;
    }
    #pragma unroll
    for (int off = 16; off; off >>= 1){
        p += __shfl_xor_sync(0xffffffffu, p, off);
        q += __shfl_xor_sync(0xffffffffu, q, off);
    }
    if (lane == 0){
        float s = tanhf(p / sqrtf(q));
        g_score[gw] = s;
        unsigned u = __float_as_uint(s);
        u = (u & 0x80000000u) ? ~u : (u | 0x80000000u);
        g_key[gw] = u;
    }
}

// ONE-KERNEL radix select + compact; keys staged in dynamic shared memory.
__global__ void __launch_bounds__(1024) topk_select_kernel(
    int* __restrict__ mapping, int* __restrict__ perm, int n, int k)
{
    extern __shared__ unsigned skey[];
    __shared__ unsigned hist[256];
    __shared__ int ws[32];
    __shared__ int s_b, s_rem;

    for (int i = threadIdx.x; i < n; i += 1024) skey[i] = g_key[i];
    __syncthreads();

    unsigned prefix = 0;
    int remaining = k;
    for (int pass = 3; pass >= 0; pass--){
        for (int t = threadIdx.x; t < 256; t += 1024) hist[t] = 0;
        __syncthreads();
        int shf = (pass+1)*8;
        unsigned pref_hi = (pass == 3) ? 0u : (prefix >> shf);
        for (int base = 0; base < n; base += 1024){
            int i = base + threadIdx.x;
            if (i < n){
                unsigned key = skey[i];
                bool ok = (pass == 3) || ((key >> shf) == pref_hi);
                if (ok) atomicAdd(&hist[(key >> (pass*8)) & 255], 1u);
            }
        }
        __syncthreads();
        if (threadIdx.x == 0){
            unsigned r = (unsigned)remaining;
            unsigned c = 0; int b = 255;
            for (; b > 0; b--){
                unsigned h = hist[b];
                if (c + h >= r) break;
                c += h;
            }
            s_b = b; s_rem = (int)(r - c);
        }
        __syncthreads();
        prefix |= ((unsigned)s_b) << (pass*8);
        remaining = s_rem;
        __syncthreads();
    }

    unsigned thr = prefix;
    int local = 0;
    for (int base = 0; base < n; base += 1024){
        int i = base + threadIdx.x;
        if (i < n) local += (skey[i] > thr) ? 1 : 0;
    }
    int totG; block_scan_incl(local, totG, ws);
    int need_eq = k - totG;

    int run_eq = 0, run_sel = 0;
    for (int base = 0; base < n; base += 1024){
        int i = base + threadIdx.x;
        int gt = 0, eq = 0;
        if (i < n){
            unsigned kv = skey[i];
            gt = (kv > thr); eq = (kv == thr);
        }
        int tot_eq; int incl_eq = block_scan_incl(eq, tot_eq, ws);
        int excl_eq = incl_eq - eq;
        int sel = gt | (eq & ((run_eq + excl_eq) < need_eq ? 1 : 0));
        int tot_sel; int incl_sel = block_scan_incl(sel, tot_sel, ws);
        if (i < n){
            if (sel){
                int idx = run_sel + incl_sel - 1;
                mapping[i] = idx;
                perm[idx] = i;
            } else mapping[i] = -1;
        }
        run_eq += tot_eq; run_sel += tot_sel;
    }
}

// fused compose of level0->level2 mapping and perm
__global__ void compose_kernel()
{
    int i = blockIdx.x*blockDim.x + threadIdx.x;
    if (i < N0){ int m = g_map1[i]; g_map02[i] = (m >= 0) ? g_map2[m] : -1; }
    if (i < K2) g_perm02[i] = g_perm1[g_perm2[i]];
}

template<int C>
__global__ void unpool_kernel(const float* __restrict__ xb, const float* __restrict__ xs,
                              const int* __restrict__ mapping, float* __restrict__ out, int n)
{
    int idx = blockIdx.x*blockDim.x + threadIdx.x;
    int total = n * (C/4);
    if (idx >= total) return;
    int i = idx / (C/4), t = idx % (C/4);
    int m = mapping[i];
    float4 v = ((const float4*)(xb + (size_t)i*C))[t];
    if (m >= 0){
        float4 w = ((const float4*)(xs + (size_t)m*C))[t];
        v.x += w.x; v.y += w.y; v.z += w.z; v.w += w.w;
    }
    ((float4*)(out + (size_t)i*C))[t] = v;
}

// ---------------- final linear + log_softmax (warp per node) ----------------
__global__ void final_kernel(const float* __restrict__ x, const float* __restrict__ lw,
                             const float* __restrict__ lb, float* __restrict__ out, int n)
{
    int gw = blockIdx.x*(blockDim.x>>5) + (threadIdx.x>>5);
    int lane = threadIdx.x & 31;
    if (gw >= n) return;
    float4 xv = ((const float4*)(x + (size_t)gw*128))[lane];
    float lg[10]; float myv = 0.f;
    #pragma unroll
    for (int c = 0; c < 10; c++){
        float4 wv = ((const float4*)(lw + c*128))[lane];
        float p = xv.x*wv.x + xv.y*wv.y + xv.z*wv.z + xv.w*wv.w;
        #pragma unroll
        for (int off = 16; off; off >>= 1) p += __shfl_xor_sync(0xffffffffu, p, off);
        p += __ldg(&lb[c]);
        lg[c] = p;
        if (lane == c) myv = p;
    }
    float m = lg[0];
    #pragma unroll
    for (int c = 1; c < 10; c++) m = fmaxf(m, lg[c]);
    float s = 0.f;
    #pragma unroll
    for (int c = 0; c < 10; c++) s += expf(lg[c] - m);
    float lse = m + logf(s);
    if (lane < 10) out[(size_t)gw*10 + lane] = myv - lse;
}

// ---------------- host driver ----------------
extern "C" void kernel_launch(void* const* d_in, const int* in_sizes, int n_in,
                              void* d_out, int out_size)
{
    (void)in_sizes; (void)n_in; (void)out_size;
    const float* x    = (const float*)d_in[0];
    const int*   ei   = (const int*)d_in[1];
    const int*   src0 = ei;
    const int*   dst0 = ei + E0;
    const float *w1r=(const float*)d_in[2], *w1o=(const float*)d_in[3], *b1=(const float*)d_in[4], *p1w=(const float*)d_in[5];
    const float *w2r=(const float*)d_in[6], *w2o=(const float*)d_in[7], *b2=(const float*)d_in[8], *p2w=(const float*)d_in[9];
    const float *w3r=(const float*)d_in[10],*w3o=(const float*)d_in[11],*b3=(const float*)d_in[12];
    const float *w4r=(const float*)d_in[13],*w4o=(const float*)d_in[14],*b4=(const float*)d_in[15];
    const float *w5r=(const float*)d_in[16],*w5o=(const float*)d_in[17],*b5=(const float*)d_in[18];
    const float *lw =(const float*)d_in[19],*lb =(const float*)d_in[20];
    float* out = (float*)d_out;

    float *x1,*agg,*x2,*x3,*u1,*x4,*u2,*x5,*wHi,*wLo,*score;
    unsigned *wb3h,*wb3l,*wb4h,*wb4l,*wb5h,*wb5l;
    int *rowptr,*fill,*part,*partx,*map1,*perm1,*map2,*perm2,*map02,*perm02;
    cudaGetSymbolAddress((void**)&x1, g_x1);
    cudaGetSymbolAddress((void**)&agg, g_agg);
    cudaGetSymbolAddress((void**)&x2, g_x2);
    cudaGetSymbolAddress((void**)&x3, g_x3);
    cudaGetSymbolAddress((void**)&u1, g_u1);
    cudaGetSymbolAddress((void**)&x4, g_x4);
    cudaGetSymbolAddress((void**)&u2, g_u2);
    cudaGetSymbolAddress((void**)&x5, g_x5);
    cudaGetSymbolAddress((void**)&wHi, g_wHi);
    cudaGetSymbolAddress((void**)&wLo, g_wLo);
    cudaGetSymbolAddress((void**)&wb3h, g_wb3h);
    cudaGetSymbolAddress((void**)&wb3l, g_wb3l);
    cudaGetSymbolAddress((void**)&wb4h, g_wb4h);
    cudaGetSymbolAddress((void**)&wb4l, g_wb4l);
    cudaGetSymbolAddress((void**)&wb5h, g_wb5h);
    cudaGetSymbolAddress((void**)&wb5l, g_wb5l);
    cudaGetSymbolAddress((void**)&score, g_score);
    cudaGetSymbolAddress((void**)&rowptr, g_rowptr);
    cudaGetSymbolAddress((void**)&fill, g_fill);
    cudaGetSymbolAddress((void**)&part, g_part);
    cudaGetSymbolAddress((void**)&partx, g_partx);
    cudaGetSymbolAddress((void**)&map1, g_map1);
    cudaGetSymbolAddress((void**)&perm1, g_perm1);
    cudaGetSymbolAddress((void**)&map2, g_map2);
    cudaGetSymbolAddress((void**)&perm2, g_perm2);
    cudaGetSymbolAddress((void**)&map02, g_map02);
    cudaGetSymbolAddress((void**)&perm02, g_perm02);

    const int W = 16384;
    float* t2 = x4;   // conv2 cat output [K1][128]
    float* t3 = u2;   // conv3 cat output [K2][128]

    cudaFuncSetAttribute(topk_select_kernel,
                         cudaFuncAttributeMaxDynamicSharedMemorySize, N0*sizeof(unsigned) + 1024);

    cudaStream_t s2;
    cudaEvent_t ev1, ev2;
    cudaStreamCreateWithFlags(&s2, cudaStreamNonBlocking);
    cudaEventCreateWithFlags(&ev1, cudaEventDisableTiming);
    cudaEventCreateWithFlags(&ev2, cudaEventDisableTiming);

    // ---- prologue fork (CSR has serialization bubbles; weight prep + GEMM fill them) ----
    cudaEventRecord(ev1, 0);
    cudaStreamWaitEvent(s2, ev1, 0);
    {
        dim3 g1(64, 4);
        prep_tf32_kernel<<<g1,256>>>(w1r, w1o, w2r, w2o);
        dim3 g2(64, 3);
        prep_bf16_kernel<<<g2,256>>>(w3r, w3o, w4r, w4o, w5r, w5o);
    }
    zero_int_kernel<<<(N0+255)/256,256,0,s2>>>(fill, N0);
    edge_count_kernel<<<(E0+255)/256,256,0,s2>>>(dst0);
    gemm_tf32_kernel<128,128,false,false><<<(N0+127)/128,256>>>(
        x, wHi+1*W, wLo+1*W, nullptr, nullptr, x1, N0, nullptr, nullptr);
    deg_reduce_kernel<<<NB_SCAN,1024,0,s2>>>(fill, part, N0);
    scan_kernel<<<1,1024,0,s2>>>(part, partx, NB_SCAN);
    deg_apply_kernel<<<NB_SCAN,1024,0,s2>>>(fill, partx, rowptr, N0);
    edge_scatter_kernel<<<(E0+255)/256,256,0,s2>>>(src0, dst0);
    agg_kernel<128><<<(N0+7)/8,256,0,s2>>>(x, agg, nullptr, nullptr, N0, 128);
    cudaEventRecord(ev2, s2);
    cudaStreamWaitEvent(0, ev2, 0);

    // conv1 rel-half (D add, bias, relu)
    gemm_tf32_kernel<128,128,true,false><<<(N0+127)/128,256>>>(
        agg, wHi+0*W, wLo+0*W, b1, x1, x1, N0, nullptr, nullptr);

    // pool1
    score_kernel<128><<<(N0+7)/8,256>>>(x1, p1w, N0);
    topk_select_kernel<<<1,1024,N0*sizeof(unsigned)>>>(map1, perm1, N0, K1);

    // conv2 (tf32 N-cat): t2 = gather(x1)·[W2r^T|W2o^T]; agg left half; merge
    gemm_tf32_kernel<128,128,false,true><<<(K1+127)/128,256>>>(
        x1, wHi+2*W, wLo+2*W, nullptr, nullptr, t2, K1, perm1, score);
    agg_kernel<64><<<(K1+7)/8,256>>>(t2, agg, perm1, map1, K1, 128);
    merge_conv_kernel<<<(K1*16+255)/256,256>>>(t2, agg, b2, x2, K1);

    // pool2
    score_kernel<64><<<(K1+7)/8,256>>>(x2, p2w, K1);
    topk_select_kernel<<<1,1024,K1*sizeof(unsigned)>>>(map2, perm2, K1, K2);
    compose_kernel<<<(N0+255)/256,256>>>();

    // conv3 (bf16 N-cat): t3 = gather(x2)·[W3r|W3o]; agg left half; merge
    gemm_bf16_kernel<128,64,64,false,false,true><<<(K2+127)/128,256>>>(
        x2, nullptr, wb3h, wb3l, nullptr, nullptr, t3, K2, perm2, score);
    agg_kernel<64><<<(K2+7)/8,256>>>(t3, agg, perm02, map02, K2, 128);
    merge_conv_kernel<<<(K2*16+255)/256,256>>>(t3, agg, b3, x3, K2);

    // unpool1 + skip
    unpool_kernel<64><<<(K1*16+255)/256,256>>>(x2, x3, map2, u1, K1);

    // conv4 (bf16 K-cat): relu(agg·W4r + u1·W4o + b4)
    agg_kernel<64><<<(K1+7)/8,256>>>(u1, agg, perm1, map1, K1, 64);
    gemm_bf16_kernel<128,128,64,true,true,false><<<(K1+127)/128,256>>>(
        agg, u1, wb4h, wb4l, b4, nullptr, x4, K1, nullptr, nullptr);

    // unpool2 + skip
    unpool_kernel<128><<<(N0*32+255)/256,256>>>(x1, x4, map1, u2, N0);

    // conv5 (bf16 K-cat)
    agg_kernel<128><<<(N0+7)/8,256>>>(u2, agg, nullptr, nullptr, N0, 128);
    gemm_bf16_kernel<128,256,128,true,true,false><<<(N0+127)/128,256>>>(
        agg, u2, wb5h, wb5l, b5, nullptr, x5, N0, nullptr, nullptr);

    // final linear + log_softmax
    final_kernel<<<(N0+7)/8,256>>>(x5, lw, lb, out, N0);
}

// round 14
// speedup vs baseline: 1.1421x; 1.0232x over previous
#include <cuda_runtime.h>
#include <cuda_bf16.h>
#include <math.h>

#define N0 50000
#define E0 1600000
#define K1 40000
#define K2 32000
#define NB_SCAN 49   // ceil(N0/1024)

// ---------------- scratch (device globals; no runtime allocation) ----------------
__device__ float g_x1[N0*128];
__device__ float g_agg[N0*128];
__device__ float g_x2[K1*64];
__device__ float g_u1[K1*64];
__device__ float g_x4[K1*128];     // also conv2 cat-GEMM output t2
__device__ float g_u2[N0*128];     // also conv3 cat-GEMM output t3
__device__ float g_x5[N0*128];
__device__ int   g_rowptr[N0+1];
__device__ int   g_fill[N0];
__device__ int   g_part[64];
__device__ int   g_partx[66];
__device__ int   g_esrc[E0];
__device__ float g_score[N0];
__device__ unsigned g_key[N0];
__device__ int   g_map1[N0];
__device__ int   g_perm1[K1];
__device__ int   g_map2[K1];
__device__ int   g_perm2[K2];
__device__ int   g_map02[N0];
__device__ int   g_perm02[K2];
// tf32 pre-split transposed weight planes: 0=W1r^T, 1=W1o^T, 2=[W2r^T|W2o^T]
__device__ float g_wHi[3*16384];
__device__ float g_wLo[3*16384];
// bf16 pre-packed hi/lo word planes
__device__ unsigned g_wb3h[128*32],  g_wb3l[128*32];
__device__ unsigned g_wb4h[128*64],  g_wb4l[128*64];
__device__ unsigned g_wb5h[128*128], g_wb5l[128*128];

// ---------------- CSR build ----------------
__global__ void zero_int_kernel(int* p, int n)
{
    int i = blockIdx.x*blockDim.x + threadIdx.x;
    if (i < n) p[i] = 0;
}

__global__ void edge_count_kernel(const int* __restrict__ dst)
{
    int e = blockIdx.x*blockDim.x + threadIdx.x;
    if (e < E0) atomicAdd(&g_fill[dst[e]], 1);
}

__device__ __forceinline__ int block_scan_incl(int val, int& total, int* ws)
{
    int lane = threadIdx.x & 31, wid = threadIdx.x >> 5;
    int x = val;
    #pragma unroll
    for (int off = 1; off < 32; off <<= 1){
        int y = __shfl_up_sync(0xffffffffu, x, off);
        if (lane >= off) x += y;
    }
    if (lane == 31) ws[wid] = x;
    __syncthreads();
    if (wid == 0){
        int s = ws[lane];
        #pragma unroll
        for (int off = 1; off < 32; off <<= 1){
            int y = __shfl_up_sync(0xffffffffu, s, off);
            if (lane >= off) s += y;
        }
        ws[lane] = s;
    }
    __syncthreads();
    int res = x + (wid ? ws[wid-1] : 0);
    total = ws[31];
    __syncthreads();
    return res;
}

__global__ void scan_kernel(const int* __restrict__ in, int* __restrict__ out, int n)
{
    __shared__ int ws[32];
    int run = 0;
    for (int base = 0; base < n; base += 1024){
        int i = base + threadIdx.x;
        int v = (i < n) ? in[i] : 0;
        int tot; int incl = block_scan_incl(v, tot, ws);
        if (i < n) out[i] = run + incl - v;
        run += tot;
    }
    if (threadIdx.x == 0) out[n] = run;
}

__global__ void deg_reduce_kernel(const int* __restrict__ in, int* __restrict__ part, int n)
{
    __shared__ int ws[32];
    int i = blockIdx.x*1024 + threadIdx.x;
    int v = (i < n) ? in[i] : 0;
    int lane = threadIdx.x & 31, wid = threadIdx.x >> 5;
    #pragma unroll
    for (int off = 16; off; off >>= 1) v += __shfl_down_sync(0xffffffffu, v, off);
    if (lane == 0) ws[wid] = v;
    __syncthreads();
    if (wid == 0){
        v = ws[lane];
        #pragma unroll
        for (int off = 16; off; off >>= 1) v += __shfl_down_sync(0xffffffffu, v, off);
        if (lane == 0) part[blockIdx.x] = v;
    }
}

__global__ void deg_apply_kernel(const int* __restrict__ in, const int* __restrict__ partx,
                                 int* __restrict__ rowptr, int n)
{
    __shared__ int ws[32];
    int i = blockIdx.x*1024 + threadIdx.x;
    int v = (i < n) ? in[i] : 0;
    int tot; int incl = block_scan_incl(v, tot, ws);
    if (i < n) rowptr[i] = partx[blockIdx.x] + incl - v;
    if (i == n) rowptr[n] = partx[gridDim.x];
}

__global__ void edge_scatter_kernel(const int* __restrict__ src, const int* __restrict__ dst)
{
    int e = blockIdx.x*blockDim.x + threadIdx.x;
    if (e < E0){
        int d = dst[e];
        int off = atomicSub(&g_fill[d], 1) - 1;
        g_esrc[g_rowptr[d] + off] = src[e];
    }
}

// ---------------- split helpers ----------------
__device__ __forceinline__ void tf32_split(float a, float& hi, float& lo)
{
    unsigned h;
    asm("cvt.rna.tf32.f32 %0, %1;" : "=r"(h) : "f"(a));
    float hf = __uint_as_float(h);
    float l = a - hf;
    unsigned lu;
    asm("cvt.rna.tf32.f32 %0, %1;" : "=r"(lu) : "f"(l));
    hi = hf; lo = __uint_as_float(lu);
}

__device__ __forceinline__ unsigned short f2bf(float x)
{
    __nv_bfloat16 b = __float2bfloat16(x);
    return *reinterpret_cast<unsigned short*>(&b);
}
__device__ __forceinline__ void bf16_split(float x, unsigned short& hi, unsigned short& lo)
{
    __nv_bfloat16 h = __float2bfloat16(x);
    float hf = __bfloat162float(h);
    hi = *reinterpret_cast<unsigned short*>(&h);
    lo = f2bf(x - hf);
}

// ---------------- weight preprocessing ----------------
__global__ void prep_tf32_kernel(const float* w0, const float* w1, const float* w2, const float* w3)
{
    const float* ws[4] = {w0,w1,w2,w3};
    const int CO[4] = {128,128,64,64};
    int m = blockIdx.y;
    int idx = blockIdx.x*blockDim.x + threadIdx.x;
    int nEl = CO[m]*128;
    if (idx < nEl){
        int r = idx >> 7, c = idx & 127;
        float hi, lo; tf32_split(ws[m][idx], hi, lo);
        int off = (m < 2) ? (m*16384 + c*128 + r)
                          : (2*16384 + c*128 + (m == 3 ? 64 : 0) + r);
        g_wHi[off] = hi; g_wLo[off] = lo;
    }
}

__global__ void prep_bf16_kernel(const float* w3r, const float* w3o,
                                 const float* w4r, const float* w4o,
                                 const float* w5r, const float* w5o)
{
    int m = blockIdx.y;
    int idx = blockIdx.x*blockDim.x + threadIdx.x;
    if (m == 0){
        if (idx < 128*32){
            int r = idx >> 5, w = idx & 31;
            const float* src = (r < 64) ? (w3r + r*64) : (w3o + (r-64)*64);
            unsigned short h0,l0,h1,l1;
            bf16_split(src[w*2],   h0, l0);
            bf16_split(src[w*2+1], h1, l1);
            g_wb3h[idx] = (unsigned)h0 | ((unsigned)h1 << 16);
            g_wb3l[idx] = (unsigned)l0 | ((unsigned)l1 << 16);
        }
    } else if (m == 1){
        if (idx < 128*64){
            int r = idx >> 6, w = idx & 63;
            int k = w*2;
            const float* src = (k < 64) ? (w4r + r*64 + k) : (w4o + r*64 + k - 64);
            unsigned short h0,l0,h1,l1;
            bf16_split(src[0], h0, l0);
            bf16_split(src[1], h1, l1);
            g_wb4h[idx] = (unsigned)h0 | ((unsigned)h1 << 16);
            g_wb4l[idx] = (unsigned)l0 | ((unsigned)l1 << 16);
        }
    } else {
        if (idx < 128*128){
            int r = idx >> 7, w = idx & 127;
            int k = w*2;
            const float* src = (k < 128) ? (w5r + r*128 + k) : (w5o + r*128 + k - 128);
            unsigned short h0,l0,h1,l1;
            bf16_split(src[0], h0, l0);
            bf16_split(src[1], h1, l1);
            g_wb5h[idx] = (unsigned)h0 | ((unsigned)h1 << 16);
            g_wb5l[idx] = (unsigned)l0 | ((unsigned)l1 << 16);
        }
    }
}

// ---------------- aggregation: warp per node, x4-unrolled gather for MLP ----------------
template<int C>
__global__ void agg_kernel(const float* __restrict__ xin, float* __restrict__ out,
                           const int* __restrict__ perm, const int* __restrict__ mapping,
                           int n, int instride)
{
    int warp = (blockIdx.x*blockDim.x + threadIdx.x) >> 5;
    int lane = threadIdx.x & 31;
    if (warp >= n) return;
    int old = perm ? perm[warp] : warp;
    int beg = g_rowptr[old], end = g_rowptr[old+1];
    if constexpr (C == 128){
        float4 acc = make_float4(0.f,0.f,0.f,0.f);
        for (int b = beg; b < end; b += 32){
            int e = b + lane;
            int s = -1;
            if (e < end){ s = g_esrc[e]; if (mapping) s = mapping[s]; }
            int cnt = min(32, end - b);
            int j = 0;
            for (; j + 4 <= cnt; j += 4){
                int s0 = __shfl_sync(0xffffffffu, s, j);
                int s1 = __shfl_sync(0xffffffffu, s, j+1);
                int s2 = __shfl_sync(0xffffffffu, s, j+2);
                int s3 = __shfl_sync(0xffffffffu, s, j+3);
                float4 v0 = make_float4(0,0,0,0), v1 = v0, v2 = v0, v3 = v0;
                if (s0 >= 0) v0 = ((const float4*)(xin + (size_t)s0*instride))[lane];
                if (s1 >= 0) v1 = ((const float4*)(xin + (size_t)s1*instride))[lane];
                if (s2 >= 0) v2 = ((const float4*)(xin + (size_t)s2*instride))[lane];
                if (s3 >= 0) v3 = ((const float4*)(xin + (size_t)s3*instride))[lane];
                acc.x += (v0.x + v1.x) + (v2.x + v3.x);
                acc.y += (v0.y + v1.y) + (v2.y + v3.y);
                acc.z += (v0.z + v1.z) + (v2.z + v3.z);
                acc.w += (v0.w + v1.w) + (v2.w + v3.w);
            }
            for (; j < cnt; j++){
                int sj = __shfl_sync(0xffffffffu, s, j);
                if (sj >= 0){
                    float4 v = ((const float4*)(xin + (size_t)sj*instride))[lane];
                    acc.x += v.x; acc.y += v.y; acc.z += v.z; acc.w += v.w;
                }
            }
        }
        ((float4*)(out + (size_t)warp*128))[lane] = acc;
    } else {
        float2 acc = make_float2(0.f,0.f);
        for (int b = beg; b < end; b += 32){
            int e = b + lane;
            int s = -1;
            if (e < end){ s = g_esrc[e]; if (mapping) s = mapping[s]; }
            int cnt = min(32, end - b);
            int j = 0;
            for (; j + 4 <= cnt; j += 4){
                int s0 = __shfl_sync(0xffffffffu, s, j);
                int s1 = __shfl_sync(0xffffffffu, s, j+1);
                int s2 = __shfl_sync(0xffffffffu, s, j+2);
                int s3 = __shfl_sync(0xffffffffu, s, j+3);
                float2 v0 = make_float2(0,0), v1 = v0, v2 = v0, v3 = v0;
                if (s0 >= 0) v0 = ((const float2*)(xin + (size_t)s0*instride))[lane];
                if (s1 >= 0) v1 = ((const float2*)(xin + (size_t)s1*instride))[lane];
                if (s2 >= 0) v2 = ((const float2*)(xin + (size_t)s2*instride))[lane];
                if (s3 >= 0) v3 = ((const float2*)(xin + (size_t)s3*instride))[lane];
                acc.x += (v0.x + v1.x) + (v2.x + v3.x);
                acc.y += (v0.y + v1.y) + (v2.y + v3.y);
            }
            for (; j < cnt; j++){
                int sj = __shfl_sync(0xffffffffu, s, j);
                if (sj >= 0){
                    float2 v = ((const float2*)(xin + (size_t)sj*instride))[lane];
                    acc.x += v.x; acc.y += v.y;
                }
            }
        }
        ((float2*)(out + (size_t)warp*64))[lane] = acc;
    }
}

#define MMA_TF32(d, a0,a1,a2,a3, b0,b1) \
    asm volatile("mma.sync.aligned.m16n8k8.row.col.f32.tf32.tf32.f32 " \
        "{%0,%1,%2,%3}, {%4,%5,%6,%7}, {%8,%9}, {%0,%1,%2,%3};" \
        : "+f"((d)[0]), "+f"((d)[1]), "+f"((d)[2]), "+f"((d)[3]) \
        : "r"(a0), "r"(a1), "r"(a2), "r"(a3), "r"(b0), "r"(b1))

#define MMA_BF16(d, a0,a1,a2,a3, b0,b1) \
    asm volatile("mma.sync.aligned.m16n8k16.row.col.f32.bf16.bf16.f32 " \
        "{%0,%1,%2,%3}, {%4,%5,%6,%7}, {%8,%9}, {%0,%1,%2,%3};" \
        : "+f"((d)[0]), "+f"((d)[1]), "+f"((d)[2]), "+f"((d)[3]) \
        : "r"(a0), "r"(a1), "r"(a2), "r"(a3), "r"(b0), "r"(b1))

// ---------------- tf32 GEMM: pre-split weight planes ----------------
template<int BN, int CIN, bool RELU, bool GATHER>
__global__ void __launch_bounds__(256, 2) gemm_tf32_kernel(
    const float* __restrict__ A1,
    const float* __restrict__ Whi, const float* __restrict__ Wlo,
    const float* __restrict__ bias, const float* __restrict__ D,
    float* __restrict__ out, int n,
    const int* __restrict__ perm, const float* __restrict__ score)
{
    constexpr int BM = 128, BK = 16, TPB = 256;
    constexpr int BMp = 136, BNp = BN + 8;
    constexpr int AV = (BM*BK/4)/TPB;
    constexpr int BV = (BK*BN/4)/TPB;
    constexpr int T = CIN/BK;
    constexpr int MT = 2;
    constexpr int NT = BN/16;

    __shared__ float As[2][BK][BMp];
    __shared__ float Bs[2][BK][BNp];

    int tid = threadIdx.x, lane = tid & 31, warp = tid >> 5;
    int m0 = (warp >> 1) * 32;
    int n0 = (warp & 1) * (BN/2);
    int row0 = blockIdx.x * BM;
    int gid = lane >> 2, tig = lane & 3;

    int am[AV], akq[AV], aar[AV]; float asc[AV];
    #pragma unroll
    for (int u = 0; u < AV; u++){
        int f = tid + u*TPB;
        am[u] = f >> 2; akq[u] = (f & 3) << 2;
        int r = row0 + am[u];
        aar[u] = -1; asc[u] = 1.f;
        if (r < n){
            int ar = r;
            if (GATHER){ ar = perm[r]; asc[u] = score[ar]; }
            aar[u] = ar;
        }
    }
    int bkk[BV], bc4[BV];
    #pragma unroll
    for (int u = 0; u < BV; u++){
        int f = tid + u*TPB;
        bkk[u] = f / (BN/4); bc4[u] = (f % (BN/4)) << 2;
    }

    float4 ra[AV], rbh[BV], rbl[BV];
    auto load_tile = [&](int t){
        int k0 = t * BK;
        #pragma unroll
        for (int u = 0; u < AV; u++){
            float4 v = make_float4(0.f,0.f,0.f,0.f);
            if (aar[u] >= 0){
                v = *(const float4*)(A1 + (size_t)aar[u]*CIN + k0 + akq[u]);
                if (GATHER){ v.x*=asc[u]; v.y*=asc[u]; v.z*=asc[u]; v.w*=asc[u]; }
            }
            ra[u] = v;
        }
        #pragma unroll
        for (int u = 0; u < BV; u++){
            size_t off = (size_t)(k0 + bkk[u])*BN + bc4[u];
            rbh[u] = *(const float4*)(Whi + off);
            rbl[u] = *(const float4*)(Wlo + off);
        }
    };
    auto store_split = [&](){
        #pragma unroll
        for (int u = 0; u < AV; u++){
            const float* s = (const float*)&ra[u];
            #pragma unroll
            for (int q = 0; q < 4; q++){
                float hi, lo; tf32_split(s[q], hi, lo);
                As[0][akq[u]+q][am[u]] = hi;
                As[1][akq[u]+q][am[u]] = lo;
            }
        }
        #pragma unroll
        for (int u = 0; u < BV; u++){
            *(float4*)&Bs[0][bkk[u]][bc4[u]] = rbh[u];
            *(float4*)&Bs[1][bkk[u]][bc4[u]] = rbl[u];
        }
    };

    float acc[MT][NT][4];
    #pragma unroll
    for (int mi = 0; mi < MT; mi++)
        #pragma unroll
        for (int ni = 0; ni < NT; ni++)
            #pragma unroll
            for (int q = 0; q < 4; q++) acc[mi][ni][q] = 0.f;

    load_tile(0);
    for (int t = 0; t < T; t++){
        store_split();
        __syncthreads();
        if (t + 1 < T) load_tile(t + 1);
        #pragma unroll
        for (int kk = 0; kk < 2; kk++){
            int ko = kk * 8;
            unsigned ah[MT][4], al[MT][4];
            #pragma unroll
            for (int mi = 0; mi < MT; mi++){
                int mb = m0 + mi*16 + gid;
                ah[mi][0] = __float_as_uint(As[0][ko+tig  ][mb  ]);
                ah[mi][1] = __float_as_uint(As[0][ko+tig  ][mb+8]);
                ah[mi][2] = __float_as_uint(As[0][ko+tig+4][mb  ]);
                ah[mi][3] = __float_as_uint(As[0][ko+tig+4][mb+8]);
                al[mi][0] = __float_as_uint(As[1][ko+tig  ][mb  ]);
                al[mi][1] = __float_as_uint(As[1][ko+tig  ][mb+8]);
                al[mi][2] = __float_as_uint(As[1][ko+tig+4][mb  ]);
                al[mi][3] = __float_as_uint(As[1][ko+tig+4][mb+8]);
            }
            #pragma unroll
            for (int ni = 0; ni < NT; ni++){
                int nb = n0 + ni*8 + gid;
                unsigned bh0 = __float_as_uint(Bs[0][ko+tig  ][nb]);
                unsigned bh1 = __float_as_uint(Bs[0][ko+tig+4][nb]);
                unsigned bl0 = __float_as_uint(Bs[1][ko+tig  ][nb]);
                unsigned bl1 = __float_as_uint(Bs[1][ko+tig+4][nb]);
                #pragma unroll
                for (int mi = 0; mi < MT; mi++){
                    MMA_TF32(acc[mi][ni], ah[mi][0],ah[mi][1],ah[mi][2],ah[mi][3], bh0,bh1);
                    MMA_TF32(acc[mi][ni], ah[mi][0],ah[mi][1],ah[mi][2],ah[mi][3], bl0,bl1);
                    MMA_TF32(acc[mi][ni], al[mi][0],al[mi][1],al[mi][2],al[mi][3], bh0,bh1);
                }
            }
        }
        __syncthreads();
    }

    #pragma unroll
    for (int mi = 0; mi < MT; mi++){
        #pragma unroll
        for (int ni = 0; ni < NT; ni++){
            int cc = n0 + ni*8 + tig*2;
            #pragma unroll
            for (int h = 0; h < 2; h++){
                int rr = row0 + m0 + mi*16 + gid + h*8;
                if (rr < n){
                    float v0 = acc[mi][ni][h*2+0];
                    float v1 = acc[mi][ni][h*2+1];
                    if (bias){ v0 += __ldg(&bias[cc]); v1 += __ldg(&bias[cc+1]); }
                    if (D){ v0 += D[(size_t)rr*BN + cc]; v1 += D[(size_t)rr*BN + cc + 1]; }
                    if (RELU){ v0 = fmaxf(v0, 0.f); v1 = fmaxf(v1, 0.f); }
                    *(float2*)(out + (size_t)rr*BN + cc) = make_float2(v0, v1);
                }
            }
        }
    }
}

// ---------------- bf16 GEMM: pre-packed weight planes [BN][KTOT/2 words] ----------------
template<int BN, int KTOT, int CINA, bool DUAL, bool RELU, bool GATHER>
__global__ void __launch_bounds__(256, 2) gemm_bf16_kernel(
    const float* __restrict__ A1, const float* __restrict__ A2,
    const unsigned* __restrict__ Wh, const unsigned* __restrict__ Wl,
    const float* __restrict__ bias, const float* __restrict__ D,
    float* __restrict__ out, int n,
    const int* __restrict__ perm, const float* __restrict__ score)
{
    constexpr int BM = 128, BK = 32, TPB = 256;
    constexpr int STR = 20;
    constexpr int AV = (BM*BK/4)/TPB;
    constexpr int BV = (BN*BK/4)/TPB;
    constexpr int TILESA = CINA/BK;
    constexpr int T = KTOT/BK;
    constexpr int KW = KTOT/2;
    constexpr int MT = 2;
    constexpr int NT = BN/16;

    __shared__ unsigned As[2][BM][STR];
    __shared__ unsigned Bs[2][BN][STR];

    int tid = threadIdx.x, lane = tid & 31, warp = tid >> 5;
    int m0 = (warp >> 1) * 32;
    int n0 = (warp & 1) * (BN/2);
    int row0 = blockIdx.x * BM;
    int gid = lane >> 2, tig = lane & 3;

    int am[AV], akq[AV], aar[AV]; float asc[AV];
    #pragma unroll
    for (int u = 0; u < AV; u++){
        int f = tid + u*TPB;
        am[u] = f >> 3; akq[u] = (f & 7) << 2;
        int r = row0 + am[u];
        aar[u] = -1; asc[u] = 1.f;
        if (r < n){
            int ar = r;
            if (GATHER){ ar = perm[r]; asc[u] = score[ar]; }
            aar[u] = ar;
        }
    }
    int bm[BV], bkq[BV];
    #pragma unroll
    for (int u = 0; u < BV; u++){
        int f = tid + u*TPB;
        bm[u] = f >> 3; bkq[u] = (f & 7) << 2;
    }

    float4 ra[AV];
    uint2 rbh[BV], rbl[BV];
    auto load_tile = [&](int t){
        int ph = DUAL ? (t / TILESA) : 0;
        int k0a = (t % TILESA) * BK;
        int k0w = t * (BK/2);
        const float* A = (DUAL && ph) ? A2 : A1;
        #pragma unroll
        for (int u = 0; u < AV; u++){
            float4 v = make_float4(0.f,0.f,0.f,0.f);
            if (aar[u] >= 0){
                v = *(const float4*)(A + (size_t)aar[u]*CINA + k0a + akq[u]);
                if (GATHER){ v.x*=asc[u]; v.y*=asc[u]; v.z*=asc[u]; v.w*=asc[u]; }
            }
            ra[u] = v;
        }
        #pragma unroll
        for (int u = 0; u < BV; u++){
            size_t off = (size_t)bm[u]*KW + k0w + (bkq[u] >> 1);
            rbh[u] = *(const uint2*)(Wh + off);
            rbl[u] = *(const uint2*)(Wl + off);
        }
    };
    auto store_split = [&](){
        #pragma unroll
        for (int u = 0; u < AV; u++){
            const float* s = (const float*)&ra[u];
            unsigned short h0,l0,h1,l1,h2,l2,h3,l3;
            bf16_split(s[0],h0,l0); bf16_split(s[1],h1,l1);
            bf16_split(s[2],h2,l2); bf16_split(s[3],h3,l3);
            int w = akq[u] >> 1;
            As[0][am[u]][w  ] = (unsigned)h0 | ((unsigned)h1 << 16);
            As[0][am[u]][w+1] = (unsigned)h2 | ((unsigned)h3 << 16);
            As[1][am[u]][w  ] = (unsigned)l0 | ((unsigned)l1 << 16);
            As[1][am[u]][w+1] = (unsigned)l2 | ((unsigned)l3 << 16);
        }
        #pragma unroll
        for (int u = 0; u < BV; u++){
            int w = bkq[u] >> 1;
            *(uint2*)&Bs[0][bm[u]][w] = rbh[u];
            *(uint2*)&Bs[1][bm[u]][w] = rbl[u];
        }
    };

    float acc[MT][NT][4];
    #pragma unroll
    for (int mi = 0; mi < MT; mi++)
        #pragma unroll
        for (int ni = 0; ni < NT; ni++)
            #pragma unroll
            for (int q = 0; q < 4; q++) acc[mi][ni][q] = 0.f;

    load_tile(0);
    for (int t = 0; t < T; t++){
        store_split();
        __syncthreads();
        if (t + 1 < T) load_tile(t + 1);
        #pragma unroll
        for (int kk = 0; kk < 2; kk++){
            int ko = kk * 8;
            unsigned ah[MT][4], al[MT][4];
            #pragma unroll
            for (int mi = 0; mi < MT; mi++){
                int mb = m0 + mi*16 + gid;
                ah[mi][0] = As[0][mb  ][ko+tig  ];
                ah[mi][1] = As[0][mb+8][ko+tig  ];
                ah[mi][2] = As[0][mb  ][ko+tig+4];
                ah[mi][3] = As[0][mb+8][ko+tig+4];
                al[mi][0] = As[1][mb  ][ko+tig  ];
                al[mi][1] = As[1][mb+8][ko+tig  ];
                al[mi][2] = As[1][mb  ][ko+tig+4];
                al[mi][3] = As[1][mb+8][ko+tig+4];
            }
            #pragma unroll
            for (int ni = 0; ni < NT; ni++){
                int nb = n0 + ni*8 + gid;
                unsigned bh0 = Bs[0][nb][ko+tig  ];
                unsigned bh1 = Bs[0][nb][ko+tig+4];
                unsigned bl0 = Bs[1][nb][ko+tig  ];
                unsigned bl1 = Bs[1][nb][ko+tig+4];
                #pragma unroll
                for (int mi = 0; mi < MT; mi++){
                    MMA_BF16(acc[mi][ni], ah[mi][0],ah[mi][1],ah[mi][2],ah[mi][3], bh0,bh1);
                    MMA_BF16(acc[mi][ni], ah[mi][0],ah[mi][1],ah[mi][2],ah[mi][3], bl0,bl1);
                    MMA_BF16(acc[mi][ni], al[mi][0],al[mi][1],al[mi][2],al[mi][3], bh0,bh1);
                }
            }
        }
        __syncthreads();
    }

    #pragma unroll
    for (int mi = 0; mi < MT; mi++){
        #pragma unroll
        for (int ni = 0; ni < NT; ni++){
            int cc = n0 + ni*8 + tig*2;
            #pragma unroll
            for (int h = 0; h < 2; h++){
                int rr = row0 + m0 + mi*16 + gid + h*8;
                if (rr < n){
                    float v0 = acc[mi][ni][h*2+0];
                    float v1 = acc[mi][ni][h*2+1];
                    if (bias){ v0 += __ldg(&bias[cc]); v1 += __ldg(&bias[cc+1]); }
                    if (D){ v0 += D[(size_t)rr*BN + cc]; v1 += D[(size_t)rr*BN + cc + 1]; }
                    if (RELU){ v0 = fmaxf(v0, 0.f); v1 = fmaxf(v1, 0.f); }
                    *(float2*)(out + (size_t)rr*BN + cc) = make_float2(v0, v1);
                }
            }
        }
    }
}

// ---------------- elementwise: x = relu(t[:,64:128] + agg + bias), t stride 128 ----------------
__global__ void merge_conv_kernel(const float* __restrict__ t, const float* __restrict__ agg,
                                  const float* __restrict__ bias, float* __restrict__ xout, int n)
{
    int idx = blockIdx.x*blockDim.x + threadIdx.x;
    int total = n * 16;
    if (idx >= total) return;
    int i = idx >> 4, c4 = (idx & 15) << 2;
    float4 r = *(const float4*)(t + (size_t)i*128 + 64 + c4);
    float4 a = *(const float4*)(agg + (size_t)i*64 + c4);
    float4 b = *(const float4*)(bias + c4);
    r.x = fmaxf(r.x + a.x + b.x, 0.f);
    r.y = fmaxf(r.y + a.y + b.y, 0.f);
    r.z = fmaxf(r.z + a.z + b.z, 0.f);
    r.w = fmaxf(r.w + a.w + b.w, 0.f);
    *(float4*)(xout + (size_t)i*64 + c4) = r;
}

// fused conv3-merge + unpool1: u1[i] = x2[i] + (map2[i]>=0 ? relu(t3[m,64:]+agg[m]+b3) : 0)
__global__ void merge_unpool_kernel(const float* __restrict__ t3, const float* __restrict__ agg,
                                    const float* __restrict__ bias, const float* __restrict__ x2,
                                    const int* __restrict__ map2, float* __restrict__ u1, int n)
{
    int idx = blockIdx.x*blockDim.x + threadIdx.x;
    int total = n * 16;
    if (idx >= total) return;
    int i = idx >> 4, c4 = (idx & 15) << 2;
    float4 v = *(const float4*)(x2 + (size_t)i*64 + c4);
    int m = map2[i];
    if (m >= 0){
        float4 r = *(const float4*)(t3 + (size_t)m*128 + 64 + c4);
        float4 a = *(const float4*)(agg + (size_t)m*64 + c4);
        float4 b = *(const float4*)(bias + c4);
        v.x += fmaxf(r.x + a.x + b.x, 0.f);
        v.y += fmaxf(r.y + a.y + b.y, 0.f);
        v.z += fmaxf(r.z + a.z + b.z, 0.f);
        v.w += fmaxf(r.w + a.w + b.w, 0.f);
    }
    *(float4*)(u1 + (size_t)i*64 + c4) = v;
}

// ---------------- topk pooling ----------------
template<int C>
__global__ void score_kernel(const float* __restrict__ x, const float* __restrict__ w, int n)
{
    int gw = blockIdx.x*(blockDim.x>>5) + (threadIdx.x>>5);
    int lane = threadIdx.x & 31;
    if (gw >= n) return;
    float p, q;
    if constexpr (C == 128){
        float4 xv = ((const float4*)(x + (size_t)gw*128))[lane];
        float4 wv = ((const float4*)w)[lane];
        p = xv.x*wv.x + xv.y*wv.y + xv.z*wv.z + xv.w*wv.w;
        q = wv.x*wv.x + wv.y*wv.y + wv.z*wv.z + wv.w*wv.w;
    } else {
        float2 xv = ((const float2*)(x + (size_t)gw*64))[lane];
        float2 wv = ((const float2*)w)[lane];
        p = xv.x*wv.x + xv.y*wv.y;
        q = wv.x*wv.x + wv.y*wv.y;
    }
    #pragma unroll
    for (int off = 16; off; off >>= 1){
        p += __shfl_xor_sync(0xffffffffu, p, off);
        q += __shfl_xor_sync(0xffffffffu, q, off);
    }
    if (lane == 0){
        float s = tanhf(p / sqrtf(q));
        g_score[gw] = s;
        unsigned u = __float_as_uint(s);
        u = (u & 0x80000000u) ? ~u : (u | 0x80000000u);
        g_key[gw] = u;
    }
}

// ONE-KERNEL radix select + compact; keys staged in dynamic shared memory.
__global__ void __launch_bounds__(1024) topk_select_kernel(
    int* __restrict__ mapping, int* __restrict__ perm, int n, int k)
{
    extern __shared__ unsigned skey[];
    __shared__ unsigned hist[256];
    __shared__ int ws[32];
    __shared__ int s_b, s_rem;

    for (int i = threadIdx.x; i < n; i += 1024) skey[i] = g_key[i];
    __syncthreads();

    unsigned prefix = 0;
    int remaining = k;
    for (int pass = 3; pass >= 0; pass--){
        for (int t = threadIdx.x; t < 256; t += 1024) hist[t] = 0;
        __syncthreads();
        int shf = (pass+1)*8;
        unsigned pref_hi = (pass == 3) ? 0u : (prefix >> shf);
        for (int base = 0; base < n; base += 1024){
            int i = base + threadIdx.x;
            if (i < n){
                unsigned key = skey[i];
                bool ok = (pass == 3) || ((key >> shf) == pref_hi);
                if (ok) atomicAdd(&hist[(key >> (pass*8)) & 255], 1u);
            }
        }
        __syncthreads();
        if (threadIdx.x == 0){
            unsigned r = (unsigned)remaining;
            unsigned c = 0; int b = 255;
            for (; b > 0; b--){
                unsigned h = hist[b];
                if (c + h >= r) break;
                c += h;
            }
            s_b = b; s_rem = (int)(r - c);
        }
        __syncthreads();
        prefix |= ((unsigned)s_b) << (pass*8);
        remaining = s_rem;
        __syncthreads();
    }

    unsigned thr = prefix;
    int local = 0;
    for (int base = 0; base < n; base += 1024){
        int i = base + threadIdx.x;
        if (i < n) local += (skey[i] > thr) ? 1 : 0;
    }
    int totG; block_scan_incl(local, totG, ws);
    int need_eq = k - totG;

    int run_eq = 0, run_sel = 0;
    for (int base = 0; base < n; base += 1024){
        int i = base + threadIdx.x;
        int gt = 0, eq = 0;
        if (i < n){
            unsigned kv = skey[i];
            gt = (kv > thr); eq = (kv == thr);
        }
        int tot_eq; int incl_eq = block_scan_incl(eq, tot_eq, ws);
        int excl_eq = incl_eq - eq;
        int sel = gt | (eq & ((run_eq + excl_eq) < need_eq ? 1 : 0));
        int tot_sel; int incl_sel = block_scan_incl(sel, tot_sel, ws);
        if (i < n){
            if (sel){
                int idx = run_sel + incl_sel - 1;
                mapping[i] = idx;
                perm[idx] = i;
            } else mapping[i] = -1;
        }
        run_eq += tot_eq; run_sel += tot_sel;
    }
}

// fused compose of level0->level2 mapping and perm
__global__ void compose_kernel()
{
    int i = blockIdx.x*blockDim.x + threadIdx.x;
    if (i < N0){ int m = g_map1[i]; g_map02[i] = (m >= 0) ? g_map2[m] : -1; }
    if (i < K2) g_perm02[i] = g_perm1[g_perm2[i]];
}

template<int C>
__global__ void unpool_kernel(const float* __restrict__ xb, const float* __restrict__ xs,
                              const int* __restrict__ mapping, float* __restrict__ out, int n)
{
    int idx = blockIdx.x*blockDim.x + threadIdx.x;
    int total = n * (C/4);
    if (idx >= total) return;
    int i = idx / (C/4), t = idx % (C/4);
    int m = mapping[i];
    float4 v = ((const float4*)(xb + (size_t)i*C))[t];
    if (m >= 0){
        float4 w = ((const float4*)(xs + (size_t)m*C))[t];
        v.x += w.x; v.y += w.y; v.z += w.z; v.w += w.w;
    }
    ((float4*)(out + (size_t)i*C))[t] = v;
}

// ---------------- final linear + log_softmax (warp per node) ----------------
__global__ void final_kernel(const float* __restrict__ x, const float* __restrict__ lw,
                             const float* __restrict__ lb, float* __restrict__ out, int n)
{
    int gw = blockIdx.x*(blockDim.x>>5) + (threadIdx.x>>5);
    int lane = threadIdx.x & 31;
    if (gw >= n) return;
    float4 xv = ((const float4*)(x + (size_t)gw*128))[lane];
    float lg[10]; float myv = 0.f;
    #pragma unroll
    for (int c = 0; c < 10; c++){
        float4 wv = ((const float4*)(lw + c*128))[lane];
        float p = xv.x*wv.x + xv.y*wv.y + xv.z*wv.z + xv.w*wv.w;
        #pragma unroll
        for (int off = 16; off; off >>= 1) p += __shfl_xor_sync(0xffffffffu, p, off);
        p += __ldg(&lb[c]);
        lg[c] = p;
        if (lane == c) myv = p;
    }
    float m = lg[0];
    #pragma unroll
    for (int c = 1; c < 10; c++) m = fmaxf(m, lg[c]);
    float s = 0.f;
    #pragma unroll
    for (int c = 0; c < 10; c++) s += expf(lg[c] - m);
    float lse = m + logf(s);
    if (lane < 10) out[(size_t)gw*10 + lane] = myv - lse;
}

// ---------------- host driver ----------------
extern "C" void kernel_launch(void* const* d_in, const int* in_sizes, int n_in,
                              void* d_out, int out_size)
{
    (void)in_sizes; (void)n_in; (void)out_size;
    const float* x    = (const float*)d_in[0];
    const int*   ei   = (const int*)d_in[1];
    const int*   src0 = ei;
    const int*   dst0 = ei + E0;
    const float *w1r=(const float*)d_in[2], *w1o=(const float*)d_in[3], *b1=(const float*)d_in[4], *p1w=(const float*)d_in[5];
    const float *w2r=(const float*)d_in[6], *w2o=(const float*)d_in[7], *b2=(const float*)d_in[8], *p2w=(const float*)d_in[9];
    const float *w3r=(const float*)d_in[10],*w3o=(const float*)d_in[11],*b3=(const float*)d_in[12];
    const float *w4r=(const float*)d_in[13],*w4o=(const float*)d_in[14],*b4=(const float*)d_in[15];
    const float *w5r=(const float*)d_in[16],*w5o=(const float*)d_in[17],*b5=(const float*)d_in[18];
    const float *lw =(const float*)d_in[19],*lb =(const float*)d_in[20];
    float* out = (float*)d_out;

    float *x1,*agg,*x2,*u1,*x4,*u2,*x5,*wHi,*wLo,*score;
    unsigned *wb3h,*wb3l,*wb4h,*wb4l,*wb5h,*wb5l;
    int *rowptr,*fill,*part,*partx,*map1,*perm1,*map2,*perm2,*map02,*perm02;
    cudaGetSymbolAddress((void**)&x1, g_x1);
    cudaGetSymbolAddress((void**)&agg, g_agg);
    cudaGetSymbolAddress((void**)&x2, g_x2);
    cudaGetSymbolAddress((void**)&u1, g_u1);
    cudaGetSymbolAddress((void**)&x4, g_x4);
    cudaGetSymbolAddress((void**)&u2, g_u2);
    cudaGetSymbolAddress((void**)&x5, g_x5);
    cudaGetSymbolAddress((void**)&wHi, g_wHi);
    cudaGetSymbolAddress((void**)&wLo, g_wLo);
    cudaGetSymbolAddress((void**)&wb3h, g_wb3h);
    cudaGetSymbolAddress((void**)&wb3l, g_wb3l);
    cudaGetSymbolAddress((void**)&wb4h, g_wb4h);
    cudaGetSymbolAddress((void**)&wb4l, g_wb4l);
    cudaGetSymbolAddress((void**)&wb5h, g_wb5h);
    cudaGetSymbolAddress((void**)&wb5l, g_wb5l);
    cudaGetSymbolAddress((void**)&score, g_score);
    cudaGetSymbolAddress((void**)&rowptr, g_rowptr);
    cudaGetSymbolAddress((void**)&fill, g_fill);
    cudaGetSymbolAddress((void**)&part, g_part);
    cudaGetSymbolAddress((void**)&partx, g_partx);
    cudaGetSymbolAddress((void**)&map1, g_map1);
    cudaGetSymbolAddress((void**)&perm1, g_perm1);
    cudaGetSymbolAddress((void**)&map2, g_map2);
    cudaGetSymbolAddress((void**)&perm2, g_perm2);
    cudaGetSymbolAddress((void**)&map02, g_map02);
    cudaGetSymbolAddress((void**)&perm02, g_perm02);

    const int W = 16384;
    float* t2 = x4;   // conv2 cat output [K1][128]
    float* t3 = u2;   // conv3 cat output [K2][128]

    cudaFuncSetAttribute(topk_select_kernel,
                         cudaFuncAttributeMaxDynamicSharedMemorySize, N0*sizeof(unsigned) + 1024);

    cudaStream_t s2;
    cudaEvent_t ev1, ev2;
    cudaStreamCreateWithFlags(&s2, cudaStreamNonBlocking);
    cudaEventCreateWithFlags(&ev1, cudaEventDisableTiming);
    cudaEventCreateWithFlags(&ev2, cudaEventDisableTiming);

    // ---- prologue fork (CSR has serialization bubbles; weight prep + GEMM fill them) ----
    cudaEventRecord(ev1, 0);
    cudaStreamWaitEvent(s2, ev1, 0);
    {
        dim3 g1(64, 4);
        prep_tf32_kernel<<<g1,256>>>(w1r, w1o, w2r, w2o);
        dim3 g2(64, 3);
        prep_bf16_kernel<<<g2,256>>>(w3r, w3o, w4r, w4o, w5r, w5o);
    }
    zero_int_kernel<<<(N0+255)/256,256,0,s2>>>(fill, N0);
    edge_count_kernel<<<(E0+255)/256,256,0,s2>>>(dst0);
    gemm_tf32_kernel<128,128,false,false><<<(N0+127)/128,256>>>(
        x, wHi+1*W, wLo+1*W, nullptr, nullptr, x1, N0, nullptr, nullptr);
    deg_reduce_kernel<<<NB_SCAN,1024,0,s2>>>(fill, part, N0);
    scan_kernel<<<1,1024,0,s2>>>(part, partx, NB_SCAN);
    deg_apply_kernel<<<NB_SCAN,1024,0,s2>>>(fill, partx, rowptr, N0);
    edge_scatter_kernel<<<(E0+255)/256,256,0,s2>>>(src0, dst0);
    agg_kernel<128><<<(N0+7)/8,256,0,s2>>>(x, agg, nullptr, nullptr, N0, 128);
    cudaEventRecord(ev2, s2);
    cudaStreamWaitEvent(0, ev2, 0);

    // conv1 rel-half (D add, bias, relu)
    gemm_tf32_kernel<128,128,true,false><<<(N0+127)/128,256>>>(
        agg, wHi+0*W, wLo+0*W, b1, x1, x1, N0, nullptr, nullptr);

    // pool1
    score_kernel<128><<<(N0+7)/8,256>>>(x1, p1w, N0);
    topk_select_kernel<<<1,1024,N0*sizeof(unsigned)>>>(map1, perm1, N0, K1);

    // conv2 (tf32 N-cat): t2 = gather(x1)·[W2r^T|W2o^T]; agg left half; merge
    gemm_tf32_kernel<128,128,false,true><<<(K1+127)/128,256>>>(
        x1, wHi+2*W, wLo+2*W, nullptr, nullptr, t2, K1, perm1, score);
    agg_kernel<64><<<(K1+7)/8,256>>>(t2, agg, perm1, map1, K1, 128);
    merge_conv_kernel<<<(K1*16+255)/256,256>>>(t2, agg, b2, x2, K1);

    // pool2
    score_kernel<64><<<(K1+7)/8,256>>>(x2, p2w, K1);
    topk_select_kernel<<<1,1024,K1*sizeof(unsigned)>>>(map2, perm2, K1, K2);
    compose_kernel<<<(N0+255)/256,256>>>();

    // conv3 (bf16 N-cat): t3 = gather(x2)·[W3r|W3o]; agg left half; fused merge+unpool1
    gemm_bf16_kernel<128,64,64,false,false,true><<<(K2+127)/128,256>>>(
        x2, nullptr, wb3h, wb3l, nullptr, nullptr, t3, K2, perm2, score);
    agg_kernel<64><<<(K2+7)/8,256>>>(t3, agg, perm02, map02, K2, 128);
    merge_unpool_kernel<<<(K1*16+255)/256,256>>>(t3, agg, b3, x2, map2, u1, K1);

    // conv4 (bf16 K-cat): relu(agg·W4r + u1·W4o + b4)
    agg_kernel<64><<<(K1+7)/8,256>>>(u1, agg, perm1, map1, K1, 64);
    gemm_bf16_kernel<128,128,64,true,true,false><<<(K1+127)/128,256>>>(
        agg, u1, wb4h, wb4l, b4, nullptr, x4, K1, nullptr, nullptr);

    // unpool2 + skip
    unpool_kernel<128><<<(N0*32+255)/256,256>>>(x1, x4, map1, u2, N0);

    // conv5 (bf16 K-cat)
    agg_kernel<128><<<(N0+7)/8,256>>>(u2, agg, nullptr, nullptr, N0, 128);
    gemm_bf16_kernel<128,256,128,true,true,false><<<(N0+127)/128,256>>>(
        agg, u2, wb5h, wb5l, b5, nullptr, x5, N0, nullptr, nullptr);

    // final linear + log_softmax
    final_kernel<<<(N0+7)/8,256>>>(x5, lw, lb, out, N0);
}

// round 15
// speedup vs baseline: 1.1459x; 1.0033x over previous
#include <cuda_runtime.h>
#include <cuda_bf16.h>
#include <math.h>

#define N0 50000
#define E0 1600000
#define K1 40000
#define K2 32000
#define NB_SCAN 49   // ceil(N0/1024)

// ---------------- scratch (device globals; no runtime allocation) ----------------
__device__ float g_x1[N0*128];
__device__ float g_agg[N0*128];
__device__ float g_x2[K1*64];
__device__ float g_x4[K1*128];     // also conv2 cat-GEMM output t2
__device__ float g_u2[N0*128];     // conv3 cat-GEMM output t3
__device__ float g_x5[N0*128];
__device__ unsigned g_u1b[K1*32];  // u1 as bf16x2 words [K1][32]
__device__ unsigned g_u2b[N0*64];  // u2 as bf16x2 words [N0][64]
__device__ int   g_rowptr[N0+1];
__device__ int   g_fill[N0];
__device__ int   g_part[64];
__device__ int   g_partx[66];
__device__ int   g_esrc[E0];
__device__ float g_score[N0];
__device__ unsigned g_key[N0];
__device__ int   g_map1[N0];
__device__ int   g_perm1[K1];
__device__ int   g_map2[K1];
__device__ int   g_perm2[K2];
__device__ int   g_map02[N0];
__device__ int   g_perm02[K2];
// tf32 pre-split transposed weight planes: 0=W1r^T, 1=W1o^T, 2=[W2r^T|W2o^T]
__device__ float g_wHi[3*16384];
__device__ float g_wLo[3*16384];
// bf16 pre-packed hi/lo word planes
__device__ unsigned g_wb3h[128*32],  g_wb3l[128*32];
__device__ unsigned g_wb4h[128*64],  g_wb4l[128*64];
__device__ unsigned g_wb5h[128*128], g_wb5l[128*128];

// ---------------- CSR build ----------------
__global__ void zero_int_kernel(int* p, int n)
{
    int i = blockIdx.x*blockDim.x + threadIdx.x;
    if (i < n) p[i] = 0;
}

__global__ void edge_count_kernel(const int* __restrict__ dst)
{
    int e = blockIdx.x*blockDim.x + threadIdx.x;
    if (e < E0) atomicAdd(&g_fill[dst[e]], 1);
}

__device__ __forceinline__ int block_scan_incl(int val, int& total, int* ws)
{
    int lane = threadIdx.x & 31, wid = threadIdx.x >> 5;
    int x = val;
    #pragma unroll
    for (int off = 1; off < 32; off <<= 1){
        int y = __shfl_up_sync(0xffffffffu, x, off);
        if (lane >= off) x += y;
    }
    if (lane == 31) ws[wid] = x;
    __syncthreads();
    if (wid == 0){
        int s = ws[lane];
        #pragma unroll
        for (int off = 1; off < 32; off <<= 1){
            int y = __shfl_up_sync(0xffffffffu, s, off);
            if (lane >= off) s += y;
        }
        ws[lane] = s;
    }
    __syncthreads();
    int res = x + (wid ? ws[wid-1] : 0);
    total = ws[31];
    __syncthreads();
    return res;
}

__global__ void scan_kernel(const int* __restrict__ in, int* __restrict__ out, int n)
{
    __shared__ int ws[32];
    int run = 0;
    for (int base = 0; base < n; base += 1024){
        int i = base + threadIdx.x;
        int v = (i < n) ? in[i] : 0;
        int tot; int incl = block_scan_incl(v, tot, ws);
        if (i < n) out[i] = run + incl - v;
        run += tot;
    }
    if (threadIdx.x == 0) out[n] = run;
}

__global__ void deg_reduce_kernel(const int* __restrict__ in, int* __restrict__ part, int n)
{
    __shared__ int ws[32];
    int i = blockIdx.x*1024 + threadIdx.x;
    int v = (i < n) ? in[i] : 0;
    int lane = threadIdx.x & 31, wid = threadIdx.x >> 5;
    #pragma unroll
    for (int off = 16; off; off >>= 1) v += __shfl_down_sync(0xffffffffu, v, off);
    if (lane == 0) ws[wid] = v;
    __syncthreads();
    if (wid == 0){
        v = ws[lane];
        #pragma unroll
        for (int off = 16; off; off >>= 1) v += __shfl_down_sync(0xffffffffu, v, off);
        if (lane == 0) part[blockIdx.x] = v;
    }
}

__global__ void deg_apply_kernel(const int* __restrict__ in, const int* __restrict__ partx,
                                 int* __restrict__ rowptr, int n)
{
    __shared__ int ws[32];
    int i = blockIdx.x*1024 + threadIdx.x;
    int v = (i < n) ? in[i] : 0;
    int tot; int incl = block_scan_incl(v, tot, ws);
    if (i < n) rowptr[i] = partx[blockIdx.x] + incl - v;
    if (i == n) rowptr[n] = partx[gridDim.x];
}

__global__ void edge_scatter_kernel(const int* __restrict__ src, const int* __restrict__ dst)
{
    int e = blockIdx.x*blockDim.x + threadIdx.x;
    if (e < E0){
        int d = dst[e];
        int off = atomicSub(&g_fill[d], 1) - 1;
        g_esrc[g_rowptr[d] + off] = src[e];
    }
}

// ---------------- split helpers ----------------
__device__ __forceinline__ void tf32_split(float a, float& hi, float& lo)
{
    unsigned h;
    asm("cvt.rna.tf32.f32 %0, %1;" : "=r"(h) : "f"(a));
    float hf = __uint_as_float(h);
    float l = a - hf;
    unsigned lu;
    asm("cvt.rna.tf32.f32 %0, %1;" : "=r"(lu) : "f"(l));
    hi = hf; lo = __uint_as_float(lu);
}

__device__ __forceinline__ unsigned short f2bf(float x)
{
    __nv_bfloat16 b = __float2bfloat16(x);
    return *reinterpret_cast<unsigned short*>(&b);
}
__device__ __forceinline__ void bf16_split(float x, unsigned short& hi, unsigned short& lo)
{
    __nv_bfloat16 h = __float2bfloat16(x);
    float hf = __bfloat162float(h);
    hi = *reinterpret_cast<unsigned short*>(&h);
    lo = f2bf(x - hf);
}
__device__ __forceinline__ unsigned pack2bf(float a, float b)
{
    return (unsigned)f2bf(a) | ((unsigned)f2bf(b) << 16);
}
__device__ __forceinline__ float2 unpack2bf(unsigned u)
{
    __nv_bfloat162 b = *reinterpret_cast<__nv_bfloat162*>(&u);
    return __bfloat1622float2(b);
}

// ---------------- weight preprocessing ----------------
__global__ void prep_tf32_kernel(const float* w0, const float* w1, const float* w2, const float* w3)
{
    const float* ws[4] = {w0,w1,w2,w3};
    const int CO[4] = {128,128,64,64};
    int m = blockIdx.y;
    int idx = blockIdx.x*blockDim.x + threadIdx.x;
    int nEl = CO[m]*128;
    if (idx < nEl){
        int r = idx >> 7, c = idx & 127;
        float hi, lo; tf32_split(ws[m][idx], hi, lo);
        int off = (m < 2) ? (m*16384 + c*128 + r)
                          : (2*16384 + c*128 + (m == 3 ? 64 : 0) + r);
        g_wHi[off] = hi; g_wLo[off] = lo;
    }
}

__global__ void prep_bf16_kernel(const float* w3r, const float* w3o,
                                 const float* w4r, const float* w4o,
                                 const float* w5r, const float* w5o)
{
    int m = blockIdx.y;
    int idx = blockIdx.x*blockDim.x + threadIdx.x;
    if (m == 0){
        if (idx < 128*32){
            int r = idx >> 5, w = idx & 31;
            const float* src = (r < 64) ? (w3r + r*64) : (w3o + (r-64)*64);
            unsigned short h0,l0,h1,l1;
            bf16_split(src[w*2],   h0, l0);
            bf16_split(src[w*2+1], h1, l1);
            g_wb3h[idx] = (unsigned)h0 | ((unsigned)h1 << 16);
            g_wb3l[idx] = (unsigned)l0 | ((unsigned)l1 << 16);
        }
    } else if (m == 1){
        if (idx < 128*64){
            int r = idx >> 6, w = idx & 63;
            int k = w*2;
            const float* src = (k < 64) ? (w4r + r*64 + k) : (w4o + r*64 + k - 64);
            unsigned short h0,l0,h1,l1;
            bf16_split(src[0], h0, l0);
            bf16_split(src[1], h1, l1);
            g_wb4h[idx] = (unsigned)h0 | ((unsigned)h1 << 16);
            g_wb4l[idx] = (unsigned)l0 | ((unsigned)l1 << 16);
        }
    } else {
        if (idx < 128*128){
            int r = idx >> 7, w = idx & 127;
            int k = w*2;
            const float* src = (k < 128) ? (w5r + r*128 + k) : (w5o + r*128 + k - 128);
            unsigned short h0,l0,h1,l1;
            bf16_split(src[0], h0, l0);
            bf16_split(src[1], h1, l1);
            g_wb5h[idx] = (unsigned)h0 | ((unsigned)h1 << 16);
            g_wb5l[idx] = (unsigned)l0 | ((unsigned)l1 << 16);
        }
    }
}

// ---------------- aggregation: warp per node, x4-unrolled gather (fp32 input) ----------------
template<int C>
__global__ void agg_kernel(const float* __restrict__ xin, float* __restrict__ out,
                           const int* __restrict__ perm, const int* __restrict__ mapping,
                           int n, int instride)
{
    int warp = (blockIdx.x*blockDim.x + threadIdx.x) >> 5;
    int lane = threadIdx.x & 31;
    if (warp >= n) return;
    int old = perm ? perm[warp] : warp;
    int beg = g_rowptr[old], end = g_rowptr[old+1];
    if constexpr (C == 128){
        float4 acc = make_float4(0.f,0.f,0.f,0.f);
        for (int b = beg; b < end; b += 32){
            int e = b + lane;
            int s = -1;
            if (e < end){ s = g_esrc[e]; if (mapping) s = mapping[s]; }
            int cnt = min(32, end - b);
            int j = 0;
            for (; j + 4 <= cnt; j += 4){
                int s0 = __shfl_sync(0xffffffffu, s, j);
                int s1 = __shfl_sync(0xffffffffu, s, j+1);
                int s2 = __shfl_sync(0xffffffffu, s, j+2);
                int s3 = __shfl_sync(0xffffffffu, s, j+3);
                float4 v0 = make_float4(0,0,0,0), v1 = v0, v2 = v0, v3 = v0;
                if (s0 >= 0) v0 = ((const float4*)(xin + (size_t)s0*instride))[lane];
                if (s1 >= 0) v1 = ((const float4*)(xin + (size_t)s1*instride))[lane];
                if (s2 >= 0) v2 = ((const float4*)(xin + (size_t)s2*instride))[lane];
                if (s3 >= 0) v3 = ((const float4*)(xin + (size_t)s3*instride))[lane];
                acc.x += (v0.x + v1.x) + (v2.x + v3.x);
                acc.y += (v0.y + v1.y) + (v2.y + v3.y);
                acc.z += (v0.z + v1.z) + (v2.z + v3.z);
                acc.w += (v0.w + v1.w) + (v2.w + v3.w);
            }
            for (; j < cnt; j++){
                int sj = __shfl_sync(0xffffffffu, s, j);
                if (sj >= 0){
                    float4 v = ((const float4*)(xin + (size_t)sj*instride))[lane];
                    acc.x += v.x; acc.y += v.y; acc.z += v.z; acc.w += v.w;
                }
            }
        }
        ((float4*)(out + (size_t)warp*128))[lane] = acc;
    } else {
        float2 acc = make_float2(0.f,0.f);
        for (int b = beg; b < end; b += 32){
            int e = b + lane;
            int s = -1;
            if (e < end){ s = g_esrc[e]; if (mapping) s = mapping[s]; }
            int cnt = min(32, end - b);
            int j = 0;
            for (; j + 4 <= cnt; j += 4){
                int s0 = __shfl_sync(0xffffffffu, s, j);
                int s1 = __shfl_sync(0xffffffffu, s, j+1);
                int s2 = __shfl_sync(0xffffffffu, s, j+2);
                int s3 = __shfl_sync(0xffffffffu, s, j+3);
                float2 v0 = make_float2(0,0), v1 = v0, v2 = v0, v3 = v0;
                if (s0 >= 0) v0 = ((const float2*)(xin + (size_t)s0*instride))[lane];
                if (s1 >= 0) v1 = ((const float2*)(xin + (size_t)s1*instride))[lane];
                if (s2 >= 0) v2 = ((const float2*)(xin + (size_t)s2*instride))[lane];
                if (s3 >= 0) v3 = ((const float2*)(xin + (size_t)s3*instride))[lane];
                acc.x += (v0.x + v1.x) + (v2.x + v3.x);
                acc.y += (v0.y + v1.y) + (v2.y + v3.y);
            }
            for (; j < cnt; j++){
                int sj = __shfl_sync(0xffffffffu, s, j);
                if (sj >= 0){
                    float2 v = ((const float2*)(xin + (size_t)sj*instride))[lane];
                    acc.x += v.x; acc.y += v.y;
                }
            }
        }
        ((float2*)(out + (size_t)warp*64))[lane] = acc;
    }
}

// ---------------- aggregation over bf16x2-packed node table ----------------
// C=128: row stride 64 words, lane reads uint2 (4 vals). C=64: stride 32 words, lane reads 1 word.
template<int C>
__global__ void agg_bf16_kernel(const unsigned* __restrict__ xin, float* __restrict__ out,
                                const int* __restrict__ perm, const int* __restrict__ mapping, int n)
{
    int warp = (blockIdx.x*blockDim.x + threadIdx.x) >> 5;
    int lane = threadIdx.x & 31;
    if (warp >= n) return;
    int old = perm ? perm[warp] : warp;
    int beg = g_rowptr[old], end = g_rowptr[old+1];
    if constexpr (C == 128){
        float4 acc = make_float4(0.f,0.f,0.f,0.f);
        for (int b = beg; b < end; b += 32){
            int e = b + lane;
            int s = -1;
            if (e < end){ s = g_esrc[e]; if (mapping) s = mapping[s]; }
            int cnt = min(32, end - b);
            int j = 0;
            for (; j + 4 <= cnt; j += 4){
                int s0 = __shfl_sync(0xffffffffu, s, j);
                int s1 = __shfl_sync(0xffffffffu, s, j+1);
                int s2 = __shfl_sync(0xffffffffu, s, j+2);
                int s3 = __shfl_sync(0xffffffffu, s, j+3);
                uint2 w0 = make_uint2(0,0), w1 = w0, w2 = w0, w3 = w0;
                if (s0 >= 0) w0 = *(const uint2*)(xin + (size_t)s0*64 + lane*2);
                if (s1 >= 0) w1 = *(const uint2*)(xin + (size_t)s1*64 + lane*2);
                if (s2 >= 0) w2 = *(const uint2*)(xin + (size_t)s2*64 + lane*2);
                if (s3 >= 0) w3 = *(const uint2*)(xin + (size_t)s3*64 + lane*2);
                float2 a0 = unpack2bf(w0.x), b0 = unpack2bf(w0.y);
                float2 a1 = unpack2bf(w1.x), b1 = unpack2bf(w1.y);
                float2 a2 = unpack2bf(w2.x), b2 = unpack2bf(w2.y);
                float2 a3 = unpack2bf(w3.x), b3 = unpack2bf(w3.y);
                acc.x += (a0.x + a1.x) + (a2.x + a3.x);
                acc.y += (a0.y + a1.y) + (a2.y + a3.y);
                acc.z += (b0.x + b1.x) + (b2.x + b3.x);
                acc.w += (b0.y + b1.y) + (b2.y + b3.y);
            }
            for (; j < cnt; j++){
                int sj = __shfl_sync(0xffffffffu, s, j);
                if (sj >= 0){
                    uint2 w = *(const uint2*)(xin + (size_t)sj*64 + lane*2);
                    float2 a = unpack2bf(w.x), b = unpack2bf(w.y);
                    acc.x += a.x; acc.y += a.y; acc.z += b.x; acc.w += b.y;
                }
            }
        }
        ((float4*)(out + (size_t)warp*128))[lane] = acc;
    } else {
        float2 acc = make_float2(0.f,0.f);
        for (int b = beg; b < end; b += 32){
            int e = b + lane;
            int s = -1;
            if (e < end){ s = g_esrc[e]; if (mapping) s = mapping[s]; }
            int cnt = min(32, end - b);
            int j = 0;
            for (; j + 4 <= cnt; j += 4){
                int s0 = __shfl_sync(0xffffffffu, s, j);
                int s1 = __shfl_sync(0xffffffffu, s, j+1);
                int s2 = __shfl_sync(0xffffffffu, s, j+2);
                int s3 = __shfl_sync(0xffffffffu, s, j+3);
                unsigned w0 = 0, w1 = 0, w2 = 0, w3 = 0;
                if (s0 >= 0) w0 = xin[(size_t)s0*32 + lane];
                if (s1 >= 0) w1 = xin[(size_t)s1*32 + lane];
                if (s2 >= 0) w2 = xin[(size_t)s2*32 + lane];
                if (s3 >= 0) w3 = xin[(size_t)s3*32 + lane];
                float2 a0 = unpack2bf(w0), a1 = unpack2bf(w1);
                float2 a2 = unpack2bf(w2), a3 = unpack2bf(w3);
                acc.x += (a0.x + a1.x) + (a2.x + a3.x);
                acc.y += (a0.y + a1.y) + (a2.y + a3.y);
            }
            for (; j < cnt; j++){
                int sj = __shfl_sync(0xffffffffu, s, j);
                if (sj >= 0){
                    float2 a = unpack2bf(xin[(size_t)sj*32 + lane]);
                    acc.x += a.x; acc.y += a.y;
                }
            }
        }
        ((float2*)(out + (size_t)warp*64))[lane] = acc;
    }
}

#define MMA_TF32(d, a0,a1,a2,a3, b0,b1) \
    asm volatile("mma.sync.aligned.m16n8k8.row.col.f32.tf32.tf32.f32 " \
        "{%0,%1,%2,%3}, {%4,%5,%6,%7}, {%8,%9}, {%0,%1,%2,%3};" \
        : "+f"((d)[0]), "+f"((d)[1]), "+f"((d)[2]), "+f"((d)[3]) \
        : "r"(a0), "r"(a1), "r"(a2), "r"(a3), "r"(b0), "r"(b1))

#define MMA_BF16(d, a0,a1,a2,a3, b0,b1) \
    asm volatile("mma.sync.aligned.m16n8k16.row.col.f32.bf16.bf16.f32 " \
        "{%0,%1,%2,%3}, {%4,%5,%6,%7}, {%8,%9}, {%0,%1,%2,%3};" \
        : "+f"((d)[0]), "+f"((d)[1]), "+f"((d)[2]), "+f"((d)[3]) \
        : "r"(a0), "r"(a1), "r"(a2), "r"(a3), "r"(b0), "r"(b1))

// ---------------- tf32 GEMM: pre-split weight planes ----------------
template<int BN, int CIN, bool RELU, bool GATHER>
__global__ void __launch_bounds__(256, 2) gemm_tf32_kernel(
    const float* __restrict__ A1,
    const float* __restrict__ Whi, const float* __restrict__ Wlo,
    const float* __restrict__ bias, const float* __restrict__ D,
    float* __restrict__ out, int n,
    const int* __restrict__ perm, const float* __restrict__ score)
{
    constexpr int BM = 128, BK = 16, TPB = 256;
    constexpr int BMp = 136, BNp = BN + 8;
    constexpr int AV = (BM*BK/4)/TPB;
    constexpr int BV = (BK*BN/4)/TPB;
    constexpr int T = CIN/BK;
    constexpr int MT = 2;
    constexpr int NT = BN/16;

    __shared__ float As[2][BK][BMp];
    __shared__ float Bs[2][BK][BNp];

    int tid = threadIdx.x, lane = tid & 31, warp = tid >> 5;
    int m0 = (warp >> 1) * 32;
    int n0 = (warp & 1) * (BN/2);
    int row0 = blockIdx.x * BM;
    int gid = lane >> 2, tig = lane & 3;

    int am[AV], akq[AV], aar[AV]; float asc[AV];
    #pragma unroll
    for (int u = 0; u < AV; u++){
        int f = tid + u*TPB;
        am[u] = f >> 2; akq[u] = (f & 3) << 2;
        int r = row0 + am[u];
        aar[u] = -1; asc[u] = 1.f;
        if (r < n){
            int ar = r;
            if (GATHER){ ar = perm[r]; asc[u] = score[ar]; }
            aar[u] = ar;
        }
    }
    int bkk[BV], bc4[BV];
    #pragma unroll
    for (int u = 0; u < BV; u++){
        int f = tid + u*TPB;
        bkk[u] = f / (BN/4); bc4[u] = (f % (BN/4)) << 2;
    }

    float4 ra[AV], rbh[BV], rbl[BV];
    auto load_tile = [&](int t){
        int k0 = t * BK;
        #pragma unroll
        for (int u = 0; u < AV; u++){
            float4 v = make_float4(0.f,0.f,0.f,0.f);
            if (aar[u] >= 0){
                v = *(const float4*)(A1 + (size_t)aar[u]*CIN + k0 + akq[u]);
                if (GATHER){ v.x*=asc[u]; v.y*=asc[u]; v.z*=asc[u]; v.w*=asc[u]; }
            }
            ra[u] = v;
        }
        #pragma unroll
        for (int u = 0; u < BV; u++){
            size_t off = (size_t)(k0 + bkk[u])*BN + bc4[u];
            rbh[u] = *(const float4*)(Whi + off);
            rbl[u] = *(const float4*)(Wlo + off);
        }
    };
    auto store_split = [&](){
        #pragma unroll
        for (int u = 0; u < AV; u++){
            const float* s = (const float*)&ra[u];
            #pragma unroll
            for (int q = 0; q < 4; q++){
                float hi, lo; tf32_split(s[q], hi, lo);
                As[0][akq[u]+q][am[u]] = hi;
                As[1][akq[u]+q][am[u]] = lo;
            }
        }
        #pragma unroll
        for (int u = 0; u < BV; u++){
            *(float4*)&Bs[0][bkk[u]][bc4[u]] = rbh[u];
            *(float4*)&Bs[1][bkk[u]][bc4[u]] = rbl[u];
        }
    };

    float acc[MT][NT][4];
    #pragma unroll
    for (int mi = 0; mi < MT; mi++)
        #pragma unroll
        for (int ni = 0; ni < NT; ni++)
            #pragma unroll
            for (int q = 0; q < 4; q++) acc[mi][ni][q] = 0.f;

    load_tile(0);
    for (int t = 0; t < T; t++){
        store_split();
        __syncthreads();
        if (t + 1 < T) load_tile(t + 1);
        #pragma unroll
        for (int kk = 0; kk < 2; kk++){
            int ko = kk * 8;
            unsigned ah[MT][4], al[MT][4];
            #pragma unroll
            for (int mi = 0; mi < MT; mi++){
                int mb = m0 + mi*16 + gid;
                ah[mi][0] = __float_as_uint(As[0][ko+tig  ][mb  ]);
                ah[mi][1] = __float_as_uint(As[0][ko+tig  ][mb+8]);
                ah[mi][2] = __float_as_uint(As[0][ko+tig+4][mb  ]);
                ah[mi][3] = __float_as_uint(As[0][ko+tig+4][mb+8]);
                al[mi][0] = __float_as_uint(As[1][ko+tig  ][mb  ]);
                al[mi][1] = __float_as_uint(As[1][ko+tig  ][mb+8]);
                al[mi][2] = __float_as_uint(As[1][ko+tig+4][mb  ]);
                al[mi][3] = __float_as_uint(As[1][ko+tig+4][mb+8]);
            }
            #pragma unroll
            for (int ni = 0; ni < NT; ni++){
                int nb = n0 + ni*8 + gid;
                unsigned bh0 = __float_as_uint(Bs[0][ko+tig  ][nb]);
                unsigned bh1 = __float_as_uint(Bs[0][ko+tig+4][nb]);
                unsigned bl0 = __float_as_uint(Bs[1][ko+tig  ][nb]);
                unsigned bl1 = __float_as_uint(Bs[1][ko+tig+4][nb]);
                #pragma unroll
                for (int mi = 0; mi < MT; mi++){
                    MMA_TF32(acc[mi][ni], ah[mi][0],ah[mi][1],ah[mi][2],ah[mi][3], bh0,bh1);
                    MMA_TF32(acc[mi][ni], ah[mi][0],ah[mi][1],ah[mi][2],ah[mi][3], bl0,bl1);
                    MMA_TF32(acc[mi][ni], al[mi][0],al[mi][1],al[mi][2],al[mi][3], bh0,bh1);
                }
            }
        }
        __syncthreads();
    }

    #pragma unroll
    for (int mi = 0; mi < MT; mi++){
        #pragma unroll
        for (int ni = 0; ni < NT; ni++){
            int cc = n0 + ni*8 + tig*2;
            #pragma unroll
            for (int h = 0; h < 2; h++){
                int rr = row0 + m0 + mi*16 + gid + h*8;
                if (rr < n){
                    float v0 = acc[mi][ni][h*2+0];
                    float v1 = acc[mi][ni][h*2+1];
                    if (bias){ v0 += __ldg(&bias[cc]); v1 += __ldg(&bias[cc+1]); }
                    if (D){ v0 += D[(size_t)rr*BN + cc]; v1 += D[(size_t)rr*BN + cc + 1]; }
                    if (RELU){ v0 = fmaxf(v0, 0.f); v1 = fmaxf(v1, 0.f); }
                    *(float2*)(out + (size_t)rr*BN + cc) = make_float2(v0, v1);
                }
            }
        }
    }
}

// ---------------- bf16 GEMM: pre-packed weight planes; DUAL A2 is bf16x2-packed ----------------
// A1: fp32 [n][CINA] (tiles 0..TILESA-1). A2 (when DUAL): bf16x2 words [n][CINA/2]
// (tiles TILESA..T-1, A-lo plane is zero -> third MMA skipped for those tiles).
template<int BN, int KTOT, int CINA, bool DUAL, bool RELU, bool GATHER>
__global__ void __launch_bounds__(256, 2) gemm_bf16_kernel(
    const float* __restrict__ A1, const unsigned* __restrict__ A2b,
    const unsigned* __restrict__ Wh, const unsigned* __restrict__ Wl,
    const float* __restrict__ bias, const float* __restrict__ D,
    float* __restrict__ out, int n,
    const int* __restrict__ perm, const float* __restrict__ score)
{
    constexpr int BM = 128, BK = 32, TPB = 256;
    constexpr int STR = 20;
    constexpr int AV = (BM*BK/4)/TPB;
    constexpr int BV = (BN*BK/4)/TPB;
    constexpr int TILESA = CINA/BK;
    constexpr int T = KTOT/BK;
    constexpr int KW = KTOT/2;
    constexpr int KWA = CINA/2;
    constexpr int MT = 2;
    constexpr int NT = BN/16;

    __shared__ unsigned As[2][BM][STR];
    __shared__ unsigned Bs[2][BN][STR];

    int tid = threadIdx.x, lane = tid & 31, warp = tid >> 5;
    int m0 = (warp >> 1) * 32;
    int n0 = (warp & 1) * (BN/2);
    int row0 = blockIdx.x * BM;
    int gid = lane >> 2, tig = lane & 3;

    int am[AV], akq[AV], aar[AV]; float asc[AV];
    #pragma unroll
    for (int u = 0; u < AV; u++){
        int f = tid + u*TPB;
        am[u] = f >> 3; akq[u] = (f & 7) << 2;
        int r = row0 + am[u];
        aar[u] = -1; asc[u] = 1.f;
        if (r < n){
            int ar = r;
            if (GATHER){ ar = perm[r]; asc[u] = score[ar]; }
            aar[u] = ar;
        }
    }
    int bm[BV], bkq[BV];
    #pragma unroll
    for (int u = 0; u < BV; u++){
        int f = tid + u*TPB;
        bm[u] = f >> 3; bkq[u] = (f & 7) << 2;
    }

    float4 ra[AV];
    uint2 ra2[AV];
    uint2 rbh[BV], rbl[BV];
    int cur_ph = 0;
    auto load_tile = [&](int t){
        int ph = DUAL ? (t / TILESA) : 0;
        cur_ph = ph;
        int k0a = (t % TILESA) * BK;
        int k0w = t * (BK/2);
        if (ph == 0){
            #pragma unroll
            for (int u = 0; u < AV; u++){
                float4 v = make_float4(0.f,0.f,0.f,0.f);
                if (aar[u] >= 0){
                    v = *(const float4*)(A1 + (size_t)aar[u]*CINA + k0a + akq[u]);
                    if (GATHER){ v.x*=asc[u]; v.y*=asc[u]; v.z*=asc[u]; v.w*=asc[u]; }
                }
                ra[u] = v;
            }
        } else {
            #pragma unroll
            for (int u = 0; u < AV; u++){
                uint2 w = make_uint2(0,0);
                if (aar[u] >= 0)
                    w = *(const uint2*)(A2b + (size_t)aar[u]*KWA + k0a/2 + (akq[u] >> 1));
                ra2[u] = w;
            }
        }
        #pragma unroll
        for (int u = 0; u < BV; u++){
            size_t off = (size_t)bm[u]*KW + k0w + (bkq[u] >> 1);
            rbh[u] = *(const uint2*)(Wh + off);
            rbl[u] = *(const uint2*)(Wl + off);
        }
    };
    auto store_split = [&](){
        if (cur_ph == 0){
            #pragma unroll
            for (int u = 0; u < AV; u++){
                const float* s = (const float*)&ra[u];
                unsigned short h0,l0,h1,l1,h2,l2,h3,l3;
                bf16_split(s[0],h0,l0); bf16_split(s[1],h1,l1);
                bf16_split(s[2],h2,l2); bf16_split(s[3],h3,l3);
                int w = akq[u] >> 1;
                As[0][am[u]][w  ] = (unsigned)h0 | ((unsigned)h1 << 16);
                As[0][am[u]][w+1] = (unsigned)h2 | ((unsigned)h3 << 16);
                As[1][am[u]][w  ] = (unsigned)l0 | ((unsigned)l1 << 16);
                As[1][am[u]][w+1] = (unsigned)l2 | ((unsigned)l3 << 16);
            }
        } else {
            #pragma unroll
            for (int u = 0; u < AV; u++){
                int w = akq[u] >> 1;
                As[0][am[u]][w  ] = ra2[u].x;
                As[0][am[u]][w+1] = ra2[u].y;
            }
        }
        #pragma unroll
        for (int u = 0; u < BV; u++){
            int w = bkq[u] >> 1;
            *(uint2*)&Bs[0][bm[u]][w] = rbh[u];
            *(uint2*)&Bs[1][bm[u]][w] = rbl[u];
        }
    };

    float acc[MT][NT][4];
    #pragma unroll
    for (int mi = 0; mi < MT; mi++)
        #pragma unroll
        for (int ni = 0; ni < NT; ni++)
            #pragma unroll
            for (int q = 0; q < 4; q++) acc[mi][ni][q] = 0.f;

    load_tile(0);
    for (int t = 0; t < T; t++){
        bool useLo = !DUAL || (t < TILESA);
        store_split();
        __syncthreads();
        if (t + 1 < T) load_tile(t + 1);
        #pragma unroll
        for (int kk = 0; kk < 2; kk++){
            int ko = kk * 8;
            unsigned ah[MT][4], al[MT][4];
            #pragma unroll
            for (int mi = 0; mi < MT; mi++){
                int mb = m0 + mi*16 + gid;
                ah[mi][0] = As[0][mb  ][ko+tig  ];
                ah[mi][1] = As[0][mb+8][ko+tig  ];
                ah[mi][2] = As[0][mb  ][ko+tig+4];
                ah[mi][3] = As[0][mb+8][ko+tig+4];
                al[mi][0] = As[1][mb  ][ko+tig  ];
                al[mi][1] = As[1][mb+8][ko+tig  ];
                al[mi][2] = As[1][mb  ][ko+tig+4];
                al[mi][3] = As[1][mb+8][ko+tig+4];
            }
            #pragma unroll
            for (int ni = 0; ni < NT; ni++){
                int nb = n0 + ni*8 + gid;
                unsigned bh0 = Bs[0][nb][ko+tig  ];
                unsigned bh1 = Bs[0][nb][ko+tig+4];
                unsigned bl0 = Bs[1][nb][ko+tig  ];
                unsigned bl1 = Bs[1][nb][ko+tig+4];
                #pragma unroll
                for (int mi = 0; mi < MT; mi++){
                    MMA_BF16(acc[mi][ni], ah[mi][0],ah[mi][1],ah[mi][2],ah[mi][3], bh0,bh1);
                    MMA_BF16(acc[mi][ni], ah[mi][0],ah[mi][1],ah[mi][2],ah[mi][3], bl0,bl1);
                    if (useLo)
                        MMA_BF16(acc[mi][ni], al[mi][0],al[mi][1],al[mi][2],al[mi][3], bh0,bh1);
                }
            }
        }
        __syncthreads();
    }

    #pragma unroll
    for (int mi = 0; mi < MT; mi++){
        #pragma unroll
        for (int ni = 0; ni < NT; ni++){
            int cc = n0 + ni*8 + tig*2;
            #pragma unroll
            for (int h = 0; h < 2; h++){
                int rr = row0 + m0 + mi*16 + gid + h*8;
                if (rr < n){
                    float v0 = acc[mi][ni][h*2+0];
                    float v1 = acc[mi][ni][h*2+1];
                    if (bias){ v0 += __ldg(&bias[cc]); v1 += __ldg(&bias[cc+1]); }
                    if (D){ v0 += D[(size_t)rr*BN + cc]; v1 += D[(size_t)rr*BN + cc + 1]; }
                    if (RELU){ v0 = fmaxf(v0, 0.f); v1 = fmaxf(v1, 0.f); }
                    *(float2*)(out + (size_t)rr*BN + cc) = make_float2(v0, v1);
                }
            }
        }
    }
}

// ---------------- elementwise: x = relu(t[:,64:128] + agg + bias), t stride 128 ----------------
__global__ void merge_conv_kernel(const float* __restrict__ t, const float* __restrict__ agg,
                                  const float* __restrict__ bias, float* __restrict__ xout, int n)
{
    int idx = blockIdx.x*blockDim.x + threadIdx.x;
    int total = n * 16;
    if (idx >= total) return;
    int i = idx >> 4, c4 = (idx & 15) << 2;
    float4 r = *(const float4*)(t + (size_t)i*128 + 64 + c4);
    float4 a = *(const float4*)(agg + (size_t)i*64 + c4);
    float4 b = *(const float4*)(bias + c4);
    r.x = fmaxf(r.x + a.x + b.x, 0.f);
    r.y = fmaxf(r.y + a.y + b.y, 0.f);
    r.z = fmaxf(r.z + a.z + b.z, 0.f);
    r.w = fmaxf(r.w + a.w + b.w, 0.f);
    *(float4*)(xout + (size_t)i*64 + c4) = r;
}

// fused conv3-merge + unpool1 -> bf16x2 u1: u1[i] = x2[i] + (m>=0 ? relu(t3[m,64:]+agg[m]+b3) : 0)
__global__ void merge_unpool_bf16_kernel(const float* __restrict__ t3, const float* __restrict__ agg,
                                         const float* __restrict__ bias, const float* __restrict__ x2,
                                         const int* __restrict__ map2, unsigned* __restrict__ u1b, int n)
{
    int idx = blockIdx.x*blockDim.x + threadIdx.x;
    int total = n * 32;
    if (idx >= total) return;
    int i = idx >> 5, w = idx & 31;
    int c0 = w*2;
    float2 v = *(const float2*)(x2 + (size_t)i*64 + c0);
    int m = map2[i];
    if (m >= 0){
        float2 r = *(const float2*)(t3 + (size_t)m*128 + 64 + c0);
        float2 a = *(const float2*)(agg + (size_t)m*64 + c0);
        float2 b = *(const float2*)(bias + c0);
        v.x += fmaxf(r.x + a.x + b.x, 0.f);
        v.y += fmaxf(r.y + a.y + b.y, 0.f);
    }
    u1b[(size_t)i*32 + w] = pack2bf(v.x, v.y);
}

// unpool2 -> bf16x2 u2: u2[i] = x1[i] + (m>=0 ? x4[m] : 0)
__global__ void unpool_bf16_kernel(const float* __restrict__ x1, const float* __restrict__ x4,
                                   const int* __restrict__ map1, unsigned* __restrict__ u2b, int n)
{
    int idx = blockIdx.x*blockDim.x + threadIdx.x;
    int total = n * 64;
    if (idx >= total) return;
    int i = idx >> 6, w = idx & 63;
    int c0 = w*2;
    float2 v = *(const float2*)(x1 + (size_t)i*128 + c0);
    int m = map1[i];
    if (m >= 0){
        float2 s = *(const float2*)(x4 + (size_t)m*128 + c0);
        v.x += s.x; v.y += s.y;
    }
    u2b[(size_t)i*64 + w] = pack2bf(v.x, v.y);
}

// ---------------- topk pooling ----------------
template<int C>
__global__ void score_kernel(const float* __restrict__ x, const float* __restrict__ w, int n)
{
    int gw = blockIdx.x*(blockDim.x>>5) + (threadIdx.x>>5);
    int lane = threadIdx.x & 31;
    if (gw >= n) return;
    float p, q;
    if constexpr (C == 128){
        float4 xv = ((const float4*)(x + (size_t)gw*128))[lane];
        float4 wv = ((const float4*)w)[lane];
        p = xv.x*wv.x + xv.y*wv.y + xv.z*wv.z + xv.w*wv.w;
        q = wv.x*wv.x + wv.y*wv.y + wv.z*wv.z + wv.w*wv.w;
    } else {
        float2 xv = ((const float2*)(x + (size_t)gw*64))[lane];
        float2 wv = ((const float2*)w)[lane];
        p = xv.x*wv.x + xv.y*wv.y;
        q = wv.x*wv.x + wv.y*wv.y;
    }
    #pragma unroll
    for (int off = 16; off; off >>= 1){
        p += __shfl_xor_sync(0xffffffffu, p, off);
        q += __shfl_xor_sync(0xffffffffu, q, off);
    }
    if (lane == 0){
        float s = tanhf(p / sqrtf(q));
        g_score[gw] = s;
        unsigned u = __float_as_uint(s);
        u = (u & 0x80000000u) ? ~u : (u | 0x80000000u);
        g_key[gw] = u;
    }
}

// ONE-KERNEL radix select + compact; keys staged in dynamic shared memory.
__global__ void __launch_bounds__(1024) topk_select_kernel(
    int* __restrict__ mapping, int* __restrict__ perm, int n, int k)
{
    extern __shared__ unsigned skey[];
    __shared__ unsigned hist[256];
    __shared__ int ws[32];
    __shared__ int s_b, s_rem;

    for (int i = threadIdx.x; i < n; i += 1024) skey[i] = g_key[i];
    __syncthreads();

    unsigned prefix = 0;
    int remaining = k;
    for (int pass = 3; pass >= 0; pass--){
        for (int t = threadIdx.x; t < 256; t += 1024) hist[t] = 0;
        __syncthreads();
        int shf = (pass+1)*8;
        unsigned pref_hi = (pass == 3) ? 0u : (prefix >> shf);
        for (int base = 0; base < n; base += 1024){
            int i = base + threadIdx.x;
            if (i < n){
                unsigned key = skey[i];
                bool ok = (pass == 3) || ((key >> shf) == pref_hi);
                if (ok) atomicAdd(&hist[(key >> (pass*8)) & 255], 1u);
            }
        }
        __syncthreads();
        if (threadIdx.x == 0){
            unsigned r = (unsigned)remaining;
            unsigned c = 0; int b = 255;
            for (; b > 0; b--){
                unsigned h = hist[b];
                if (c + h >= r) break;
                c += h;
            }
            s_b = b; s_rem = (int)(r - c);
        }
        __syncthreads();
        prefix |= ((unsigned)s_b) << (pass*8);
        remaining = s_rem;
        __syncthreads();
    }

    unsigned thr = prefix;
    int local = 0;
    for (int base = 0; base < n; base += 1024){
        int i = base + threadIdx.x;
        if (i < n) local += (skey[i] > thr) ? 1 : 0;
    }
    int totG; block_scan_incl(local, totG, ws);
    int need_eq = k - totG;

    int run_eq = 0, run_sel = 0;
    for (int base = 0; base < n; base += 1024){
        int i = base + threadIdx.x;
        int gt = 0, eq = 0;
        if (i < n){
            unsigned kv = skey[i];
            gt = (kv > thr); eq = (kv == thr);
        }
        int tot_eq; int incl_eq = block_scan_incl(eq, tot_eq, ws);
        int excl_eq = incl_eq - eq;
        int sel = gt | (eq & ((run_eq + excl_eq) < need_eq ? 1 : 0));
        int tot_sel; int incl_sel = block_scan_incl(sel, tot_sel, ws);
        if (i < n){
            if (sel){
                int idx = run_sel + incl_sel - 1;
                mapping[i] = idx;
                perm[idx] = i;
            } else mapping[i] = -1;
        }
        run_eq += tot_eq; run_sel += tot_sel;
    }
}

// fused compose of level0->level2 mapping and perm
__global__ void compose_kernel()
{
    int i = blockIdx.x*blockDim.x + threadIdx.x;
    if (i < N0){ int m = g_map1[i]; g_map02[i] = (m >= 0) ? g_map2[m] : -1; }
    if (i < K2) g_perm02[i] = g_perm1[g_perm2[i]];
}

// ---------------- final linear + log_softmax (warp per node) ----------------
__global__ void final_kernel(const float* __restrict__ x, const float* __restrict__ lw,
                             const float* __restrict__ lb, float* __restrict__ out, int n)
{
    int gw = blockIdx.x*(blockDim.x>>5) + (threadIdx.x>>5);
    int lane = threadIdx.x & 31;
    if (gw >= n) return;
    float4 xv = ((const float4*)(x + (size_t)gw*128))[lane];
    float lg[10]; float myv = 0.f;
    #pragma unroll
    for (int c = 0; c < 10; c++){
        float4 wv = ((const float4*)(lw + c*128))[lane];
        float p = xv.x*wv.x + xv.y*wv.y + xv.z*wv.z + xv.w*wv.w;
        #pragma unroll
        for (int off = 16; off; off >>= 1) p += __shfl_xor_sync(0xffffffffu, p, off);
        p += __ldg(&lb[c]);
        lg[c] = p;
        if (lane == c) myv = p;
    }
    float m = lg[0];
    #pragma unroll
    for (int c = 1; c < 10; c++) m = fmaxf(m, lg[c]);
    float s = 0.f;
    #pragma unroll
    for (int c = 0; c < 10; c++) s += expf(lg[c] - m);
    float lse = m + logf(s);
    if (lane < 10) out[(size_t)gw*10 + lane] = myv - lse;
}

// ---------------- host driver ----------------
extern "C" void kernel_launch(void* const* d_in, const int* in_sizes, int n_in,
                              void* d_out, int out_size)
{
    (void)in_sizes; (void)n_in; (void)out_size;
    const float* x    = (const float*)d_in[0];
    const int*   ei   = (const int*)d_in[1];
    const int*   src0 = ei;
    const int*   dst0 = ei + E0;
    const float *w1r=(const float*)d_in[2], *w1o=(const float*)d_in[3], *b1=(const float*)d_in[4], *p1w=(const float*)d_in[5];
    const float *w2r=(const float*)d_in[6], *w2o=(const float*)d_in[7], *b2=(const float*)d_in[8], *p2w=(const float*)d_in[9];
    const float *w3r=(const float*)d_in[10],*w3o=(const float*)d_in[11],*b3=(const float*)d_in[12];
    const float *w4r=(const float*)d_in[13],*w4o=(const float*)d_in[14],*b4=(const float*)d_in[15];
    const float *w5r=(const float*)d_in[16],*w5o=(const float*)d_in[17],*b5=(const float*)d_in[18];
    const float *lw =(const float*)d_in[19],*lb =(const float*)d_in[20];
    float* out = (float*)d_out;

    float *x1,*agg,*x2,*x4,*u2,*x5,*wHi,*wLo,*score;
    unsigned *u1b,*u2b,*wb3h,*wb3l,*wb4h,*wb4l,*wb5h,*wb5l;
    int *rowptr,*fill,*part,*partx,*map1,*perm1,*map2,*perm2,*map02,*perm02;
    cudaGetSymbolAddress((void**)&x1, g_x1);
    cudaGetSymbolAddress((void**)&agg, g_agg);
    cudaGetSymbolAddress((void**)&x2, g_x2);
    cudaGetSymbolAddress((void**)&x4, g_x4);
    cudaGetSymbolAddress((void**)&u2, g_u2);
    cudaGetSymbolAddress((void**)&x5, g_x5);
    cudaGetSymbolAddress((void**)&u1b, g_u1b);
    cudaGetSymbolAddress((void**)&u2b, g_u2b);
    cudaGetSymbolAddress((void**)&wHi, g_wHi);
    cudaGetSymbolAddress((void**)&wLo, g_wLo);
    cudaGetSymbolAddress((void**)&wb3h, g_wb3h);
    cudaGetSymbolAddress((void**)&wb3l, g_wb3l);
    cudaGetSymbolAddress((void**)&wb4h, g_wb4h);
    cudaGetSymbolAddress((void**)&wb4l, g_wb4l);
    cudaGetSymbolAddress((void**)&wb5h, g_wb5h);
    cudaGetSymbolAddress((void**)&wb5l, g_wb5l);
    cudaGetSymbolAddress((void**)&score, g_score);
    cudaGetSymbolAddress((void**)&rowptr, g_rowptr);
    cudaGetSymbolAddress((void**)&fill, g_fill);
    cudaGetSymbolAddress((void**)&part, g_part);
    cudaGetSymbolAddress((void**)&partx, g_partx);
    cudaGetSymbolAddress((void**)&map1, g_map1);
    cudaGetSymbolAddress((void**)&perm1, g_perm1);
    cudaGetSymbolAddress((void**)&map2, g_map2);
    cudaGetSymbolAddress((void**)&perm2, g_perm2);
    cudaGetSymbolAddress((void**)&map02, g_map02);
    cudaGetSymbolAddress((void**)&perm02, g_perm02);

    const int W = 16384;
    float* t2 = x4;   // conv2 cat output [K1][128]
    float* t3 = u2;   // conv3 cat output [K2][128]

    cudaFuncSetAttribute(topk_select_kernel,
                         cudaFuncAttributeMaxDynamicSharedMemorySize, N0*sizeof(unsigned) + 1024);

    cudaStream_t s2;
    cudaEvent_t ev1, ev2;
    cudaStreamCreateWithFlags(&s2, cudaStreamNonBlocking);
    cudaEventCreateWithFlags(&ev1, cudaEventDisableTiming);
    cudaEventCreateWithFlags(&ev2, cudaEventDisableTiming);

    // ---- prologue fork (CSR has serialization bubbles; weight prep + GEMM fill them) ----
    cudaEventRecord(ev1, 0);
    cudaStreamWaitEvent(s2, ev1, 0);
    {
        dim3 g1(64, 4);
        prep_tf32_kernel<<<g1,256>>>(w1r, w1o, w2r, w2o);
        dim3 g2(64, 3);
        prep_bf16_kernel<<<g2,256>>>(w3r, w3o, w4r, w4o, w5r, w5o);
    }
    zero_int_kernel<<<(N0+255)/256,256,0,s2>>>(fill, N0);
    edge_count_kernel<<<(E0+255)/256,256,0,s2>>>(dst0);
    gemm_tf32_kernel<128,128,false,false><<<(N0+127)/128,256>>>(
        x, wHi+1*W, wLo+1*W, nullptr, nullptr, x1, N0, nullptr, nullptr);
    deg_reduce_kernel<<<NB_SCAN,1024,0,s2>>>(fill, part, N0);
    scan_kernel<<<1,1024,0,s2>>>(part, partx, NB_SCAN);
    deg_apply_kernel<<<NB_SCAN,1024,0,s2>>>(fill, partx, rowptr, N0);
    edge_scatter_kernel<<<(E0+255)/256,256,0,s2>>>(src0, dst0);
    agg_kernel<128><<<(N0+7)/8,256,0,s2>>>(x, agg, nullptr, nullptr, N0, 128);
    cudaEventRecord(ev2, s2);
    cudaStreamWaitEvent(0, ev2, 0);

    // conv1 rel-half (D add, bias, relu)
    gemm_tf32_kernel<128,128,true,false><<<(N0+127)/128,256>>>(
        agg, wHi+0*W, wLo+0*W, b1, x1, x1, N0, nullptr, nullptr);

    // pool1
    score_kernel<128><<<(N0+7)/8,256>>>(x1, p1w, N0);
    topk_select_kernel<<<1,1024,N0*sizeof(unsigned)>>>(map1, perm1, N0, K1);

    // conv2 (tf32 N-cat): t2 = gather(x1)·[W2r^T|W2o^T]; agg left half; merge
    gemm_tf32_kernel<128,128,false,true><<<(K1+127)/128,256>>>(
        x1, wHi+2*W, wLo+2*W, nullptr, nullptr, t2, K1, perm1, score);
    agg_kernel<64><<<(K1+7)/8,256>>>(t2, agg, perm1, map1, K1, 128);
    merge_conv_kernel<<<(K1*16+255)/256,256>>>(t2, agg, b2, x2, K1);

    // pool2
    score_kernel<64><<<(K1+7)/8,256>>>(x2, p2w, K1);
    topk_select_kernel<<<1,1024,K1*sizeof(unsigned)>>>(map2, perm2, K1, K2);
    compose_kernel<<<(N0+255)/256,256>>>();

    // conv3 (bf16 N-cat): t3 = gather(x2)·[W3r|W3o]; agg left half; fused merge+unpool1 -> u1b
    gemm_bf16_kernel<128,64,64,false,false,true><<<(K2+127)/128,256>>>(
        x2, nullptr, wb3h, wb3l, nullptr, nullptr, t3, K2, perm2, score);
    agg_kernel<64><<<(K2+7)/8,256>>>(t3, agg, perm02, map02, K2, 128);
    merge_unpool_bf16_kernel<<<(K1*32+255)/256,256>>>(t3, agg, b3, x2, map2, u1b, K1);

    // conv4 (bf16 K-cat, A2 = u1b bf16): relu(agg·W4r + u1·W4o + b4)
    agg_bf16_kernel<64><<<(K1+7)/8,256>>>(u1b, agg, perm1, map1, K1);
    gemm_bf16_kernel<128,128,64,true,true,false><<<(K1+127)/128,256>>>(
        agg, u1b, wb4h, wb4l, b4, nullptr, x4, K1, nullptr, nullptr);

    // unpool2 + skip -> u2b (bf16)
    unpool_bf16_kernel<<<(N0*64+255)/256,256>>>(x1, x4, map1, u2b, N0);

    // conv5 (bf16 K-cat, A2 = u2b bf16)
    agg_bf16_kernel<128><<<(N0+7)/8,256>>>(u2b, agg, nullptr, nullptr, N0);
    gemm_bf16_kernel<128,256,128,true,true,false><<<(N0+127)/128,256>>>(
        agg, u2b, wb5h, wb5l, b5, nullptr, x5, N0, nullptr, nullptr);

    // final linear + log_softmax
    final_kernel<<<(N0+7)/8,256>>>(x5, lw, lb, out, N0);
}